// round 7
// baseline (speedup 1.0000x reference)
#include <cuda_runtime.h>
#include <cuda_bf16.h>

// Problem constants
#define EN    512
#define SEQ   2048
#define NBAT  4
#define NHEAD 8
#define HDIM  64
#define MTOT  (NBAT * SEQ)          // 8192
#define NSE   (NBAT * SEQ * EN)     // 4,194,304 floats per buffer

// 64 MB scratch: Q, K, V, O (pre-projection attention output)
__device__ float g_scratch[4ull * NSE];

// ---------------------------------------------------------------------------
// Packed fp32x2 helpers (sm_100+): FFMA2 doubles fp32 FMA throughput.
// ptxas never emits FFMA2 from C++ — must be written as PTX fma.rn.f32x2.
// Numerics: two independent IEEE fp32 FMAs — identical to scalar FFMA.
// ---------------------------------------------------------------------------
union V4 { float4 v; unsigned long long u[2]; float f[4]; };
union F2 { unsigned long long u; float2 f; };

__device__ __forceinline__ unsigned long long dup2(float x)
{
    unsigned long long r;
    asm("mov.b64 %0, {%1, %1};" : "=l"(r) : "f"(x));
    return r;
}
__device__ __forceinline__ void fma2(unsigned long long& d,
                                     unsigned long long a, unsigned long long b)
{
    asm("fma.rn.f32x2 %0, %1, %2, %0;" : "+l"(d) : "l"(a), "l"(b));
}

// ---------------------------------------------------------------------------
// GEMM: C[m][n] = (sum_k A[m][k] * W[n][k] + bias[n]) * scale
// Block tile 128x128, K-tile 8, 256 threads, 8x8 micro-tile via FFMA2
// (row-paired accumulators), register-prefetch double buffering.
// grid: (EN/128, M/128)
// ---------------------------------------------------------------------------
__global__ __launch_bounds__(256, 2)
void gemm_bias_kernel(const float* __restrict__ A, const float* __restrict__ W,
                      const float* __restrict__ bias, float* __restrict__ C,
                      float scale)
{
    __shared__ float As[8][132];   // +4 pad: conflict-free transposed stores
    __shared__ float Bs[8][132];

    const int t  = threadIdx.x;
    const int m0 = blockIdx.y << 7;
    const int n0 = blockIdx.x << 7;
    const int tx = t & 15, ty = t >> 4;
    const int ry = ty << 3, cx = tx << 3;

    const int lr = t >> 1;           // tile row 0..127
    const int lk = (t & 1) << 2;     // k offset 0 or 4
    const float* Ap = A + (size_t)(m0 + lr) * EN + lk;
    const float* Wp = W + (size_t)(n0 + lr) * EN + lk;

    // acc2[i2][j]: rows (ry+2*i2, ry+2*i2+1), col cx+j
    F2 acc2[4][8];
#pragma unroll
    for (int i = 0; i < 4; i++)
#pragma unroll
        for (int j = 0; j < 8; j++) acc2[i][j].u = 0ull;

    float4 aN = *(const float4*)Ap;
    float4 bN = *(const float4*)Wp;

    for (int kt = 0; kt < EN; kt += 8) {
        As[lk + 0][lr] = aN.x; As[lk + 1][lr] = aN.y;
        As[lk + 2][lr] = aN.z; As[lk + 3][lr] = aN.w;
        Bs[lk + 0][lr] = bN.x; Bs[lk + 1][lr] = bN.y;
        Bs[lk + 2][lr] = bN.z; Bs[lk + 3][lr] = bN.w;
        __syncthreads();

        if (kt + 8 < EN) {                     // prefetch next K-tile
            aN = *(const float4*)(Ap + kt + 8);
            bN = *(const float4*)(Wp + kt + 8);
        }

#pragma unroll
        for (int k = 0; k < 8; k++) {
            V4 A0, A1, B0, B1;
            A0.v = *(const float4*)&As[k][ry];
            A1.v = *(const float4*)&As[k][ry + 4];
            B0.v = *(const float4*)&Bs[k][cx];
            B1.v = *(const float4*)&Bs[k][cx + 4];
#pragma unroll
            for (int j = 0; j < 4; j++) {
                unsigned long long bj = dup2(B0.f[j]);
                fma2(acc2[0][j].u, A0.u[0], bj);
                fma2(acc2[1][j].u, A0.u[1], bj);
                fma2(acc2[2][j].u, A1.u[0], bj);
                fma2(acc2[3][j].u, A1.u[1], bj);
            }
#pragma unroll
            for (int j = 0; j < 4; j++) {
                unsigned long long bj = dup2(B1.f[j]);
                fma2(acc2[0][4 + j].u, A0.u[0], bj);
                fma2(acc2[1][4 + j].u, A0.u[1], bj);
                fma2(acc2[2][4 + j].u, A1.u[0], bj);
                fma2(acc2[3][4 + j].u, A1.u[1], bj);
            }
        }
        __syncthreads();
    }

    float bb[8];
    *(float4*)(bb)     = *(const float4*)&bias[n0 + cx];
    *(float4*)(bb + 4) = *(const float4*)&bias[n0 + cx + 4];

#pragma unroll
    for (int i2 = 0; i2 < 4; i2++)
#pragma unroll
        for (int hf = 0; hf < 2; hf++) {
            int r = (i2 << 1) + hf;
            float* Cp = C + (size_t)(m0 + ry + r) * EN + n0 + cx;
            float o[8];
#pragma unroll
            for (int j = 0; j < 8; j++) {
                float v = hf ? acc2[i2][j].f.y : acc2[i2][j].f.x;
                o[j] = (v + bb[j]) * scale;
            }
            *(float4*)(Cp)     = *(float4*)(o);
            *(float4*)(Cp + 4) = *(float4*)(o + 4);
        }
}

// ---------------------------------------------------------------------------
// Flash attention, fp32, causal, FFMA2 inner products.
// Br = 128 (row tile), Bc = 64 (col tile), HD = 64, 128 threads (16x8 groups),
// 8x8 micro-tiles for both S = Q K^T and O += P V  (1.0 B/FMA -> co-bound
// with the doubled FFMA2 roofline).
// Smem 96 KB/CTA -> 2 CTAs/SM. grid: (S/128 = 16, NBAT*NHEAD = 32).
// Transposed tiles (Qt/Ks/Pt) are k-major with an XOR swizzle on the
// 4-float group index so transpose stores are ~2-way and GEMM reads clean.
// ---------------------------------------------------------------------------
__global__ __launch_bounds__(128)
void attention_kernel(const float* __restrict__ gQ, const float* __restrict__ gK,
                      const float* __restrict__ gV, float* __restrict__ gO)
{
    extern __shared__ float smem[];
    float* Qt = smem;           // [k][r] 64x128, swizzled   (32 KB)
    float* Ks = smem + 8192;    // [k][c] 64x64,  swizzled   (16 KB)
    float* Vs = smem + 12288;   // [c][d] 64x64,  natural    (16 KB)
    float* Pt = smem + 16384;   // [c][r] 64x128, swizzled   (32 KB)

    const int t  = threadIdx.x;
    const int tx = t & 7,  ty = t >> 3;     // 8 col-groups x 16 row-groups
    const int cx = tx << 3, ry = ty << 3;   // 8 cols, 8 rows per thread
    // heavy-first: large sb (most causal work) launches first
    const int sb = (int)gridDim.x - 1 - (int)blockIdx.x;
    const int s0 = sb << 7;
    const int nh = blockIdx.y;
    const int n  = nh >> 3, h = nh & 7;

    const float* Qp = gQ + ((size_t)(n * SEQ + s0)) * EN + h * HDIM;
    const float* Kp = gK + (size_t)n * SEQ * EN + h * HDIM;
    const float* Vp = gV + (size_t)n * SEQ * EN + h * HDIM;

    // ---- load Q tile (128 rows x 64) transposed+swizzled ----
#pragma unroll
    for (int i = 0; i < 16; i++) {
        int idx = t + (i << 7);
        int k4 = idx & 15, r = idx >> 4;          // r 0..127
        V4 q; q.v = *(const float4*)(Qp + (size_t)r * EN + (k4 << 2));
        int r4 = r >> 2, rm3 = r & 3;
        int grp = ((r4 ^ k4) & 31) << 2;          // k>>2 == k4 for all 4 elems
#pragma unroll
        for (int e = 0; e < 4; e++)
            Qt[(((k4 << 2) + e) << 7) + grp + rm3] = q.f[e];
    }

    F2 accO2[4][8];
    float rm[8], rl[8];
#pragma unroll
    for (int i = 0; i < 8; i++) { rm[i] = -1e30f; rl[i] = 0.0f; }
#pragma unroll
    for (int i = 0; i < 4; i++)
#pragma unroll
        for (int j = 0; j < 8; j++) accO2[i][j].u = 0ull;

    const int kbmax = (sb << 1) + 2;   // 64-col tiles needed for causal rows
    for (int kb = 0; kb < kbmax; kb++) {
        __syncthreads();   // prior iter's smem reads done before overwrite
        const float* Kt = Kp + ((size_t)(kb << 6)) * EN;
        const float* Vt = Vp + ((size_t)(kb << 6)) * EN;

        // ---- load K (transposed+swizzled, [k][c] 64x64) and V (natural) ----
#pragma unroll
        for (int i = 0; i < 8; i++) {
            int idx = t + (i << 7);
            int k4 = idx & 15, r = idx >> 4;      // r = col 0..63
            V4 kk; kk.v = *(const float4*)(Kt + (size_t)r * EN + (k4 << 2));
            int r4 = r >> 2, rm3 = r & 3;
            int grp = ((r4 ^ k4) & 15) << 2;
#pragma unroll
            for (int e = 0; e < 4; e++)
                Ks[(((k4 << 2) + e) << 6) + grp + rm3] = kk.f[e];
            float4 vv = *(const float4*)(Vt + (size_t)r * EN + (k4 << 2));
            *(float4*)&Vs[(r << 6) + (k4 << 2)] = vv;
        }
        __syncthreads();

        // ---- S = Q K^T (Q pre-scaled); s2[i2][j] = rows (ry+2i2, +1), col cx+j
        F2 s2[4][8];
#pragma unroll
        for (int i = 0; i < 4; i++)
#pragma unroll
            for (int j = 0; j < 8; j++) s2[i][j].u = 0ull;

#pragma unroll 4
        for (int k = 0; k < 64; k++) {
            int g = k >> 2;
            V4 A0, A1, B0, B1;
            A0.v = *(const float4*)&Qt[(k << 7) + ((((ty << 1)     ^ g) & 31) << 2)];
            A1.v = *(const float4*)&Qt[(k << 7) + (((((ty << 1)|1) ^ g) & 31) << 2)];
            B0.v = *(const float4*)&Ks[(k << 6) + ((((tx << 1)     ^ g) & 15) << 2)];
            B1.v = *(const float4*)&Ks[(k << 6) + (((((tx << 1)|1) ^ g) & 15) << 2)];
#pragma unroll
            for (int j = 0; j < 4; j++) {
                unsigned long long bj = dup2(B0.f[j]);
                fma2(s2[0][j].u, A0.u[0], bj);
                fma2(s2[1][j].u, A0.u[1], bj);
                fma2(s2[2][j].u, A1.u[0], bj);
                fma2(s2[3][j].u, A1.u[1], bj);
            }
#pragma unroll
            for (int j = 0; j < 4; j++) {
                unsigned long long bj = dup2(B1.f[j]);
                fma2(s2[0][4 + j].u, A0.u[0], bj);
                fma2(s2[1][4 + j].u, A0.u[1], bj);
                fma2(s2[2][4 + j].u, A1.u[0], bj);
                fma2(s2[3][4 + j].u, A1.u[1], bj);
            }
        }

        // ---- causal mask on diagonal tiles ----
        if (kb >= (sb << 1)) {
            int c0 = (kb << 6) + cx;
#pragma unroll
            for (int i2 = 0; i2 < 4; i2++) {
                int r0 = s0 + ry + (i2 << 1);
#pragma unroll
                for (int j = 0; j < 8; j++) {
                    if (c0 + j > r0)     s2[i2][j].f.x = -1e30f;
                    if (c0 + j > r0 + 1) s2[i2][j].f.y = -1e30f;
                }
            }
        }

        // ---- online softmax (row reduce across 8 tx-lanes) ----
#pragma unroll
        for (int i2 = 0; i2 < 4; i2++)
#pragma unroll
            for (int hf = 0; hf < 2; hf++) {
                int ri = (i2 << 1) + hf;
                float mx = -1e30f;
#pragma unroll
                for (int j = 0; j < 8; j++)
                    mx = fmaxf(mx, hf ? s2[i2][j].f.y : s2[i2][j].f.x);
                mx = fmaxf(mx, __shfl_xor_sync(0xffffffffu, mx, 1));
                mx = fmaxf(mx, __shfl_xor_sync(0xffffffffu, mx, 2));
                mx = fmaxf(mx, __shfl_xor_sync(0xffffffffu, mx, 4));
                float nm    = fmaxf(rm[ri], mx);
                float alpha = __expf(rm[ri] - nm);
                float ps = 0.0f;
#pragma unroll
                for (int j = 0; j < 8; j++) {
                    float v = hf ? s2[i2][j].f.y : s2[i2][j].f.x;
                    float e = __expf(v - nm);
                    if (hf) s2[i2][j].f.y = e; else s2[i2][j].f.x = e;
                    ps += e;
                }
                ps += __shfl_xor_sync(0xffffffffu, ps, 1);
                ps += __shfl_xor_sync(0xffffffffu, ps, 2);
                ps += __shfl_xor_sync(0xffffffffu, ps, 4);
                rl[ri] = rl[ri] * alpha + ps;
                rm[ri] = nm;
#pragma unroll
                for (int j = 0; j < 8; j++) {
                    if (hf) accO2[i2][j].f.y *= alpha;
                    else    accO2[i2][j].f.x *= alpha;
                }
            }

        // ---- write P transposed ([c][r], swizzled like Qt) ----
#pragma unroll
        for (int j = 0; j < 8; j++) {
            int c = cx + j;
            int grp = (c << 7) + ((c >> 2) & 31 ? 0 : 0);  // placeholder fold
            (void)grp;
            int glo = (c << 7) + ((((ty << 1)     ^ (c >> 2)) & 31) << 2);
            int ghi = (c << 7) + (((((ty << 1)|1) ^ (c >> 2)) & 31) << 2);
            float4 lo = make_float4(s2[0][j].f.x, s2[0][j].f.y,
                                    s2[1][j].f.x, s2[1][j].f.y);
            float4 hi = make_float4(s2[2][j].f.x, s2[2][j].f.y,
                                    s2[3][j].f.x, s2[3][j].f.y);
            *(float4*)&Pt[glo] = lo;
            *(float4*)&Pt[ghi] = hi;
        }
        __syncthreads();

        // ---- O += P V ----
#pragma unroll 4
        for (int c = 0; c < 64; c++) {
            int g = c >> 2;
            V4 A0, A1, B0, B1;
            A0.v = *(const float4*)&Pt[(c << 7) + ((((ty << 1)     ^ g) & 31) << 2)];
            A1.v = *(const float4*)&Pt[(c << 7) + (((((ty << 1)|1) ^ g) & 31) << 2)];
            B0.v = *(const float4*)&Vs[(c << 6) + cx];
            B1.v = *(const float4*)&Vs[(c << 6) + cx + 4];
#pragma unroll
            for (int j = 0; j < 4; j++) {
                unsigned long long bj = dup2(B0.f[j]);
                fma2(accO2[0][j].u, A0.u[0], bj);
                fma2(accO2[1][j].u, A0.u[1], bj);
                fma2(accO2[2][j].u, A1.u[0], bj);
                fma2(accO2[3][j].u, A1.u[1], bj);
            }
#pragma unroll
            for (int j = 0; j < 4; j++) {
                unsigned long long bj = dup2(B1.f[j]);
                fma2(accO2[0][4 + j].u, A0.u[0], bj);
                fma2(accO2[1][4 + j].u, A0.u[1], bj);
                fma2(accO2[2][4 + j].u, A1.u[0], bj);
                fma2(accO2[3][4 + j].u, A1.u[1], bj);
            }
        }
    }

    // ---- epilogue: normalize, store to (n, s, h*HD + d) ----
    float* Op = gO + (size_t)(n * SEQ + s0 + ry) * EN + h * HDIM + cx;
#pragma unroll
    for (int i2 = 0; i2 < 4; i2++)
#pragma unroll
        for (int hf = 0; hf < 2; hf++) {
            int ri = (i2 << 1) + hf;
            float inv = 1.0f / rl[ri];
            float o[8];
#pragma unroll
            for (int j = 0; j < 8; j++) {
                float v = hf ? accO2[i2][j].f.y : accO2[i2][j].f.x;
                o[j] = v * inv;
            }
            float* p = Op + (size_t)ri * EN;
            *(float4*)(p)     = *(float4*)(o);
            *(float4*)(p + 4) = *(float4*)(o + 4);
        }
}

// ---------------------------------------------------------------------------
// kernel_launch: 3 projections -> attention -> output projection.
// Scale 1/sqrt(HD) = 0.125 folded into Q projection (bias included).
// ---------------------------------------------------------------------------
extern "C" void kernel_launch(void* const* d_in, const int* in_sizes, int n_in,
                              void* d_out, int out_size)
{
    (void)in_sizes; (void)n_in; (void)out_size;

    const float* query = (const float*)d_in[0];
    const float* key   = (const float*)d_in[1];
    const float* value = (const float*)d_in[2];
    // d_in[3] = attn_mask (int32 tril) -- causal, handled analytically
    const float* Wq = (const float*)d_in[4];
    const float* bq = (const float*)d_in[5];
    const float* Wk = (const float*)d_in[6];
    const float* bk = (const float*)d_in[7];
    const float* Wv = (const float*)d_in[8];
    const float* bv = (const float*)d_in[9];
    const float* Wp = (const float*)d_in[10];
    const float* bp = (const float*)d_in[11];
    float* out = (float*)d_out;

    void* sp = nullptr;
    cudaGetSymbolAddress(&sp, g_scratch);
    float* gQ = (float*)sp;
    float* gK = gQ + NSE;
    float* gV = gK + NSE;
    float* gO = gV + NSE;

    cudaFuncSetAttribute(attention_kernel,
                         cudaFuncAttributeMaxDynamicSharedMemorySize, 98304);

    dim3 gg(EN / 128, MTOT / 128);   // (4, 64)
    gemm_bias_kernel<<<gg, 256>>>(query, Wq, bq, gQ, 0.125f);
    gemm_bias_kernel<<<gg, 256>>>(key,   Wk, bk, gK, 1.0f);
    gemm_bias_kernel<<<gg, 256>>>(value, Wv, bv, gV, 1.0f);
    attention_kernel<<<dim3(SEQ / 128, NBAT * NHEAD), 128, 98304>>>(gQ, gK, gV, gO);
    gemm_bias_kernel<<<gg, 256>>>(gO, Wp, bp, out, 1.0f);
}

// round 9
// speedup vs baseline: 1.0577x; 1.0577x over previous
#include <cuda_runtime.h>
#include <cuda_bf16.h>

// Problem constants
#define EN    512
#define SEQ   2048
#define NBAT  4
#define NHEAD 8
#define HDIM  64
#define MTOT  (NBAT * SEQ)          // 8192
#define NSE   (NBAT * SEQ * EN)     // 4,194,304 floats per buffer

// 64 MB scratch: Q, K, V, O (pre-projection attention output)
__device__ float g_scratch[4ull * NSE];

// ---------------------------------------------------------------------------
// Packed fp32x2 helpers (sm_100+): FFMA2 doubles fp32 FMA throughput.
// ptxas never emits FFMA2 from C++ — must be written as PTX fma.rn.f32x2.
// Numerics: two independent IEEE fp32 FMAs — identical to scalar FFMA.
// ---------------------------------------------------------------------------
union V4 { float4 v; unsigned long long u[2]; float f[4]; };
union F2 { unsigned long long u; float2 f; };

__device__ __forceinline__ unsigned long long dup2(float x)
{
    unsigned long long r;
    asm("mov.b64 %0, {%1, %1};" : "=l"(r) : "f"(x));
    return r;
}
__device__ __forceinline__ void fma2(unsigned long long& d,
                                     unsigned long long a, unsigned long long b)
{
    asm("fma.rn.f32x2 %0, %1, %2, %0;" : "+l"(d) : "l"(a), "l"(b));
}

// ---------------------------------------------------------------------------
// GEMM: C[m][n] = (sum_k A[m][k] * W[n][k] + bias[n]) * scale
// Block tile 128x128, K-tile 8, 256 threads, 8x8 micro-tile via FFMA2
// (row-paired accumulators), register-prefetch double buffering.
// grid: (EN/128, M/128)
// ---------------------------------------------------------------------------
__global__ __launch_bounds__(256, 2)
void gemm_bias_kernel(const float* __restrict__ A, const float* __restrict__ W,
                      const float* __restrict__ bias, float* __restrict__ C,
                      float scale)
{
    __shared__ float As[8][132];   // +4 pad: conflict-free transposed stores
    __shared__ float Bs[8][132];

    const int t  = threadIdx.x;
    const int m0 = blockIdx.y << 7;
    const int n0 = blockIdx.x << 7;
    const int tx = t & 15, ty = t >> 4;
    const int ry = ty << 3, cx = tx << 3;

    const int lr = t >> 1;           // tile row 0..127
    const int lk = (t & 1) << 2;     // k offset 0 or 4
    const float* Ap = A + (size_t)(m0 + lr) * EN + lk;
    const float* Wp = W + (size_t)(n0 + lr) * EN + lk;

    // acc2[i2][j]: rows (ry+2*i2, ry+2*i2+1), col cx+j
    F2 acc2[4][8];
#pragma unroll
    for (int i = 0; i < 4; i++)
#pragma unroll
        for (int j = 0; j < 8; j++) acc2[i][j].u = 0ull;

    float4 aN = *(const float4*)Ap;
    float4 bN = *(const float4*)Wp;

    for (int kt = 0; kt < EN; kt += 8) {
        As[lk + 0][lr] = aN.x; As[lk + 1][lr] = aN.y;
        As[lk + 2][lr] = aN.z; As[lk + 3][lr] = aN.w;
        Bs[lk + 0][lr] = bN.x; Bs[lk + 1][lr] = bN.y;
        Bs[lk + 2][lr] = bN.z; Bs[lk + 3][lr] = bN.w;
        __syncthreads();

        if (kt + 8 < EN) {                     // prefetch next K-tile
            aN = *(const float4*)(Ap + kt + 8);
            bN = *(const float4*)(Wp + kt + 8);
        }

#pragma unroll
        for (int k = 0; k < 8; k++) {
            V4 A0, A1, B0, B1;
            A0.v = *(const float4*)&As[k][ry];
            A1.v = *(const float4*)&As[k][ry + 4];
            B0.v = *(const float4*)&Bs[k][cx];
            B1.v = *(const float4*)&Bs[k][cx + 4];
#pragma unroll
            for (int j = 0; j < 4; j++) {
                unsigned long long bj = dup2(B0.f[j]);
                fma2(acc2[0][j].u, A0.u[0], bj);
                fma2(acc2[1][j].u, A0.u[1], bj);
                fma2(acc2[2][j].u, A1.u[0], bj);
                fma2(acc2[3][j].u, A1.u[1], bj);
            }
#pragma unroll
            for (int j = 0; j < 4; j++) {
                unsigned long long bj = dup2(B1.f[j]);
                fma2(acc2[0][4 + j].u, A0.u[0], bj);
                fma2(acc2[1][4 + j].u, A0.u[1], bj);
                fma2(acc2[2][4 + j].u, A1.u[0], bj);
                fma2(acc2[3][4 + j].u, A1.u[1], bj);
            }
        }
        __syncthreads();
    }

    float bb[8];
    *(float4*)(bb)     = *(const float4*)&bias[n0 + cx];
    *(float4*)(bb + 4) = *(const float4*)&bias[n0 + cx + 4];

#pragma unroll
    for (int i2 = 0; i2 < 4; i2++)
#pragma unroll
        for (int hf = 0; hf < 2; hf++) {
            int r = (i2 << 1) + hf;
            float* Cp = C + (size_t)(m0 + ry + r) * EN + n0 + cx;
            float o[8];
#pragma unroll
            for (int j = 0; j < 8; j++) {
                float v = hf ? acc2[i2][j].f.y : acc2[i2][j].f.x;
                o[j] = (v + bb[j]) * scale;
            }
            *(float4*)(Cp)     = *(float4*)(o);
            *(float4*)(Cp + 4) = *(float4*)(o + 4);
        }
}

// ---------------------------------------------------------------------------
// Flash attention, fp32, causal, FFMA2 inner products.
// R5 skeleton: Br = Bc = 64, HD = 64, 256 threads (16x16), 4x4 micro-tiles,
// 64 KB smem -> 2 CTAs/SM (16 warps/SM, the occupancy that made R5 fast).
// FFMA2: accumulators paired along COLUMNS so the b-pairs come straight from
// LDS.128 (u[0], u[1]) — only 4 dup movs per k-step (a-scalars).
// K/V tiles register-prefetched one iteration ahead (LDG issued a full
// compute phase early).
// grid: (S/64 = 32, NBAT*NHEAD = 32), dynamic smem = 64 KB.
// ---------------------------------------------------------------------------
__device__ __forceinline__ int swz4(int maj, int min4)
{
    // float offset of the 4-aligned group (maj, min4*4) in a [64][64] buffer
    return (maj << 6) + ((min4 ^ ((maj >> 2) & 15)) << 2);
}

__global__ __launch_bounds__(256, 2)
void attention_kernel(const float* __restrict__ gQ, const float* __restrict__ gK,
                      const float* __restrict__ gV, float* __restrict__ gO)
{
    extern __shared__ float smem[];
    float* Qt = smem;           // [k][r] swizzled  (Q transposed, pre-scaled)
    float* Ks = smem + 4096;    // [k][c] swizzled  (K transposed)
    float* Vs = smem + 8192;    // [c][d] natural
    float* Pt = smem + 12288;   // [c][r] swizzled  (P transposed)

    const int t  = threadIdx.x;
    const int tx = t & 15, ty = t >> 4;
    const int ry = ty << 2, cx = tx << 2;
    // reverse order: heaviest causal blocks (large sb) launch first
    const int sb = (int)gridDim.x - 1 - (int)blockIdx.x;
    const int s0 = sb << 6;
    const int nh = blockIdx.y;
    const int n  = nh >> 3, h = nh & 7;

    const float* Qp = gQ + ((size_t)(n * SEQ + s0)) * EN + h * HDIM;
    const float* Kp = gK + (size_t)n * SEQ * EN + h * HDIM;
    const float* Vp = gV + (size_t)n * SEQ * EN + h * HDIM;

    // loader mapping (i = 0..3): row r_i = ty + 16*i, k-offset tx*4
    // (idx = t + i*256 -> k4 = tx, r = ty + 16i)

    // ---- prefetch K/V tile 0 into registers ----
    V4 kreg[4], vreg[4];
#pragma unroll
    for (int i = 0; i < 4; i++) {
        int r = ty + (i << 4);
        kreg[i].v = *(const float4*)(Kp + (size_t)r * EN + (tx << 2));
        vreg[i].v = *(const float4*)(Vp + (size_t)r * EN + (tx << 2));
    }

    // ---- load Q tile transposed+swizzled (pre-scaled by GEMM) ----
#pragma unroll
    for (int i = 0; i < 4; i++) {
        int r = ty + (i << 4);
        V4 q; q.v = *(const float4*)(Qp + (size_t)r * EN + (tx << 2));
        int r4 = r >> 2, rm3 = r & 3;
        int grp = ((r4 ^ tx) & 15) << 2;
#pragma unroll
        for (int e = 0; e < 4; e++)
            Qt[(((tx << 2) + e) << 6) + grp + rm3] = q.f[e];
    }

    // accO2[i][j2]: row ry+i, cols (cx+2*j2, cx+2*j2+1)
    F2 accO2[4][2];
    float rm[4], rl[4];
#pragma unroll
    for (int i = 0; i < 4; i++) {
        rm[i] = -1e30f; rl[i] = 0.0f;
        accO2[i][0].u = 0ull; accO2[i][1].u = 0ull;
    }

    for (int kb = 0; kb <= sb; kb++) {
        __syncthreads();   // previous tile's smem reads complete before overwrite

        // ---- store prefetched K (transposed+swizzled) and V (natural) ----
#pragma unroll
        for (int i = 0; i < 4; i++) {
            int r = ty + (i << 4);
            int r4 = r >> 2, rm3 = r & 3;
            int grp = ((r4 ^ tx) & 15) << 2;
#pragma unroll
            for (int e = 0; e < 4; e++)
                Ks[(((tx << 2) + e) << 6) + grp + rm3] = kreg[i].f[e];
            *(float4*)&Vs[(r << 6) + (tx << 2)] = vreg[i].v;
        }
        __syncthreads();

        // ---- prefetch next K/V tile (hidden under this tile's compute) ----
        if (kb < sb) {
            const float* Kn = Kp + ((size_t)((kb + 1) << 6)) * EN;
            const float* Vn = Vp + ((size_t)((kb + 1) << 6)) * EN;
#pragma unroll
            for (int i = 0; i < 4; i++) {
                int r = ty + (i << 4);
                kreg[i].v = *(const float4*)(Kn + (size_t)r * EN + (tx << 2));
                vreg[i].v = *(const float4*)(Vn + (size_t)r * EN + (tx << 2));
            }
        }

        // ---- S = Q K^T (Q pre-scaled); s2[i][j2]: row ry+i, col pair ----
        F2 s2[4][2];
#pragma unroll
        for (int i = 0; i < 4; i++) { s2[i][0].u = 0ull; s2[i][1].u = 0ull; }

#pragma unroll 8
        for (int k = 0; k < 64; k++) {
            V4 a, b;
            a.v = *(const float4*)&Qt[swz4(k, ty)];
            b.v = *(const float4*)&Ks[swz4(k, tx)];
            unsigned long long a0 = dup2(a.f[0]);
            unsigned long long a1 = dup2(a.f[1]);
            unsigned long long a2 = dup2(a.f[2]);
            unsigned long long a3 = dup2(a.f[3]);
            fma2(s2[0][0].u, a0, b.u[0]); fma2(s2[0][1].u, a0, b.u[1]);
            fma2(s2[1][0].u, a1, b.u[0]); fma2(s2[1][1].u, a1, b.u[1]);
            fma2(s2[2][0].u, a2, b.u[0]); fma2(s2[2][1].u, a2, b.u[1]);
            fma2(s2[3][0].u, a3, b.u[0]); fma2(s2[3][1].u, a3, b.u[1]);
        }

        if (kb == sb) {   // diagonal tile: causal mask (col > row)
#pragma unroll
            for (int i = 0; i < 4; i++)
#pragma unroll
                for (int j2 = 0; j2 < 2; j2++) {
                    int c = cx + (j2 << 1), r = ry + i;
                    if (c > r)     s2[i][j2].f.x = -1e30f;
                    if (c + 1 > r) s2[i][j2].f.y = -1e30f;
                }
        }

        // ---- online softmax update (row groups = 16 lanes) ----
#pragma unroll
        for (int i = 0; i < 4; i++) {
            float mx = fmaxf(fmaxf(s2[i][0].f.x, s2[i][0].f.y),
                             fmaxf(s2[i][1].f.x, s2[i][1].f.y));
            mx = fmaxf(mx, __shfl_xor_sync(0xffffffffu, mx, 1));
            mx = fmaxf(mx, __shfl_xor_sync(0xffffffffu, mx, 2));
            mx = fmaxf(mx, __shfl_xor_sync(0xffffffffu, mx, 4));
            mx = fmaxf(mx, __shfl_xor_sync(0xffffffffu, mx, 8));
            float nm    = fmaxf(rm[i], mx);
            float alpha = __expf(rm[i] - nm);
            float e0 = __expf(s2[i][0].f.x - nm);
            float e1 = __expf(s2[i][0].f.y - nm);
            float e2 = __expf(s2[i][1].f.x - nm);
            float e3 = __expf(s2[i][1].f.y - nm);
            s2[i][0].f.x = e0; s2[i][0].f.y = e1;
            s2[i][1].f.x = e2; s2[i][1].f.y = e3;
            float ps = (e0 + e1) + (e2 + e3);
            ps += __shfl_xor_sync(0xffffffffu, ps, 1);
            ps += __shfl_xor_sync(0xffffffffu, ps, 2);
            ps += __shfl_xor_sync(0xffffffffu, ps, 4);
            ps += __shfl_xor_sync(0xffffffffu, ps, 8);
            rl[i] = rl[i] * alpha + ps;
            rm[i] = nm;
            unsigned long long al2 = dup2(alpha);
            // accO *= alpha  (packed: acc = acc*alpha via fma with 0 add? no —
            // plain packed multiply)
            asm("mul.rn.f32x2 %0, %0, %1;" : "+l"(accO2[i][0].u) : "l"(al2));
            asm("mul.rn.f32x2 %0, %0, %1;" : "+l"(accO2[i][1].u) : "l"(al2));
        }

        // ---- write P transposed ([c][r], swizzled) ----
#pragma unroll
        for (int j = 0; j < 4; j++) {
            int c = cx + j, j2 = j >> 1;
            float4 p;
            if (j & 1)
                p = make_float4(s2[0][j2].f.y, s2[1][j2].f.y,
                                s2[2][j2].f.y, s2[3][j2].f.y);
            else
                p = make_float4(s2[0][j2].f.x, s2[1][j2].f.x,
                                s2[2][j2].f.x, s2[3][j2].f.x);
            *(float4*)&Pt[swz4(c, ty)] = p;
        }
        __syncthreads();

        // ---- O += P V ----
#pragma unroll 8
        for (int c = 0; c < 64; c++) {
            V4 a, b;
            a.v = *(const float4*)&Pt[swz4(c, ty)];
            b.v = *(const float4*)&Vs[(c << 6) + cx];
            unsigned long long a0 = dup2(a.f[0]);
            unsigned long long a1 = dup2(a.f[1]);
            unsigned long long a2 = dup2(a.f[2]);
            unsigned long long a3 = dup2(a.f[3]);
            fma2(accO2[0][0].u, a0, b.u[0]); fma2(accO2[0][1].u, a0, b.u[1]);
            fma2(accO2[1][0].u, a1, b.u[0]); fma2(accO2[1][1].u, a1, b.u[1]);
            fma2(accO2[2][0].u, a2, b.u[0]); fma2(accO2[2][1].u, a2, b.u[1]);
            fma2(accO2[3][0].u, a3, b.u[0]); fma2(accO2[3][1].u, a3, b.u[1]);
        }
    }

    // ---- epilogue: normalize and store (n, s, h*HD + d) layout ----
    float* Op = gO + (size_t)(n * SEQ + s0 + ry) * EN + h * HDIM + cx;
#pragma unroll
    for (int i = 0; i < 4; i++) {
        float inv = 1.0f / rl[i];
        float4 o = make_float4(accO2[i][0].f.x * inv, accO2[i][0].f.y * inv,
                               accO2[i][1].f.x * inv, accO2[i][1].f.y * inv);
        *(float4*)(Op + (size_t)i * EN) = o;
    }
}

// ---------------------------------------------------------------------------
// kernel_launch: 3 projections -> attention -> output projection.
// Scale 1/sqrt(HD) = 0.125 folded into Q projection (bias included, matching
// the reference which scales (xWq^T + bq) dot products).
// ---------------------------------------------------------------------------
extern "C" void kernel_launch(void* const* d_in, const int* in_sizes, int n_in,
                              void* d_out, int out_size)
{
    (void)in_sizes; (void)n_in; (void)out_size;

    const float* query = (const float*)d_in[0];
    const float* key   = (const float*)d_in[1];
    const float* value = (const float*)d_in[2];
    // d_in[3] = attn_mask (int32 tril) -- causal, handled analytically
    const float* Wq = (const float*)d_in[4];
    const float* bq = (const float*)d_in[5];
    const float* Wk = (const float*)d_in[6];
    const float* bk = (const float*)d_in[7];
    const float* Wv = (const float*)d_in[8];
    const float* bv = (const float*)d_in[9];
    const float* Wp = (const float*)d_in[10];
    const float* bp = (const float*)d_in[11];
    float* out = (float*)d_out;

    void* sp = nullptr;
    cudaGetSymbolAddress(&sp, g_scratch);
    float* gQ = (float*)sp;
    float* gK = gQ + NSE;
    float* gV = gK + NSE;
    float* gO = gV + NSE;

    cudaFuncSetAttribute(attention_kernel,
                         cudaFuncAttributeMaxDynamicSharedMemorySize, 65536);

    dim3 gg(EN / 128, MTOT / 128);   // (4, 64)
    gemm_bias_kernel<<<gg, 256>>>(query, Wq, bq, gQ, 0.125f);
    gemm_bias_kernel<<<gg, 256>>>(key,   Wk, bk, gK, 1.0f);
    gemm_bias_kernel<<<gg, 256>>>(value, Wv, bv, gV, 1.0f);
    attention_kernel<<<dim3(SEQ / 64, NBAT * NHEAD), 256, 65536>>>(gQ, gK, gV, gO);
    gemm_bias_kernel<<<gg, 256>>>(gO, Wp, bp, out, 1.0f);
}

// round 11
// speedup vs baseline: 1.2900x; 1.2196x over previous
#include <cuda_runtime.h>
#include <cuda_bf16.h>
#include <mma.h>
#include <cstdint>

using namespace nvcuda;

// Problem constants
#define EN    512
#define SEQ   2048
#define NBAT  4
#define NHEAD 8
#define HDIM  64
#define MTOT  (NBAT * SEQ)          // 8192
#define NSE   (NBAT * SEQ * EN)     // 4,194,304 floats per buffer
#define FM    (1024 * 1024)

// 132 MB scratch: fp32 Q,K,V,O + bf16 hi/lo split buffers + split weights
__device__ float g_scratch[33ull * FM];

// ---------------------------------------------------------------------------
// Packed fp32x2 helpers (attention kernel)
// ---------------------------------------------------------------------------
union V4 { float4 v; unsigned long long u[2]; float f[4]; };
union F2 { unsigned long long u; float2 f; };

__device__ __forceinline__ unsigned long long dup2(float x)
{
    unsigned long long r;
    asm("mov.b64 %0, {%1, %1};" : "=l"(r) : "f"(x));
    return r;
}
__device__ __forceinline__ void fma2(unsigned long long& d,
                                     unsigned long long a, unsigned long long b)
{
    asm("fma.rn.f32x2 %0, %1, %2, %0;" : "+l"(d) : "l"(a), "l"(b));
}

// ---------------------------------------------------------------------------
// Split fp32 -> bf16 (hi, lo):  x = hi + lo + O(2^-17 x)
// ---------------------------------------------------------------------------
__global__ void split_kernel(const float* __restrict__ x,
                             __nv_bfloat16* __restrict__ hi,
                             __nv_bfloat16* __restrict__ lo, int n4)
{
    int i = blockIdx.x * blockDim.x + threadIdx.x;
    if (i >= n4) return;
    float4 v = ((const float4*)x)[i];
    __nv_bfloat16 h0 = __float2bfloat16_rn(v.x);
    __nv_bfloat16 h1 = __float2bfloat16_rn(v.y);
    __nv_bfloat16 h2 = __float2bfloat16_rn(v.z);
    __nv_bfloat16 h3 = __float2bfloat16_rn(v.w);
    __nv_bfloat16 l0 = __float2bfloat16_rn(v.x - __bfloat162float(h0));
    __nv_bfloat16 l1 = __float2bfloat16_rn(v.y - __bfloat162float(h1));
    __nv_bfloat16 l2 = __float2bfloat16_rn(v.z - __bfloat162float(h2));
    __nv_bfloat16 l3 = __float2bfloat16_rn(v.w - __bfloat162float(h3));
    __nv_bfloat162* hp = (__nv_bfloat162*)hi;
    __nv_bfloat162* lp = (__nv_bfloat162*)lo;
    hp[2 * i]     = __nv_bfloat162(h0, h1);
    hp[2 * i + 1] = __nv_bfloat162(h2, h3);
    lp[2 * i]     = __nv_bfloat162(l0, l1);
    lp[2 * i + 1] = __nv_bfloat162(l2, l3);
}

// ---------------------------------------------------------------------------
// WMMA GEMM: C[m][n] = (sum_k A[m][k]*W[n][k] + bias[n]) * scale
// bf16 hi/lo split, 3 terms: hi*hi + hi*lo + lo*hi (fp32 accum).
// CTA tile 128x128, BK=32, 256 threads = 8 warps, warp tile 32x64
// (2x4 m16n16k16 accum frags). Register-prefetched global loads.
// grid: (EN/128 = 4, M/128).
// ---------------------------------------------------------------------------
#define LDT 40   // smem row stride (bf16 elems): 80 B, 16B-aligned, padded

#define GEMM_SM (4 * 128 * LDT * 2 + 16 * 128 * 4)   // 40960 + 8192 = 49152

__global__ __launch_bounds__(256, 1)
void gemm_wmma_kernel(const __nv_bfloat16* __restrict__ Ahi,
                      const __nv_bfloat16* __restrict__ Alo,
                      const __nv_bfloat16* __restrict__ Whi,
                      const __nv_bfloat16* __restrict__ Wlo,
                      const float* __restrict__ bias,
                      float* __restrict__ C, float scale)
{
    extern __shared__ char smraw[];
    __nv_bfloat16* sAh = (__nv_bfloat16*)smraw;       // [128][LDT]
    __nv_bfloat16* sAl = sAh + 128 * LDT;
    __nv_bfloat16* sWh = sAl + 128 * LDT;
    __nv_bfloat16* sWl = sWh + 128 * LDT;
    float* sBias = (float*)(sWl + 128 * LDT);         // [16][128] replicated

    const int t   = threadIdx.x;
    const int wid = t >> 5;
    const int n0  = blockIdx.x << 7;
    const int m0  = blockIdx.y << 7;
    const int wm  = wid >> 1;        // 0..3  -> rows wm*32
    const int wn  = wid & 1;         // 0..1  -> cols wn*64

    for (int i = t; i < 16 * 128; i += 256) sBias[i] = bias[n0 + (i & 127)];

    // loader mapping: 512 uint4 per 128x32 tile; thread t handles
    // v = t + j*256 (j=0,1): row = v>>2 (0..127), kq = v&3 (k-offset kq*8)
    const int lr0 = t >> 2, lkq = (t & 3) << 3;

    wmma::fragment<wmma::accumulator, 16, 16, 16, float> acc[2][4];
#pragma unroll
    for (int i = 0; i < 2; i++)
#pragma unroll
        for (int j = 0; j < 4; j++) wmma::fill_fragment(acc[i][j], 0.0f);

    // prefetch chunk 0
    uint4 pAh[2], pAl[2], pWh[2], pWl[2];
#pragma unroll
    for (int j = 0; j < 2; j++) {
        int row = lr0 + j * 64;
        size_t ao = (size_t)(m0 + row) * EN + lkq;
        size_t wo = (size_t)(n0 + row) * EN + lkq;
        pAh[j] = *(const uint4*)(Ahi + ao);
        pAl[j] = *(const uint4*)(Alo + ao);
        pWh[j] = *(const uint4*)(Whi + wo);
        pWl[j] = *(const uint4*)(Wlo + wo);
    }

    for (int kt = 0; kt < EN; kt += 32) {
#pragma unroll
        for (int j = 0; j < 2; j++) {
            int row = lr0 + j * 64;
            *(uint4*)(sAh + row * LDT + lkq) = pAh[j];
            *(uint4*)(sAl + row * LDT + lkq) = pAl[j];
            *(uint4*)(sWh + row * LDT + lkq) = pWh[j];
            *(uint4*)(sWl + row * LDT + lkq) = pWl[j];
        }
        __syncthreads();

        if (kt + 32 < EN) {
#pragma unroll
            for (int j = 0; j < 2; j++) {
                int row = lr0 + j * 64;
                size_t ao = (size_t)(m0 + row) * EN + kt + 32 + lkq;
                size_t wo = (size_t)(n0 + row) * EN + kt + 32 + lkq;
                pAh[j] = *(const uint4*)(Ahi + ao);
                pAl[j] = *(const uint4*)(Alo + ao);
                pWh[j] = *(const uint4*)(Whi + wo);
                pWl[j] = *(const uint4*)(Wlo + wo);
            }
        }

#pragma unroll
        for (int kk = 0; kk < 32; kk += 16) {
            wmma::fragment<wmma::matrix_a, 16, 16, 16, __nv_bfloat16,
                           wmma::row_major> ah[2], al[2];
            wmma::fragment<wmma::matrix_b, 16, 16, 16, __nv_bfloat16,
                           wmma::col_major> bh[4], bl[4];
#pragma unroll
            for (int i = 0; i < 2; i++) {
                int r = wm * 32 + i * 16;
                wmma::load_matrix_sync(ah[i], sAh + r * LDT + kk, LDT);
                wmma::load_matrix_sync(al[i], sAl + r * LDT + kk, LDT);
            }
#pragma unroll
            for (int j = 0; j < 4; j++) {
                int c = wn * 64 + j * 16;
                wmma::load_matrix_sync(bh[j], sWh + c * LDT + kk, LDT);
                wmma::load_matrix_sync(bl[j], sWl + c * LDT + kk, LDT);
            }
#pragma unroll
            for (int i = 0; i < 2; i++)
#pragma unroll
                for (int j = 0; j < 4; j++) {
                    wmma::mma_sync(acc[i][j], ah[i], bh[j], acc[i][j]);
                    wmma::mma_sync(acc[i][j], ah[i], bl[j], acc[i][j]);
                    wmma::mma_sync(acc[i][j], al[i], bh[j], acc[i][j]);
                }
        }
        __syncthreads();
    }

    // epilogue: bias (replicated-tile accumulator fragment) + scale, store
    wmma::fragment<wmma::accumulator, 16, 16, 16, float> bf;
#pragma unroll
    for (int j = 0; j < 4; j++) {
        int c = wn * 64 + j * 16;
        wmma::load_matrix_sync(bf, sBias + c, 128, wmma::mem_row_major);
#pragma unroll
        for (int i = 0; i < 2; i++) {
            int r = wm * 32 + i * 16;
#pragma unroll
            for (int e = 0; e < bf.num_elements; e++)
                acc[i][j].x[e] = (acc[i][j].x[e] + bf.x[e]) * scale;
            wmma::store_matrix_sync(C + (size_t)(m0 + r) * EN + n0 + c,
                                    acc[i][j], EN, wmma::mem_row_major);
        }
    }
}

// ---------------------------------------------------------------------------
// Flash attention, fp32, causal, FFMA2 inner products (R9 verified, 564 us).
// Br = Bc = 64, 256 threads, 4x4 micro-tiles, 64 KB smem, 2 CTAs/SM.
// ---------------------------------------------------------------------------
__device__ __forceinline__ int swz4(int maj, int min4)
{
    return (maj << 6) + ((min4 ^ ((maj >> 2) & 15)) << 2);
}

__global__ __launch_bounds__(256, 2)
void attention_kernel(const float* __restrict__ gQ, const float* __restrict__ gK,
                      const float* __restrict__ gV, float* __restrict__ gO)
{
    extern __shared__ float smem[];
    float* Qt = smem;           // [k][r] swizzled  (Q transposed, pre-scaled)
    float* Ks = smem + 4096;    // [k][c] swizzled  (K transposed)
    float* Vs = smem + 8192;    // [c][d] natural
    float* Pt = smem + 12288;   // [c][r] swizzled  (P transposed)

    const int t  = threadIdx.x;
    const int tx = t & 15, ty = t >> 4;
    const int ry = ty << 2, cx = tx << 2;
    const int sb = (int)gridDim.x - 1 - (int)blockIdx.x;
    const int s0 = sb << 6;
    const int nh = blockIdx.y;
    const int n  = nh >> 3, h = nh & 7;

    const float* Qp = gQ + ((size_t)(n * SEQ + s0)) * EN + h * HDIM;
    const float* Kp = gK + (size_t)n * SEQ * EN + h * HDIM;
    const float* Vp = gV + (size_t)n * SEQ * EN + h * HDIM;

    V4 kreg[4], vreg[4];
#pragma unroll
    for (int i = 0; i < 4; i++) {
        int r = ty + (i << 4);
        kreg[i].v = *(const float4*)(Kp + (size_t)r * EN + (tx << 2));
        vreg[i].v = *(const float4*)(Vp + (size_t)r * EN + (tx << 2));
    }

#pragma unroll
    for (int i = 0; i < 4; i++) {
        int r = ty + (i << 4);
        V4 q; q.v = *(const float4*)(Qp + (size_t)r * EN + (tx << 2));
        int r4 = r >> 2, rm3 = r & 3;
        int grp = ((r4 ^ tx) & 15) << 2;
#pragma unroll
        for (int e = 0; e < 4; e++)
            Qt[(((tx << 2) + e) << 6) + grp + rm3] = q.f[e];
    }

    F2 accO2[4][2];
    float rm[4], rl[4];
#pragma unroll
    for (int i = 0; i < 4; i++) {
        rm[i] = -1e30f; rl[i] = 0.0f;
        accO2[i][0].u = 0ull; accO2[i][1].u = 0ull;
    }

    for (int kb = 0; kb <= sb; kb++) {
        __syncthreads();

#pragma unroll
        for (int i = 0; i < 4; i++) {
            int r = ty + (i << 4);
            int r4 = r >> 2, rm3 = r & 3;
            int grp = ((r4 ^ tx) & 15) << 2;
#pragma unroll
            for (int e = 0; e < 4; e++)
                Ks[(((tx << 2) + e) << 6) + grp + rm3] = kreg[i].f[e];
            *(float4*)&Vs[(r << 6) + (tx << 2)] = vreg[i].v;
        }
        __syncthreads();

        if (kb < sb) {
            const float* Kn = Kp + ((size_t)((kb + 1) << 6)) * EN;
            const float* Vn = Vp + ((size_t)((kb + 1) << 6)) * EN;
#pragma unroll
            for (int i = 0; i < 4; i++) {
                int r = ty + (i << 4);
                kreg[i].v = *(const float4*)(Kn + (size_t)r * EN + (tx << 2));
                vreg[i].v = *(const float4*)(Vn + (size_t)r * EN + (tx << 2));
            }
        }

        F2 s2[4][2];
#pragma unroll
        for (int i = 0; i < 4; i++) { s2[i][0].u = 0ull; s2[i][1].u = 0ull; }

#pragma unroll 8
        for (int k = 0; k < 64; k++) {
            V4 a, b;
            a.v = *(const float4*)&Qt[swz4(k, ty)];
            b.v = *(const float4*)&Ks[swz4(k, tx)];
            unsigned long long a0 = dup2(a.f[0]);
            unsigned long long a1 = dup2(a.f[1]);
            unsigned long long a2 = dup2(a.f[2]);
            unsigned long long a3 = dup2(a.f[3]);
            fma2(s2[0][0].u, a0, b.u[0]); fma2(s2[0][1].u, a0, b.u[1]);
            fma2(s2[1][0].u, a1, b.u[0]); fma2(s2[1][1].u, a1, b.u[1]);
            fma2(s2[2][0].u, a2, b.u[0]); fma2(s2[2][1].u, a2, b.u[1]);
            fma2(s2[3][0].u, a3, b.u[0]); fma2(s2[3][1].u, a3, b.u[1]);
        }

        if (kb == sb) {
#pragma unroll
            for (int i = 0; i < 4; i++)
#pragma unroll
                for (int j2 = 0; j2 < 2; j2++) {
                    int c = cx + (j2 << 1), r = ry + i;
                    if (c > r)     s2[i][j2].f.x = -1e30f;
                    if (c + 1 > r) s2[i][j2].f.y = -1e30f;
                }
        }

#pragma unroll
        for (int i = 0; i < 4; i++) {
            float mx = fmaxf(fmaxf(s2[i][0].f.x, s2[i][0].f.y),
                             fmaxf(s2[i][1].f.x, s2[i][1].f.y));
            mx = fmaxf(mx, __shfl_xor_sync(0xffffffffu, mx, 1));
            mx = fmaxf(mx, __shfl_xor_sync(0xffffffffu, mx, 2));
            mx = fmaxf(mx, __shfl_xor_sync(0xffffffffu, mx, 4));
            mx = fmaxf(mx, __shfl_xor_sync(0xffffffffu, mx, 8));
            float nm    = fmaxf(rm[i], mx);
            float alpha = __expf(rm[i] - nm);
            float e0 = __expf(s2[i][0].f.x - nm);
            float e1 = __expf(s2[i][0].f.y - nm);
            float e2 = __expf(s2[i][1].f.x - nm);
            float e3 = __expf(s2[i][1].f.y - nm);
            s2[i][0].f.x = e0; s2[i][0].f.y = e1;
            s2[i][1].f.x = e2; s2[i][1].f.y = e3;
            float ps = (e0 + e1) + (e2 + e3);
            ps += __shfl_xor_sync(0xffffffffu, ps, 1);
            ps += __shfl_xor_sync(0xffffffffu, ps, 2);
            ps += __shfl_xor_sync(0xffffffffu, ps, 4);
            ps += __shfl_xor_sync(0xffffffffu, ps, 8);
            rl[i] = rl[i] * alpha + ps;
            rm[i] = nm;
            unsigned long long al2 = dup2(alpha);
            asm("mul.rn.f32x2 %0, %0, %1;" : "+l"(accO2[i][0].u) : "l"(al2));
            asm("mul.rn.f32x2 %0, %0, %1;" : "+l"(accO2[i][1].u) : "l"(al2));
        }

#pragma unroll
        for (int j = 0; j < 4; j++) {
            int c = cx + j, j2 = j >> 1;
            float4 p;
            if (j & 1)
                p = make_float4(s2[0][j2].f.y, s2[1][j2].f.y,
                                s2[2][j2].f.y, s2[3][j2].f.y);
            else
                p = make_float4(s2[0][j2].f.x, s2[1][j2].f.x,
                                s2[2][j2].f.x, s2[3][j2].f.x);
            *(float4*)&Pt[swz4(c, ty)] = p;
        }
        __syncthreads();

#pragma unroll 8
        for (int c = 0; c < 64; c++) {
            V4 a, b;
            a.v = *(const float4*)&Pt[swz4(c, ty)];
            b.v = *(const float4*)&Vs[(c << 6) + cx];
            unsigned long long a0 = dup2(a.f[0]);
            unsigned long long a1 = dup2(a.f[1]);
            unsigned long long a2 = dup2(a.f[2]);
            unsigned long long a3 = dup2(a.f[3]);
            fma2(accO2[0][0].u, a0, b.u[0]); fma2(accO2[0][1].u, a0, b.u[1]);
            fma2(accO2[1][0].u, a1, b.u[0]); fma2(accO2[1][1].u, a1, b.u[1]);
            fma2(accO2[2][0].u, a2, b.u[0]); fma2(accO2[2][1].u, a2, b.u[1]);
            fma2(accO2[3][0].u, a3, b.u[0]); fma2(accO2[3][1].u, a3, b.u[1]);
        }
    }

    float* Op = gO + (size_t)(n * SEQ + s0 + ry) * EN + h * HDIM + cx;
#pragma unroll
    for (int i = 0; i < 4; i++) {
        float inv = 1.0f / rl[i];
        float4 o = make_float4(accO2[i][0].f.x * inv, accO2[i][0].f.y * inv,
                               accO2[i][1].f.x * inv, accO2[i][1].f.y * inv);
        *(float4*)(Op + (size_t)i * EN) = o;
    }
}

// ---------------------------------------------------------------------------
// kernel_launch: split -> 3 WMMA projections -> attention -> split ->
// WMMA output projection.  1/sqrt(HD) folded into Q projection epilogue.
// ---------------------------------------------------------------------------
extern "C" void kernel_launch(void* const* d_in, const int* in_sizes, int n_in,
                              void* d_out, int out_size)
{
    (void)in_sizes; (void)n_in; (void)out_size;

    const float* query = (const float*)d_in[0];
    const float* key   = (const float*)d_in[1];
    const float* value = (const float*)d_in[2];
    // d_in[3] = attn_mask (int32 tril) -- causal, handled analytically
    const float* Wq = (const float*)d_in[4];
    const float* bq = (const float*)d_in[5];
    const float* Wk = (const float*)d_in[6];
    const float* bk = (const float*)d_in[7];
    const float* Wv = (const float*)d_in[8];
    const float* bv = (const float*)d_in[9];
    const float* Wp = (const float*)d_in[10];
    const float* bp = (const float*)d_in[11];
    float* out = (float*)d_out;

    void* sp = nullptr;
    cudaGetSymbolAddress(&sp, g_scratch);
    float* base = (float*)sp;
    float* gQ = base;
    float* gK = base + 4ull * FM;
    float* gV = base + 8ull * FM;
    float* gO = base + 12ull * FM;
    __nv_bfloat16* qhi = (__nv_bfloat16*)(base + 16ull * FM);
    __nv_bfloat16* qlo = (__nv_bfloat16*)(base + 18ull * FM);
    __nv_bfloat16* khi = (__nv_bfloat16*)(base + 20ull * FM);
    __nv_bfloat16* klo = (__nv_bfloat16*)(base + 22ull * FM);
    __nv_bfloat16* vhi = (__nv_bfloat16*)(base + 24ull * FM);
    __nv_bfloat16* vlo = (__nv_bfloat16*)(base + 26ull * FM);
    __nv_bfloat16* ohi = (__nv_bfloat16*)(base + 28ull * FM);
    __nv_bfloat16* olo = (__nv_bfloat16*)(base + 30ull * FM);
    __nv_bfloat16* wb  = (__nv_bfloat16*)(base + 32ull * FM);
    __nv_bfloat16* wqh = wb;            __nv_bfloat16* wql = wb + 262144;
    __nv_bfloat16* wkh = wb + 524288;   __nv_bfloat16* wkl = wb + 786432;
    __nv_bfloat16* wvh = wb + 1048576;  __nv_bfloat16* wvl = wb + 1310720;
    __nv_bfloat16* wph = wb + 1572864;  __nv_bfloat16* wpl = wb + 1835008;

    cudaFuncSetAttribute(attention_kernel,
                         cudaFuncAttributeMaxDynamicSharedMemorySize, 65536);
    cudaFuncSetAttribute(gemm_wmma_kernel,
                         cudaFuncAttributeMaxDynamicSharedMemorySize, GEMM_SM);

    const int NB = NSE / 4;       // 1,048,576 float4s per big tensor
    const int WB = EN * EN / 4;   // 65,536 per weight
    split_kernel<<<NB / 256, 256>>>(query, qhi, qlo, NB);
    split_kernel<<<NB / 256, 256>>>(key,   khi, klo, NB);
    split_kernel<<<NB / 256, 256>>>(value, vhi, vlo, NB);
    split_kernel<<<WB / 256, 256>>>(Wq, wqh, wql, WB);
    split_kernel<<<WB / 256, 256>>>(Wk, wkh, wkl, WB);
    split_kernel<<<WB / 256, 256>>>(Wv, wvh, wvl, WB);
    split_kernel<<<WB / 256, 256>>>(Wp, wph, wpl, WB);

    dim3 gg(EN / 128, MTOT / 128);   // (4, 64)
    gemm_wmma_kernel<<<gg, 256, GEMM_SM>>>(qhi, qlo, wqh, wql, bq, gQ, 0.125f);
    gemm_wmma_kernel<<<gg, 256, GEMM_SM>>>(khi, klo, wkh, wkl, bk, gK, 1.0f);
    gemm_wmma_kernel<<<gg, 256, GEMM_SM>>>(vhi, vlo, wvh, wvl, bv, gV, 1.0f);

    attention_kernel<<<dim3(SEQ / 64, NBAT * NHEAD), 256, 65536>>>(gQ, gK, gV, gO);

    split_kernel<<<NB / 256, 256>>>(gO, ohi, olo, NB);
    gemm_wmma_kernel<<<gg, 256, GEMM_SM>>>(ohi, olo, wph, wpl, bp, out, 1.0f);
}

// round 12
// speedup vs baseline: 1.6332x; 1.2661x over previous
#include <cuda_runtime.h>
#include <cuda_bf16.h>
#include <mma.h>
#include <cstdint>

using namespace nvcuda;

// Problem constants
#define EN    512
#define SEQ   2048
#define NBAT  4
#define NHEAD 8
#define HDIM  64
#define MTOT  (NBAT * SEQ)          // 8192
#define NSE   (NBAT * SEQ * EN)     // 4,194,304 floats per buffer
#define FM    (1024 * 1024)

// 132 MB scratch
__device__ float g_scratch[33ull * FM];

// ---------------------------------------------------------------------------
// Split fp32 -> bf16 (hi, lo):  x = hi + lo + O(2^-17 x)
// ---------------------------------------------------------------------------
__global__ void split_kernel(const float* __restrict__ x,
                             __nv_bfloat16* __restrict__ hi,
                             __nv_bfloat16* __restrict__ lo, int n4)
{
    int i = blockIdx.x * blockDim.x + threadIdx.x;
    if (i >= n4) return;
    float4 v = ((const float4*)x)[i];
    __nv_bfloat16 h0 = __float2bfloat16_rn(v.x);
    __nv_bfloat16 h1 = __float2bfloat16_rn(v.y);
    __nv_bfloat16 h2 = __float2bfloat16_rn(v.z);
    __nv_bfloat16 h3 = __float2bfloat16_rn(v.w);
    __nv_bfloat16 l0 = __float2bfloat16_rn(v.x - __bfloat162float(h0));
    __nv_bfloat16 l1 = __float2bfloat16_rn(v.y - __bfloat162float(h1));
    __nv_bfloat16 l2 = __float2bfloat16_rn(v.z - __bfloat162float(h2));
    __nv_bfloat16 l3 = __float2bfloat16_rn(v.w - __bfloat162float(h3));
    __nv_bfloat162* hp = (__nv_bfloat162*)hi;
    __nv_bfloat162* lp = (__nv_bfloat162*)lo;
    hp[2 * i]     = __nv_bfloat162(h0, h1);
    hp[2 * i + 1] = __nv_bfloat162(h2, h3);
    lp[2 * i]     = __nv_bfloat162(l0, l1);
    lp[2 * i + 1] = __nv_bfloat162(l2, l3);
}

// ---------------------------------------------------------------------------
// WMMA GEMM (verified R11): C = (A W^T + bias) * scale, 3-term hi/lo split.
// CTA tile 128x128, BK=32, 8 warps, warp tile 32x64.
// ---------------------------------------------------------------------------
#define LDT 40
#define GEMM_SM (4 * 128 * LDT * 2 + 16 * 128 * 4)   // 49152

__global__ __launch_bounds__(256, 1)
void gemm_wmma_kernel(const __nv_bfloat16* __restrict__ Ahi,
                      const __nv_bfloat16* __restrict__ Alo,
                      const __nv_bfloat16* __restrict__ Whi,
                      const __nv_bfloat16* __restrict__ Wlo,
                      const float* __restrict__ bias,
                      float* __restrict__ C, float scale)
{
    extern __shared__ char smraw[];
    __nv_bfloat16* sAh = (__nv_bfloat16*)smraw;       // [128][LDT]
    __nv_bfloat16* sAl = sAh + 128 * LDT;
    __nv_bfloat16* sWh = sAl + 128 * LDT;
    __nv_bfloat16* sWl = sWh + 128 * LDT;
    float* sBias = (float*)(sWl + 128 * LDT);         // [16][128] replicated

    const int t   = threadIdx.x;
    const int wid = t >> 5;
    const int n0  = blockIdx.x << 7;
    const int m0  = blockIdx.y << 7;
    const int wm  = wid >> 1;
    const int wn  = wid & 1;

    for (int i = t; i < 16 * 128; i += 256) sBias[i] = bias[n0 + (i & 127)];

    const int lr0 = t >> 2, lkq = (t & 3) << 3;

    wmma::fragment<wmma::accumulator, 16, 16, 16, float> acc[2][4];
#pragma unroll
    for (int i = 0; i < 2; i++)
#pragma unroll
        for (int j = 0; j < 4; j++) wmma::fill_fragment(acc[i][j], 0.0f);

    uint4 pAh[2], pAl[2], pWh[2], pWl[2];
#pragma unroll
    for (int j = 0; j < 2; j++) {
        int row = lr0 + j * 64;
        size_t ao = (size_t)(m0 + row) * EN + lkq;
        size_t wo = (size_t)(n0 + row) * EN + lkq;
        pAh[j] = *(const uint4*)(Ahi + ao);
        pAl[j] = *(const uint4*)(Alo + ao);
        pWh[j] = *(const uint4*)(Whi + wo);
        pWl[j] = *(const uint4*)(Wlo + wo);
    }

    for (int kt = 0; kt < EN; kt += 32) {
#pragma unroll
        for (int j = 0; j < 2; j++) {
            int row = lr0 + j * 64;
            *(uint4*)(sAh + row * LDT + lkq) = pAh[j];
            *(uint4*)(sAl + row * LDT + lkq) = pAl[j];
            *(uint4*)(sWh + row * LDT + lkq) = pWh[j];
            *(uint4*)(sWl + row * LDT + lkq) = pWl[j];
        }
        __syncthreads();

        if (kt + 32 < EN) {
#pragma unroll
            for (int j = 0; j < 2; j++) {
                int row = lr0 + j * 64;
                size_t ao = (size_t)(m0 + row) * EN + kt + 32 + lkq;
                size_t wo = (size_t)(n0 + row) * EN + kt + 32 + lkq;
                pAh[j] = *(const uint4*)(Ahi + ao);
                pAl[j] = *(const uint4*)(Alo + ao);
                pWh[j] = *(const uint4*)(Whi + wo);
                pWl[j] = *(const uint4*)(Wlo + wo);
            }
        }

#pragma unroll
        for (int kk = 0; kk < 32; kk += 16) {
            wmma::fragment<wmma::matrix_a, 16, 16, 16, __nv_bfloat16,
                           wmma::row_major> ah[2], al[2];
            wmma::fragment<wmma::matrix_b, 16, 16, 16, __nv_bfloat16,
                           wmma::col_major> bh[4], bl[4];
#pragma unroll
            for (int i = 0; i < 2; i++) {
                int r = wm * 32 + i * 16;
                wmma::load_matrix_sync(ah[i], sAh + r * LDT + kk, LDT);
                wmma::load_matrix_sync(al[i], sAl + r * LDT + kk, LDT);
            }
#pragma unroll
            for (int j = 0; j < 4; j++) {
                int c = wn * 64 + j * 16;
                wmma::load_matrix_sync(bh[j], sWh + c * LDT + kk, LDT);
                wmma::load_matrix_sync(bl[j], sWl + c * LDT + kk, LDT);
            }
#pragma unroll
            for (int i = 0; i < 2; i++)
#pragma unroll
                for (int j = 0; j < 4; j++) {
                    wmma::mma_sync(acc[i][j], ah[i], bh[j], acc[i][j]);
                    wmma::mma_sync(acc[i][j], ah[i], bl[j], acc[i][j]);
                    wmma::mma_sync(acc[i][j], al[i], bh[j], acc[i][j]);
                }
        }
        __syncthreads();
    }

    wmma::fragment<wmma::accumulator, 16, 16, 16, float> bf;
#pragma unroll
    for (int j = 0; j < 4; j++) {
        int c = wn * 64 + j * 16;
        wmma::load_matrix_sync(bf, sBias + c, 128, wmma::mem_row_major);
#pragma unroll
        for (int i = 0; i < 2; i++) {
            int r = wm * 32 + i * 16;
#pragma unroll
            for (int e = 0; e < bf.num_elements; e++)
                acc[i][j].x[e] = (acc[i][j].x[e] + bf.x[e]) * scale;
            wmma::store_matrix_sync(C + (size_t)(m0 + r) * EN + n0 + c,
                                    acc[i][j], EN, wmma::mem_row_major);
        }
    }
}

// ---------------------------------------------------------------------------
// WMMA flash attention, causal. Br = Bc = 64, HD = 64, 256 threads (8 warps),
// 2 CTAs/SM.  S = QK^T and O += PV both via 3-term bf16 hi/lo WMMA with fp32
// accumulation; online softmax in scalar registers (4 threads per row, O rows
// live in thread registers so fragment layout never needs per-row scaling).
// Inputs: pre-split bf16 hi/lo Q (pre-scaled by 0.125), K, V.
// Output: bf16 hi/lo O (feeds the out-projection GEMM directly).
// ---------------------------------------------------------------------------
#define ALA 72    // bf16 tile row stride (elems)
#define ALS 68    // fp32 S/PV row stride (elems)
#define ATT_TILE_B (64 * ALA * 2)          // 9216 bytes per bf16 tile
#define AOF_QH 0
#define AOF_QL (ATT_TILE_B)
#define AOF_KH (2 * ATT_TILE_B)
#define AOF_KL (3 * ATT_TILE_B)
#define AOF_VH (4 * ATT_TILE_B)
#define AOF_VL (5 * ATT_TILE_B)
#define AOF_PH (6 * ATT_TILE_B)
#define AOF_PL (7 * ATT_TILE_B)
#define AOF_S  (8 * ATT_TILE_B)            // 73728
#define ATT_SM (AOF_S + 64 * ALS * 4)      // 91136

__global__ __launch_bounds__(256, 2)
void attention_wmma_kernel(const __nv_bfloat16* __restrict__ qh,
                           const __nv_bfloat16* __restrict__ ql,
                           const __nv_bfloat16* __restrict__ kh,
                           const __nv_bfloat16* __restrict__ kl,
                           const __nv_bfloat16* __restrict__ vh,
                           const __nv_bfloat16* __restrict__ vl,
                           __nv_bfloat16* __restrict__ oh,
                           __nv_bfloat16* __restrict__ ol)
{
    extern __shared__ char smraw[];
    __nv_bfloat16* sQh = (__nv_bfloat16*)(smraw + AOF_QH);
    __nv_bfloat16* sQl = (__nv_bfloat16*)(smraw + AOF_QL);
    __nv_bfloat16* sKh = (__nv_bfloat16*)(smraw + AOF_KH);
    __nv_bfloat16* sKl = (__nv_bfloat16*)(smraw + AOF_KL);
    __nv_bfloat16* sVh = (__nv_bfloat16*)(smraw + AOF_VH);
    __nv_bfloat16* sVl = (__nv_bfloat16*)(smraw + AOF_VL);
    __nv_bfloat16* sPh = (__nv_bfloat16*)(smraw + AOF_PH);
    __nv_bfloat16* sPl = (__nv_bfloat16*)(smraw + AOF_PL);
    float*         sS  = (float*)(smraw + AOF_S);

    const int t    = threadIdx.x;
    const int w    = t >> 5;
    const int mw   = w >> 1;          // frag row group (0..3) -> rows mw*16
    const int cb   = (w & 1) << 5;    // frag col base (0 or 32)
    // heavy-first causal ordering
    const int sb = (int)gridDim.x - 1 - (int)blockIdx.x;
    const int s0 = sb << 6;
    const int nh = blockIdx.y;
    const int n  = nh >> 3, h = nh & 7;

    // softmax-land mapping: row r, column quarter qd (16 cols)
    const int r  = t >> 2;
    const int qd = t & 3;

    const size_t qbase = (size_t)(n * SEQ + s0) * EN + h * HDIM;
    const size_t kvb0  = (size_t)(n * SEQ) * EN + h * HDIM;

    // loader mapping: idx = t + j*256; row = idx>>3, 16B chunk = idx&7
    const int lr = t >> 3, lc = (t & 7) << 3;

    // ---- load Q tiles (hi/lo) ----
#pragma unroll
    for (int j = 0; j < 2; j++) {
        int row = lr + j * 32;
        size_t g = qbase + (size_t)row * EN + lc;
        *(uint4*)(sQh + row * ALA + lc) = *(const uint4*)(qh + g);
        *(uint4*)(sQl + row * ALA + lc) = *(const uint4*)(ql + g);
    }

    float accO[16];
    float rm = -1e30f, rl = 0.0f;
#pragma unroll
    for (int j = 0; j < 16; j++) accO[j] = 0.0f;

    for (int kb = 0; kb <= sb; kb++) {
        __syncthreads();   // prior tile fully consumed

        // ---- load K/V tiles (hi/lo) ----
        size_t kvb = kvb0 + (size_t)(kb << 6) * EN;
#pragma unroll
        for (int j = 0; j < 2; j++) {
            int row = lr + j * 32;
            size_t g = kvb + (size_t)row * EN + lc;
            *(uint4*)(sKh + row * ALA + lc) = *(const uint4*)(kh + g);
            *(uint4*)(sKl + row * ALA + lc) = *(const uint4*)(kl + g);
            *(uint4*)(sVh + row * ALA + lc) = *(const uint4*)(vh + g);
            *(uint4*)(sVl + row * ALA + lc) = *(const uint4*)(vl + g);
        }
        __syncthreads();

        // ---- S = Q K^T : 3-term WMMA ----
        {
            wmma::fragment<wmma::accumulator, 16, 16, 16, float> fc0, fc1;
            wmma::fill_fragment(fc0, 0.0f);
            wmma::fill_fragment(fc1, 0.0f);
#pragma unroll
            for (int ks = 0; ks < 64; ks += 16) {
                wmma::fragment<wmma::matrix_a, 16, 16, 16, __nv_bfloat16,
                               wmma::row_major> fa, fal;
                wmma::fragment<wmma::matrix_b, 16, 16, 16, __nv_bfloat16,
                               wmma::col_major> fb0, fb1, fl0, fl1;
                wmma::load_matrix_sync(fa,  sQh + mw * 16 * ALA + ks, ALA);
                wmma::load_matrix_sync(fal, sQl + mw * 16 * ALA + ks, ALA);
                wmma::load_matrix_sync(fb0, sKh + cb * ALA + ks, ALA);
                wmma::load_matrix_sync(fb1, sKh + (cb + 16) * ALA + ks, ALA);
                wmma::load_matrix_sync(fl0, sKl + cb * ALA + ks, ALA);
                wmma::load_matrix_sync(fl1, sKl + (cb + 16) * ALA + ks, ALA);
                wmma::mma_sync(fc0, fa,  fb0, fc0);
                wmma::mma_sync(fc0, fa,  fl0, fc0);
                wmma::mma_sync(fc0, fal, fb0, fc0);
                wmma::mma_sync(fc1, fa,  fb1, fc1);
                wmma::mma_sync(fc1, fa,  fl1, fc1);
                wmma::mma_sync(fc1, fal, fb1, fc1);
            }
            wmma::store_matrix_sync(sS + mw * 16 * ALS + cb, fc0, ALS,
                                    wmma::mem_row_major);
            wmma::store_matrix_sync(sS + mw * 16 * ALS + cb + 16, fc1, ALS,
                                    wmma::mem_row_major);
        }
        __syncthreads();

        // ---- online softmax (scalar; 4 threads per row) ----
        {
            float s[16];
            const float* Sr = sS + r * ALS + qd * 16;
#pragma unroll
            for (int j = 0; j < 16; j++) s[j] = Sr[j];
            if (kb == sb) {
#pragma unroll
                for (int j = 0; j < 16; j++)
                    if (qd * 16 + j > r) s[j] = -1e30f;
            }
            float mx = -1e30f;
#pragma unroll
            for (int j = 0; j < 16; j++) mx = fmaxf(mx, s[j]);
            mx = fmaxf(mx, __shfl_xor_sync(0xffffffffu, mx, 1));
            mx = fmaxf(mx, __shfl_xor_sync(0xffffffffu, mx, 2));
            float nm    = fmaxf(rm, mx);
            float alpha = __expf(rm - nm);
            float ps = 0.0f;
            __nv_bfloat162* Ph = (__nv_bfloat162*)(sPh + r * ALA + qd * 16);
            __nv_bfloat162* Pl = (__nv_bfloat162*)(sPl + r * ALA + qd * 16);
#pragma unroll
            for (int j = 0; j < 16; j += 2) {
                float e0 = __expf(s[j]     - nm);
                float e1 = __expf(s[j + 1] - nm);
                ps += e0 + e1;
                __nv_bfloat16 h0 = __float2bfloat16_rn(e0);
                __nv_bfloat16 h1 = __float2bfloat16_rn(e1);
                __nv_bfloat16 l0 = __float2bfloat16_rn(e0 - __bfloat162float(h0));
                __nv_bfloat16 l1 = __float2bfloat16_rn(e1 - __bfloat162float(h1));
                Ph[j >> 1] = __nv_bfloat162(h0, h1);
                Pl[j >> 1] = __nv_bfloat162(l0, l1);
            }
            ps += __shfl_xor_sync(0xffffffffu, ps, 1);
            ps += __shfl_xor_sync(0xffffffffu, ps, 2);
            rl = rl * alpha + ps;
            rm = nm;
#pragma unroll
            for (int j = 0; j < 16; j++) accO[j] *= alpha;
        }
        __syncthreads();

        // ---- PV = P V : 3-term WMMA ----
        {
            wmma::fragment<wmma::accumulator, 16, 16, 16, float> fc0, fc1;
            wmma::fill_fragment(fc0, 0.0f);
            wmma::fill_fragment(fc1, 0.0f);
#pragma unroll
            for (int ks = 0; ks < 64; ks += 16) {
                wmma::fragment<wmma::matrix_a, 16, 16, 16, __nv_bfloat16,
                               wmma::row_major> fa, fal;
                wmma::fragment<wmma::matrix_b, 16, 16, 16, __nv_bfloat16,
                               wmma::row_major> fb0, fb1, fl0, fl1;
                wmma::load_matrix_sync(fa,  sPh + mw * 16 * ALA + ks, ALA);
                wmma::load_matrix_sync(fal, sPl + mw * 16 * ALA + ks, ALA);
                wmma::load_matrix_sync(fb0, sVh + ks * ALA + cb, ALA);
                wmma::load_matrix_sync(fb1, sVh + ks * ALA + cb + 16, ALA);
                wmma::load_matrix_sync(fl0, sVl + ks * ALA + cb, ALA);
                wmma::load_matrix_sync(fl1, sVl + ks * ALA + cb + 16, ALA);
                wmma::mma_sync(fc0, fa,  fb0, fc0);
                wmma::mma_sync(fc0, fa,  fl0, fc0);
                wmma::mma_sync(fc0, fal, fb0, fc0);
                wmma::mma_sync(fc1, fa,  fb1, fc1);
                wmma::mma_sync(fc1, fa,  fl1, fc1);
                wmma::mma_sync(fc1, fal, fb1, fc1);
            }
            wmma::store_matrix_sync(sS + mw * 16 * ALS + cb, fc0, ALS,
                                    wmma::mem_row_major);
            wmma::store_matrix_sync(sS + mw * 16 * ALS + cb + 16, fc1, ALS,
                                    wmma::mem_row_major);
        }
        __syncthreads();

        // ---- merge: O += PV ----
        {
            const float* Pr = sS + r * ALS + qd * 16;
#pragma unroll
            for (int j = 0; j < 16; j++) accO[j] += Pr[j];
        }
    }

    // ---- epilogue: normalize, write bf16 hi/lo output ----
    {
        float inv = 1.0f / rl;
        size_t g = qbase + (size_t)r * EN + qd * 16;
        __nv_bfloat162* Oh = (__nv_bfloat162*)(oh + g);
        __nv_bfloat162* Ol = (__nv_bfloat162*)(ol + g);
#pragma unroll
        for (int j = 0; j < 16; j += 2) {
            float o0 = accO[j] * inv, o1 = accO[j + 1] * inv;
            __nv_bfloat16 h0 = __float2bfloat16_rn(o0);
            __nv_bfloat16 h1 = __float2bfloat16_rn(o1);
            __nv_bfloat16 l0 = __float2bfloat16_rn(o0 - __bfloat162float(h0));
            __nv_bfloat16 l1 = __float2bfloat16_rn(o1 - __bfloat162float(h1));
            Oh[j >> 1] = __nv_bfloat162(h0, h1);
            Ol[j >> 1] = __nv_bfloat162(l0, l1);
        }
    }
}

// ---------------------------------------------------------------------------
// kernel_launch
// ---------------------------------------------------------------------------
extern "C" void kernel_launch(void* const* d_in, const int* in_sizes, int n_in,
                              void* d_out, int out_size)
{
    (void)in_sizes; (void)n_in; (void)out_size;

    const float* query = (const float*)d_in[0];
    const float* key   = (const float*)d_in[1];
    const float* value = (const float*)d_in[2];
    // d_in[3] = attn_mask (int32 tril) -- causal, handled analytically
    const float* Wq = (const float*)d_in[4];
    const float* bq = (const float*)d_in[5];
    const float* Wk = (const float*)d_in[6];
    const float* bk = (const float*)d_in[7];
    const float* Wv = (const float*)d_in[8];
    const float* bv = (const float*)d_in[9];
    const float* Wp = (const float*)d_in[10];
    const float* bp = (const float*)d_in[11];
    float* out = (float*)d_out;

    void* sp = nullptr;
    cudaGetSymbolAddress(&sp, g_scratch);
    float* base = (float*)sp;
    float* gQ = base;                 // fp32 proj outputs
    float* gK = base + 4ull * FM;
    float* gV = base + 8ull * FM;
    // bf16 split region (reused: input splits, then QKV splits)
    __nv_bfloat16* qh = (__nv_bfloat16*)(base + 12ull * FM);
    __nv_bfloat16* ql = (__nv_bfloat16*)(base + 14ull * FM);
    __nv_bfloat16* kh = (__nv_bfloat16*)(base + 16ull * FM);
    __nv_bfloat16* kl = (__nv_bfloat16*)(base + 18ull * FM);
    __nv_bfloat16* vh = (__nv_bfloat16*)(base + 20ull * FM);
    __nv_bfloat16* vl = (__nv_bfloat16*)(base + 22ull * FM);
    __nv_bfloat16* ohi = (__nv_bfloat16*)(base + 24ull * FM);
    __nv_bfloat16* olo = (__nv_bfloat16*)(base + 26ull * FM);
    __nv_bfloat16* wb  = (__nv_bfloat16*)(base + 28ull * FM);
    __nv_bfloat16* wqh = wb;            __nv_bfloat16* wql = wb + 262144;
    __nv_bfloat16* wkh = wb + 524288;   __nv_bfloat16* wkl = wb + 786432;
    __nv_bfloat16* wvh = wb + 1048576;  __nv_bfloat16* wvl = wb + 1310720;
    __nv_bfloat16* wph = wb + 1572864;  __nv_bfloat16* wpl = wb + 1835008;

    cudaFuncSetAttribute(gemm_wmma_kernel,
                         cudaFuncAttributeMaxDynamicSharedMemorySize, GEMM_SM);
    cudaFuncSetAttribute(attention_wmma_kernel,
                         cudaFuncAttributeMaxDynamicSharedMemorySize, ATT_SM);

    const int NB = NSE / 4;       // float4s per big tensor
    const int WB = EN * EN / 4;   // float4s per weight

    // phase 0: split inputs (into the reusable split region) and weights
    split_kernel<<<NB / 256, 256>>>(query, qh, ql, NB);
    split_kernel<<<NB / 256, 256>>>(key,   kh, kl, NB);
    split_kernel<<<NB / 256, 256>>>(value, vh, vl, NB);
    split_kernel<<<WB / 256, 256>>>(Wq, wqh, wql, WB);
    split_kernel<<<WB / 256, 256>>>(Wk, wkh, wkl, WB);
    split_kernel<<<WB / 256, 256>>>(Wv, wvh, wvl, WB);
    split_kernel<<<WB / 256, 256>>>(Wp, wph, wpl, WB);

    // phase 1: projections (Q pre-scaled by 1/sqrt(HD) = 0.125)
    dim3 gg(EN / 128, MTOT / 128);   // (4, 64)
    gemm_wmma_kernel<<<gg, 256, GEMM_SM>>>(qh, ql, wqh, wql, bq, gQ, 0.125f);
    gemm_wmma_kernel<<<gg, 256, GEMM_SM>>>(kh, kl, wkh, wkl, bk, gK, 1.0f);
    gemm_wmma_kernel<<<gg, 256, GEMM_SM>>>(vh, vl, wvh, wvl, bv, gV, 1.0f);

    // phase 2: split projected Q/K/V (overwrites dead input splits)
    split_kernel<<<NB / 256, 256>>>(gQ, qh, ql, NB);
    split_kernel<<<NB / 256, 256>>>(gK, kh, kl, NB);
    split_kernel<<<NB / 256, 256>>>(gV, vh, vl, NB);

    // phase 3: tensor-core flash attention -> bf16 hi/lo O
    attention_wmma_kernel<<<dim3(SEQ / 64, NBAT * NHEAD), 256, ATT_SM>>>(
        qh, ql, kh, kl, vh, vl, ohi, olo);

    // phase 4: output projection
    gemm_wmma_kernel<<<gg, 256, GEMM_SM>>>(ohi, olo, wph, wpl, bp, out, 1.0f);
}

// round 13
// speedup vs baseline: 2.2067x; 1.3512x over previous
#include <cuda_runtime.h>
#include <cuda_bf16.h>
#include <cuda_fp16.h>
#include <mma.h>
#include <cstdint>

using namespace nvcuda;

// Problem constants
#define EN    512
#define SEQ   2048
#define NBAT  4
#define NHEAD 8
#define HDIM  64
#define MTOT  (NBAT * SEQ)          // 8192
#define NSE   (NBAT * SEQ * EN)     // 4,194,304 floats per buffer
#define FM    (1024 * 1024)

// 132 MB scratch
__device__ float g_scratch[33ull * FM];

// ---------------------------------------------------------------------------
// Convert fp32 -> fp16 (single)
// ---------------------------------------------------------------------------
__global__ void cvt_fp16_kernel(const float* __restrict__ x,
                                __half* __restrict__ y, int n4)
{
    int i = blockIdx.x * blockDim.x + threadIdx.x;
    if (i >= n4) return;
    float4 v = ((const float4*)x)[i];
    __half2* yp = (__half2*)y;
    yp[2 * i]     = __floats2half2_rn(v.x, v.y);
    yp[2 * i + 1] = __floats2half2_rn(v.z, v.w);
}

// ---------------------------------------------------------------------------
// Split fp32 -> bf16 (hi, lo):  x = hi + lo + O(2^-17 x)
// ---------------------------------------------------------------------------
__global__ void split_kernel(const float* __restrict__ x,
                             __nv_bfloat16* __restrict__ hi,
                             __nv_bfloat16* __restrict__ lo, int n4)
{
    int i = blockIdx.x * blockDim.x + threadIdx.x;
    if (i >= n4) return;
    float4 v = ((const float4*)x)[i];
    __nv_bfloat16 h0 = __float2bfloat16_rn(v.x);
    __nv_bfloat16 h1 = __float2bfloat16_rn(v.y);
    __nv_bfloat16 h2 = __float2bfloat16_rn(v.z);
    __nv_bfloat16 h3 = __float2bfloat16_rn(v.w);
    __nv_bfloat16 l0 = __float2bfloat16_rn(v.x - __bfloat162float(h0));
    __nv_bfloat16 l1 = __float2bfloat16_rn(v.y - __bfloat162float(h1));
    __nv_bfloat16 l2 = __float2bfloat16_rn(v.z - __bfloat162float(h2));
    __nv_bfloat16 l3 = __float2bfloat16_rn(v.w - __bfloat162float(h3));
    __nv_bfloat162* hp = (__nv_bfloat162*)hi;
    __nv_bfloat162* lp = (__nv_bfloat162*)lo;
    hp[2 * i]     = __nv_bfloat162(h0, h1);
    hp[2 * i + 1] = __nv_bfloat162(h2, h3);
    lp[2 * i]     = __nv_bfloat162(l0, l1);
    lp[2 * i + 1] = __nv_bfloat162(l2, l3);
}

// ---------------------------------------------------------------------------
// fp16 single-term WMMA GEMM: C = (A W^T + bias) * scale
// CTA tile 128x128, BK=32, 8 warps, warp tile 32x64 (structure identical to
// the verified R11/R12 GEMM, minus the lo-term operands).
// grid: (EN/128 = 4, M/128).
// ---------------------------------------------------------------------------
#define LDT 40   // smem row stride (halfs): 80 B -> conflict-free ldmatrix
#define GEMM16_SM (2 * 128 * LDT * 2 + 16 * 128 * 4)   // 20480 + 8192 = 28672

__global__ __launch_bounds__(256)
void gemm_fp16_kernel(const __half* __restrict__ Af,
                      const __half* __restrict__ Wf,
                      const float* __restrict__ bias,
                      float* __restrict__ C, float scale)
{
    extern __shared__ char smraw[];
    __half* sA = (__half*)smraw;            // [128][LDT]
    __half* sW = sA + 128 * LDT;
    float* sBias = (float*)(sW + 128 * LDT);  // [16][128] replicated

    const int t   = threadIdx.x;
    const int wid = t >> 5;
    const int n0  = blockIdx.x << 7;
    const int m0  = blockIdx.y << 7;
    const int wm  = wid >> 1;        // rows wm*32
    const int wn  = wid & 1;         // cols wn*64

    for (int i = t; i < 16 * 128; i += 256) sBias[i] = bias[n0 + (i & 127)];

    // loader: idx = t + j*256; row = idx>>2 (0..127 over j), c = (idx&3)*8 halfs
    const int lr0 = t >> 2, lc = (t & 3) << 3;

    wmma::fragment<wmma::accumulator, 16, 16, 16, float> acc[2][4];
#pragma unroll
    for (int i = 0; i < 2; i++)
#pragma unroll
        for (int j = 0; j < 4; j++) wmma::fill_fragment(acc[i][j], 0.0f);

    uint4 pA[2], pW[2];
#pragma unroll
    for (int j = 0; j < 2; j++) {
        int row = lr0 + j * 64;
        pA[j] = *(const uint4*)(Af + (size_t)(m0 + row) * EN + lc);
        pW[j] = *(const uint4*)(Wf + (size_t)(n0 + row) * EN + lc);
    }

    for (int kt = 0; kt < EN; kt += 32) {
#pragma unroll
        for (int j = 0; j < 2; j++) {
            int row = lr0 + j * 64;
            *(uint4*)(sA + row * LDT + lc) = pA[j];
            *(uint4*)(sW + row * LDT + lc) = pW[j];
        }
        __syncthreads();

        if (kt + 32 < EN) {
#pragma unroll
            for (int j = 0; j < 2; j++) {
                int row = lr0 + j * 64;
                pA[j] = *(const uint4*)(Af + (size_t)(m0 + row) * EN + kt + 32 + lc);
                pW[j] = *(const uint4*)(Wf + (size_t)(n0 + row) * EN + kt + 32 + lc);
            }
        }

#pragma unroll
        for (int kk = 0; kk < 32; kk += 16) {
            wmma::fragment<wmma::matrix_a, 16, 16, 16, __half,
                           wmma::row_major> ah[2];
            wmma::fragment<wmma::matrix_b, 16, 16, 16, __half,
                           wmma::col_major> bh[4];
#pragma unroll
            for (int i = 0; i < 2; i++)
                wmma::load_matrix_sync(ah[i], sA + (wm * 32 + i * 16) * LDT + kk, LDT);
#pragma unroll
            for (int j = 0; j < 4; j++)
                wmma::load_matrix_sync(bh[j], sW + (wn * 64 + j * 16) * LDT + kk, LDT);
#pragma unroll
            for (int i = 0; i < 2; i++)
#pragma unroll
                for (int j = 0; j < 4; j++)
                    wmma::mma_sync(acc[i][j], ah[i], bh[j], acc[i][j]);
        }
        __syncthreads();
    }

    wmma::fragment<wmma::accumulator, 16, 16, 16, float> bf;
#pragma unroll
    for (int j = 0; j < 4; j++) {
        int c = wn * 64 + j * 16;
        wmma::load_matrix_sync(bf, sBias + c, 128, wmma::mem_row_major);
#pragma unroll
        for (int i = 0; i < 2; i++) {
            int r = wm * 32 + i * 16;
#pragma unroll
            for (int e = 0; e < bf.num_elements; e++)
                acc[i][j].x[e] = (acc[i][j].x[e] + bf.x[e]) * scale;
            wmma::store_matrix_sync(C + (size_t)(m0 + r) * EN + n0 + c,
                                    acc[i][j], EN, wmma::mem_row_major);
        }
    }
}

// ---------------------------------------------------------------------------
// WMMA flash attention, causal (verified R12; epilogue now writes fp16 O).
// Br = Bc = 64, HD = 64, 256 threads (8 warps), 2 CTAs/SM.
// S = QK^T and O += PV via 3-term bf16 hi/lo WMMA, fp32 accumulation;
// online softmax in scalar registers (4 threads per row).
// ---------------------------------------------------------------------------
#define ALA 72    // bf16 tile row stride (elems)
#define ALS 68    // fp32 S/PV row stride (elems)
#define ATT_TILE_B (64 * ALA * 2)          // 9216 bytes per bf16 tile
#define AOF_QH 0
#define AOF_QL (ATT_TILE_B)
#define AOF_KH (2 * ATT_TILE_B)
#define AOF_KL (3 * ATT_TILE_B)
#define AOF_VH (4 * ATT_TILE_B)
#define AOF_VL (5 * ATT_TILE_B)
#define AOF_PH (6 * ATT_TILE_B)
#define AOF_PL (7 * ATT_TILE_B)
#define AOF_S  (8 * ATT_TILE_B)            // 73728
#define ATT_SM (AOF_S + 64 * ALS * 4)      // 91136

__global__ __launch_bounds__(256, 2)
void attention_wmma_kernel(const __nv_bfloat16* __restrict__ qh,
                           const __nv_bfloat16* __restrict__ ql,
                           const __nv_bfloat16* __restrict__ kh,
                           const __nv_bfloat16* __restrict__ kl,
                           const __nv_bfloat16* __restrict__ vh,
                           const __nv_bfloat16* __restrict__ vl,
                           __half* __restrict__ ofp)
{
    extern __shared__ char smraw[];
    __nv_bfloat16* sQh = (__nv_bfloat16*)(smraw + AOF_QH);
    __nv_bfloat16* sQl = (__nv_bfloat16*)(smraw + AOF_QL);
    __nv_bfloat16* sKh = (__nv_bfloat16*)(smraw + AOF_KH);
    __nv_bfloat16* sKl = (__nv_bfloat16*)(smraw + AOF_KL);
    __nv_bfloat16* sVh = (__nv_bfloat16*)(smraw + AOF_VH);
    __nv_bfloat16* sVl = (__nv_bfloat16*)(smraw + AOF_VL);
    __nv_bfloat16* sPh = (__nv_bfloat16*)(smraw + AOF_PH);
    __nv_bfloat16* sPl = (__nv_bfloat16*)(smraw + AOF_PL);
    float*         sS  = (float*)(smraw + AOF_S);

    const int t    = threadIdx.x;
    const int w    = t >> 5;
    const int mw   = w >> 1;          // frag row group -> rows mw*16
    const int cb   = (w & 1) << 5;    // frag col base (0 or 32)
    const int sb = (int)gridDim.x - 1 - (int)blockIdx.x;
    const int s0 = sb << 6;
    const int nh = blockIdx.y;
    const int n  = nh >> 3, h = nh & 7;

    const int r  = t >> 2;
    const int qd = t & 3;

    const size_t qbase = (size_t)(n * SEQ + s0) * EN + h * HDIM;
    const size_t kvb0  = (size_t)(n * SEQ) * EN + h * HDIM;

    const int lr = t >> 3, lc = (t & 7) << 3;

#pragma unroll
    for (int j = 0; j < 2; j++) {
        int row = lr + j * 32;
        size_t g = qbase + (size_t)row * EN + lc;
        *(uint4*)(sQh + row * ALA + lc) = *(const uint4*)(qh + g);
        *(uint4*)(sQl + row * ALA + lc) = *(const uint4*)(ql + g);
    }

    float accO[16];
    float rm = -1e30f, rl = 0.0f;
#pragma unroll
    for (int j = 0; j < 16; j++) accO[j] = 0.0f;

    for (int kb = 0; kb <= sb; kb++) {
        __syncthreads();

        size_t kvb = kvb0 + (size_t)(kb << 6) * EN;
#pragma unroll
        for (int j = 0; j < 2; j++) {
            int row = lr + j * 32;
            size_t g = kvb + (size_t)row * EN + lc;
            *(uint4*)(sKh + row * ALA + lc) = *(const uint4*)(kh + g);
            *(uint4*)(sKl + row * ALA + lc) = *(const uint4*)(kl + g);
            *(uint4*)(sVh + row * ALA + lc) = *(const uint4*)(vh + g);
            *(uint4*)(sVl + row * ALA + lc) = *(const uint4*)(vl + g);
        }
        __syncthreads();

        // ---- S = Q K^T : 3-term WMMA ----
        {
            wmma::fragment<wmma::accumulator, 16, 16, 16, float> fc0, fc1;
            wmma::fill_fragment(fc0, 0.0f);
            wmma::fill_fragment(fc1, 0.0f);
#pragma unroll
            for (int ks = 0; ks < 64; ks += 16) {
                wmma::fragment<wmma::matrix_a, 16, 16, 16, __nv_bfloat16,
                               wmma::row_major> fa, fal;
                wmma::fragment<wmma::matrix_b, 16, 16, 16, __nv_bfloat16,
                               wmma::col_major> fb0, fb1, fl0, fl1;
                wmma::load_matrix_sync(fa,  sQh + mw * 16 * ALA + ks, ALA);
                wmma::load_matrix_sync(fal, sQl + mw * 16 * ALA + ks, ALA);
                wmma::load_matrix_sync(fb0, sKh + cb * ALA + ks, ALA);
                wmma::load_matrix_sync(fb1, sKh + (cb + 16) * ALA + ks, ALA);
                wmma::load_matrix_sync(fl0, sKl + cb * ALA + ks, ALA);
                wmma::load_matrix_sync(fl1, sKl + (cb + 16) * ALA + ks, ALA);
                wmma::mma_sync(fc0, fa,  fb0, fc0);
                wmma::mma_sync(fc0, fa,  fl0, fc0);
                wmma::mma_sync(fc0, fal, fb0, fc0);
                wmma::mma_sync(fc1, fa,  fb1, fc1);
                wmma::mma_sync(fc1, fa,  fl1, fc1);
                wmma::mma_sync(fc1, fal, fb1, fc1);
            }
            wmma::store_matrix_sync(sS + mw * 16 * ALS + cb, fc0, ALS,
                                    wmma::mem_row_major);
            wmma::store_matrix_sync(sS + mw * 16 * ALS + cb + 16, fc1, ALS,
                                    wmma::mem_row_major);
        }
        __syncthreads();

        // ---- online softmax (scalar; 4 threads per row) ----
        {
            float s[16];
            const float* Sr = sS + r * ALS + qd * 16;
#pragma unroll
            for (int j = 0; j < 16; j++) s[j] = Sr[j];
            if (kb == sb) {
#pragma unroll
                for (int j = 0; j < 16; j++)
                    if (qd * 16 + j > r) s[j] = -1e30f;
            }
            float mx = -1e30f;
#pragma unroll
            for (int j = 0; j < 16; j++) mx = fmaxf(mx, s[j]);
            mx = fmaxf(mx, __shfl_xor_sync(0xffffffffu, mx, 1));
            mx = fmaxf(mx, __shfl_xor_sync(0xffffffffu, mx, 2));
            float nm    = fmaxf(rm, mx);
            float alpha = __expf(rm - nm);
            float ps = 0.0f;
            __nv_bfloat162* Ph = (__nv_bfloat162*)(sPh + r * ALA + qd * 16);
            __nv_bfloat162* Pl = (__nv_bfloat162*)(sPl + r * ALA + qd * 16);
#pragma unroll
            for (int j = 0; j < 16; j += 2) {
                float e0 = __expf(s[j]     - nm);
                float e1 = __expf(s[j + 1] - nm);
                ps += e0 + e1;
                __nv_bfloat16 h0 = __float2bfloat16_rn(e0);
                __nv_bfloat16 h1 = __float2bfloat16_rn(e1);
                __nv_bfloat16 l0 = __float2bfloat16_rn(e0 - __bfloat162float(h0));
                __nv_bfloat16 l1 = __float2bfloat16_rn(e1 - __bfloat162float(h1));
                Ph[j >> 1] = __nv_bfloat162(h0, h1);
                Pl[j >> 1] = __nv_bfloat162(l0, l1);
            }
            ps += __shfl_xor_sync(0xffffffffu, ps, 1);
            ps += __shfl_xor_sync(0xffffffffu, ps, 2);
            rl = rl * alpha + ps;
            rm = nm;
#pragma unroll
            for (int j = 0; j < 16; j++) accO[j] *= alpha;
        }
        __syncthreads();

        // ---- PV = P V : 3-term WMMA ----
        {
            wmma::fragment<wmma::accumulator, 16, 16, 16, float> fc0, fc1;
            wmma::fill_fragment(fc0, 0.0f);
            wmma::fill_fragment(fc1, 0.0f);
#pragma unroll
            for (int ks = 0; ks < 64; ks += 16) {
                wmma::fragment<wmma::matrix_a, 16, 16, 16, __nv_bfloat16,
                               wmma::row_major> fa, fal;
                wmma::fragment<wmma::matrix_b, 16, 16, 16, __nv_bfloat16,
                               wmma::row_major> fb0, fb1, fl0, fl1;
                wmma::load_matrix_sync(fa,  sPh + mw * 16 * ALA + ks, ALA);
                wmma::load_matrix_sync(fal, sPl + mw * 16 * ALA + ks, ALA);
                wmma::load_matrix_sync(fb0, sVh + ks * ALA + cb, ALA);
                wmma::load_matrix_sync(fb1, sVh + ks * ALA + cb + 16, ALA);
                wmma::load_matrix_sync(fl0, sVl + ks * ALA + cb, ALA);
                wmma::load_matrix_sync(fl1, sVl + ks * ALA + cb + 16, ALA);
                wmma::mma_sync(fc0, fa,  fb0, fc0);
                wmma::mma_sync(fc0, fa,  fl0, fc0);
                wmma::mma_sync(fc0, fal, fb0, fc0);
                wmma::mma_sync(fc1, fa,  fb1, fc1);
                wmma::mma_sync(fc1, fa,  fl1, fc1);
                wmma::mma_sync(fc1, fal, fb1, fc1);
            }
            wmma::store_matrix_sync(sS + mw * 16 * ALS + cb, fc0, ALS,
                                    wmma::mem_row_major);
            wmma::store_matrix_sync(sS + mw * 16 * ALS + cb + 16, fc1, ALS,
                                    wmma::mem_row_major);
        }
        __syncthreads();

        // ---- merge: O += PV ----
        {
            const float* Pr = sS + r * ALS + qd * 16;
#pragma unroll
            for (int j = 0; j < 16; j++) accO[j] += Pr[j];
        }
    }

    // ---- epilogue: normalize, write fp16 output ----
    {
        float inv = 1.0f / rl;
        size_t g = qbase + (size_t)r * EN + qd * 16;
        __half2* Op = (__half2*)(ofp + g);
#pragma unroll
        for (int j = 0; j < 16; j += 2)
            Op[j >> 1] = __floats2half2_rn(accO[j] * inv, accO[j + 1] * inv);
    }
}

// ---------------------------------------------------------------------------
// kernel_launch
// ---------------------------------------------------------------------------
extern "C" void kernel_launch(void* const* d_in, const int* in_sizes, int n_in,
                              void* d_out, int out_size)
{
    (void)in_sizes; (void)n_in; (void)out_size;

    const float* query = (const float*)d_in[0];
    const float* key   = (const float*)d_in[1];
    const float* value = (const float*)d_in[2];
    // d_in[3] = attn_mask (int32 tril) -- causal, handled analytically
    const float* Wq = (const float*)d_in[4];
    const float* bq = (const float*)d_in[5];
    const float* Wk = (const float*)d_in[6];
    const float* bk = (const float*)d_in[7];
    const float* Wv = (const float*)d_in[8];
    const float* bv = (const float*)d_in[9];
    const float* Wp = (const float*)d_in[10];
    const float* bp = (const float*)d_in[11];
    float* out = (float*)d_out;

    void* sp = nullptr;
    cudaGetSymbolAddress(&sp, g_scratch);
    float* base = (float*)sp;
    float* gQ = base;                 // fp32 proj outputs
    float* gK = base + 4ull * FM;
    float* gV = base + 8ull * FM;
    __nv_bfloat16* qh = (__nv_bfloat16*)(base + 12ull * FM);
    __nv_bfloat16* ql = (__nv_bfloat16*)(base + 14ull * FM);
    __nv_bfloat16* kh = (__nv_bfloat16*)(base + 16ull * FM);
    __nv_bfloat16* kl = (__nv_bfloat16*)(base + 18ull * FM);
    __nv_bfloat16* vh = (__nv_bfloat16*)(base + 20ull * FM);
    __nv_bfloat16* vl = (__nv_bfloat16*)(base + 22ull * FM);
    __half* qf  = (__half*)(base + 24ull * FM);
    __half* kf  = (__half*)(base + 26ull * FM);
    __half* vf  = (__half*)(base + 28ull * FM);
    __half* ofp = (__half*)(base + 30ull * FM);
    __half* wf  = (__half*)(base + 32ull * FM);
    __half* wqf = wf;
    __half* wkf = wf + 262144;
    __half* wvf = wf + 524288;
    __half* wpf = wf + 786432;

    cudaFuncSetAttribute(gemm_fp16_kernel,
                         cudaFuncAttributeMaxDynamicSharedMemorySize, GEMM16_SM);
    cudaFuncSetAttribute(attention_wmma_kernel,
                         cudaFuncAttributeMaxDynamicSharedMemorySize, ATT_SM);

    const int NB = NSE / 4;       // float4s per big tensor
    const int WB = EN * EN / 4;   // float4s per weight

    // phase 0: convert inputs + weights to fp16
    cvt_fp16_kernel<<<NB / 256, 256>>>(query, qf, NB);
    cvt_fp16_kernel<<<NB / 256, 256>>>(key,   kf, NB);
    cvt_fp16_kernel<<<NB / 256, 256>>>(value, vf, NB);
    cvt_fp16_kernel<<<WB / 256, 256>>>(Wq, wqf, WB);
    cvt_fp16_kernel<<<WB / 256, 256>>>(Wk, wkf, WB);
    cvt_fp16_kernel<<<WB / 256, 256>>>(Wv, wvf, WB);
    cvt_fp16_kernel<<<WB / 256, 256>>>(Wp, wpf, WB);

    // phase 1: projections (Q pre-scaled by 1/sqrt(HD) = 0.125)
    dim3 gg(EN / 128, MTOT / 128);   // (4, 64)
    gemm_fp16_kernel<<<gg, 256, GEMM16_SM>>>(qf, wqf, bq, gQ, 0.125f);
    gemm_fp16_kernel<<<gg, 256, GEMM16_SM>>>(kf, wkf, bk, gK, 1.0f);
    gemm_fp16_kernel<<<gg, 256, GEMM16_SM>>>(vf, wvf, bv, gV, 1.0f);

    // phase 2: split projected Q/K/V to bf16 hi/lo for the attention core
    split_kernel<<<NB / 256, 256>>>(gQ, qh, ql, NB);
    split_kernel<<<NB / 256, 256>>>(gK, kh, kl, NB);
    split_kernel<<<NB / 256, 256>>>(gV, vh, vl, NB);

    // phase 3: tensor-core flash attention -> fp16 O
    attention_wmma_kernel<<<dim3(SEQ / 64, NBAT * NHEAD), 256, ATT_SM>>>(
        qh, ql, kh, kl, vh, vl, ofp);

    // phase 4: output projection (fp16 single-term)
    gemm_fp16_kernel<<<gg, 256, GEMM16_SM>>>(ofp, wpf, bp, out, 1.0f);
}

// round 14
// speedup vs baseline: 3.1772x; 1.4398x over previous
#include <cuda_runtime.h>
#include <cuda_bf16.h>
#include <cuda_fp16.h>
#include <mma.h>
#include <cstdint>

using namespace nvcuda;

// Problem constants
#define EN    512
#define SEQ   2048
#define NBAT  4
#define NHEAD 8
#define HDIM  64
#define MTOT  (NBAT * SEQ)          // 8192
#define NSE   (NBAT * SEQ * EN)     // 4,194,304 floats per buffer
#define FM    (1024 * 1024)

// 132 MB scratch
__device__ float g_scratch[33ull * FM];

// ---------------------------------------------------------------------------
// Convert fp32 -> fp16
// ---------------------------------------------------------------------------
__global__ void cvt_fp16_kernel(const float* __restrict__ x,
                                __half* __restrict__ y, int n4)
{
    int i = blockIdx.x * blockDim.x + threadIdx.x;
    if (i >= n4) return;
    float4 v = ((const float4*)x)[i];
    __half2* yp = (__half2*)y;
    yp[2 * i]     = __floats2half2_rn(v.x, v.y);
    yp[2 * i + 1] = __floats2half2_rn(v.z, v.w);
}

// ---------------------------------------------------------------------------
// Split fp32 -> bf16 (hi, lo):  x = hi + lo + O(2^-17 x)
// ---------------------------------------------------------------------------
__global__ void split_kernel(const float* __restrict__ x,
                             __nv_bfloat16* __restrict__ hi,
                             __nv_bfloat16* __restrict__ lo, int n4)
{
    int i = blockIdx.x * blockDim.x + threadIdx.x;
    if (i >= n4) return;
    float4 v = ((const float4*)x)[i];
    __nv_bfloat16 h0 = __float2bfloat16_rn(v.x);
    __nv_bfloat16 h1 = __float2bfloat16_rn(v.y);
    __nv_bfloat16 h2 = __float2bfloat16_rn(v.z);
    __nv_bfloat16 h3 = __float2bfloat16_rn(v.w);
    __nv_bfloat16 l0 = __float2bfloat16_rn(v.x - __bfloat162float(h0));
    __nv_bfloat16 l1 = __float2bfloat16_rn(v.y - __bfloat162float(h1));
    __nv_bfloat16 l2 = __float2bfloat16_rn(v.z - __bfloat162float(h2));
    __nv_bfloat16 l3 = __float2bfloat16_rn(v.w - __bfloat162float(h3));
    __nv_bfloat162* hp = (__nv_bfloat162*)hi;
    __nv_bfloat162* lp = (__nv_bfloat162*)lo;
    hp[2 * i]     = __nv_bfloat162(h0, h1);
    hp[2 * i + 1] = __nv_bfloat162(h2, h3);
    lp[2 * i]     = __nv_bfloat162(l0, l1);
    lp[2 * i + 1] = __nv_bfloat162(l2, l3);
}

// ---------------------------------------------------------------------------
// fp16 single-term WMMA GEMM (verified R13): C = (A W^T + bias) * scale
// ---------------------------------------------------------------------------
#define LDT 40
#define GEMM16_SM (2 * 128 * LDT * 2 + 16 * 128 * 4)   // 28672

__global__ __launch_bounds__(256)
void gemm_fp16_kernel(const __half* __restrict__ Af,
                      const __half* __restrict__ Wf,
                      const float* __restrict__ bias,
                      float* __restrict__ C, float scale)
{
    extern __shared__ char smraw[];
    __half* sA = (__half*)smraw;
    __half* sW = sA + 128 * LDT;
    float* sBias = (float*)(sW + 128 * LDT);

    const int t   = threadIdx.x;
    const int wid = t >> 5;
    const int n0  = blockIdx.x << 7;
    const int m0  = blockIdx.y << 7;
    const int wm  = wid >> 1;
    const int wn  = wid & 1;

    for (int i = t; i < 16 * 128; i += 256) sBias[i] = bias[n0 + (i & 127)];

    const int lr0 = t >> 2, lc = (t & 3) << 3;

    wmma::fragment<wmma::accumulator, 16, 16, 16, float> acc[2][4];
#pragma unroll
    for (int i = 0; i < 2; i++)
#pragma unroll
        for (int j = 0; j < 4; j++) wmma::fill_fragment(acc[i][j], 0.0f);

    uint4 pA[2], pW[2];
#pragma unroll
    for (int j = 0; j < 2; j++) {
        int row = lr0 + j * 64;
        pA[j] = *(const uint4*)(Af + (size_t)(m0 + row) * EN + lc);
        pW[j] = *(const uint4*)(Wf + (size_t)(n0 + row) * EN + lc);
    }

    for (int kt = 0; kt < EN; kt += 32) {
#pragma unroll
        for (int j = 0; j < 2; j++) {
            int row = lr0 + j * 64;
            *(uint4*)(sA + row * LDT + lc) = pA[j];
            *(uint4*)(sW + row * LDT + lc) = pW[j];
        }
        __syncthreads();

        if (kt + 32 < EN) {
#pragma unroll
            for (int j = 0; j < 2; j++) {
                int row = lr0 + j * 64;
                pA[j] = *(const uint4*)(Af + (size_t)(m0 + row) * EN + kt + 32 + lc);
                pW[j] = *(const uint4*)(Wf + (size_t)(n0 + row) * EN + kt + 32 + lc);
            }
        }

#pragma unroll
        for (int kk = 0; kk < 32; kk += 16) {
            wmma::fragment<wmma::matrix_a, 16, 16, 16, __half,
                           wmma::row_major> ah[2];
            wmma::fragment<wmma::matrix_b, 16, 16, 16, __half,
                           wmma::col_major> bh[4];
#pragma unroll
            for (int i = 0; i < 2; i++)
                wmma::load_matrix_sync(ah[i], sA + (wm * 32 + i * 16) * LDT + kk, LDT);
#pragma unroll
            for (int j = 0; j < 4; j++)
                wmma::load_matrix_sync(bh[j], sW + (wn * 64 + j * 16) * LDT + kk, LDT);
#pragma unroll
            for (int i = 0; i < 2; i++)
#pragma unroll
                for (int j = 0; j < 4; j++)
                    wmma::mma_sync(acc[i][j], ah[i], bh[j], acc[i][j]);
        }
        __syncthreads();
    }

    wmma::fragment<wmma::accumulator, 16, 16, 16, float> bf;
#pragma unroll
    for (int j = 0; j < 4; j++) {
        int c = wn * 64 + j * 16;
        wmma::load_matrix_sync(bf, sBias + c, 128, wmma::mem_row_major);
#pragma unroll
        for (int i = 0; i < 2; i++) {
            int r = wm * 32 + i * 16;
#pragma unroll
            for (int e = 0; e < bf.num_elements; e++)
                acc[i][j].x[e] = (acc[i][j].x[e] + bf.x[e]) * scale;
            wmma::store_matrix_sync(C + (size_t)(m0 + r) * EN + n0 + c,
                                    acc[i][j], EN, wmma::mem_row_major);
        }
    }
}

// ---------------------------------------------------------------------------
// FA2-style flash attention with raw mma.sync.m16n8k16 (bf16 3-term, f32 acc)
// Br = 128, Bc = 64, 256 threads = 8 warps; warp w owns rows 16w..16w+15 and
// ALL 64 columns -> softmax fully warp-local (quad shfl), S/P/O in registers.
// Smem: Q(128x64 hi/lo) + K,V(64x64 hi/lo), stride 72 bf16 (conflict-free
// ldmatrix). 72 KB -> 2 CTAs/SM. 2 syncs per tile.
// ---------------------------------------------------------------------------
#define ALA 72
#define AQ_B (128 * ALA * 2)      // 18432 bytes per Q tile
#define AK_B (64 * ALA * 2)       //  9216 bytes per K/V tile
#define AT_QH 0
#define AT_QL (AQ_B)
#define AT_KH (2 * AQ_B)
#define AT_KL (2 * AQ_B + AK_B)
#define AT_VH (2 * AQ_B + 2 * AK_B)
#define AT_VL (2 * AQ_B + 3 * AK_B)
#define ATT_SM (2 * AQ_B + 4 * AK_B)   // 73728

__device__ __forceinline__ void ldsm4(uint32_t& r0, uint32_t& r1,
                                      uint32_t& r2, uint32_t& r3, uint32_t a)
{
    asm volatile("ldmatrix.sync.aligned.m8n8.x4.shared.b16 {%0,%1,%2,%3}, [%4];"
                 : "=r"(r0), "=r"(r1), "=r"(r2), "=r"(r3) : "r"(a) : "memory");
}
__device__ __forceinline__ void ldsm4t(uint32_t& r0, uint32_t& r1,
                                       uint32_t& r2, uint32_t& r3, uint32_t a)
{
    asm volatile("ldmatrix.sync.aligned.m8n8.x4.trans.shared.b16 {%0,%1,%2,%3}, [%4];"
                 : "=r"(r0), "=r"(r1), "=r"(r2), "=r"(r3) : "r"(a) : "memory");
}
__device__ __forceinline__ void mma16816(float* c, uint32_t a0, uint32_t a1,
                                         uint32_t a2, uint32_t a3,
                                         uint32_t b0, uint32_t b1)
{
    asm volatile(
        "mma.sync.aligned.m16n8k16.row.col.f32.bf16.bf16.f32 "
        "{%0,%1,%2,%3}, {%4,%5,%6,%7}, {%8,%9}, {%0,%1,%2,%3};"
        : "+f"(c[0]), "+f"(c[1]), "+f"(c[2]), "+f"(c[3])
        : "r"(a0), "r"(a1), "r"(a2), "r"(a3), "r"(b0), "r"(b1));
}
__device__ __forceinline__ uint32_t pk2(float x, float y)
{
    __nv_bfloat162 t = __floats2bfloat162_rn(x, y);
    return *reinterpret_cast<uint32_t*>(&t);
}

__global__ __launch_bounds__(256, 2)
void attention_mma_kernel(const __nv_bfloat16* __restrict__ qh,
                          const __nv_bfloat16* __restrict__ ql,
                          const __nv_bfloat16* __restrict__ kh,
                          const __nv_bfloat16* __restrict__ kl,
                          const __nv_bfloat16* __restrict__ vh,
                          const __nv_bfloat16* __restrict__ vl,
                          __half* __restrict__ ofp)
{
    extern __shared__ char smraw[];
    __nv_bfloat16* sQh = (__nv_bfloat16*)(smraw + AT_QH);
    __nv_bfloat16* sQl = (__nv_bfloat16*)(smraw + AT_QL);
    __nv_bfloat16* sKh = (__nv_bfloat16*)(smraw + AT_KH);
    __nv_bfloat16* sKl = (__nv_bfloat16*)(smraw + AT_KL);
    __nv_bfloat16* sVh = (__nv_bfloat16*)(smraw + AT_VH);
    __nv_bfloat16* sVl = (__nv_bfloat16*)(smraw + AT_VL);

    const int t  = threadIdx.x;
    const int w  = t >> 5;
    const int l  = t & 31;
    const int g  = l >> 2;           // fragment row within 8
    const int tq = l & 3;            // fragment col pair index
    const int sb = (int)gridDim.x - 1 - (int)blockIdx.x;   // heavy-first
    const int s0 = sb << 7;
    const int nh = blockIdx.y;
    const int n  = nh >> 3, h = nh & 7;

    const size_t qbase = (size_t)(n * SEQ + s0) * EN + h * HDIM;
    const size_t kvb0  = (size_t)(n * SEQ) * EN + h * HDIM;

    // ---- load Q tile 128x64 hi/lo into smem ----
    {
        const int lrow = t >> 3, lc = (t & 7) << 3;
#pragma unroll
        for (int p = 0; p < 4; p++) {
            int row = lrow + p * 32;
            size_t gidx = qbase + (size_t)row * EN + lc;
            *(uint4*)(sQh + row * ALA + lc) = *(const uint4*)(qh + gidx);
            *(uint4*)(sQl + row * ALA + lc) = *(const uint4*)(ql + gidx);
        }
    }

    // ldmatrix lane address components
    const uint32_t bQh = (uint32_t)__cvta_generic_to_shared(sQh);
    const uint32_t bQl = (uint32_t)__cvta_generic_to_shared(sQl);
    const uint32_t bKh = (uint32_t)__cvta_generic_to_shared(sKh);
    const uint32_t bKl = (uint32_t)__cvta_generic_to_shared(sKl);
    const uint32_t bVh = (uint32_t)__cvta_generic_to_shared(sVh);
    const uint32_t bVl = (uint32_t)__cvta_generic_to_shared(sVl);
    // Q (A-frag): row = 16w + (l&15), col = kk*16 + (l>>4)*8
    const uint32_t qoff = (uint32_t)(((16 * w + (l & 15)) * ALA + ((l >> 4) << 3)) * 2);
    // K (B-frag): nrow = 16ng + (l>>4)*8 + (l&7), col = kk*16 + ((l>>3)&1)*8
    const uint32_t koff = (uint32_t)(((((l >> 4) << 3) + (l & 7)) * ALA
                                     + (((l >> 3) & 1) << 3)) * 2);
    // V (B-frag, trans): krow = 16kk + ((l>>3)&1)*8 + (l&7), col = 16ng + (l>>4)*8
    const uint32_t voff = (uint32_t)(((((( l >> 3) & 1) << 3) + (l & 7)) * ALA
                                     + ((l >> 4) << 3)) * 2);

    float accO[8][4];
#pragma unroll
    for (int j = 0; j < 8; j++)
#pragma unroll
        for (int e = 0; e < 4; e++) accO[j][e] = 0.0f;
    float rm0 = -1e30f, rm1 = -1e30f, rl0 = 0.0f, rl1 = 0.0f;

    const int kbmax = (sb << 1) + 2;
    for (int kb = 0; kb < kbmax; kb++) {
        __syncthreads();   // prior tile's ldmatrix reads complete

        // ---- fill K/V tiles ----
        {
            const int lrow = t >> 3, lc = (t & 7) << 3;
            size_t kvb = kvb0 + (size_t)(kb << 6) * EN;
#pragma unroll
            for (int p = 0; p < 2; p++) {
                int row = lrow + p * 32;
                size_t gidx = kvb + (size_t)row * EN + lc;
                *(uint4*)(sKh + row * ALA + lc) = *(const uint4*)(kh + gidx);
                *(uint4*)(sKl + row * ALA + lc) = *(const uint4*)(kl + gidx);
                *(uint4*)(sVh + row * ALA + lc) = *(const uint4*)(vh + gidx);
                *(uint4*)(sVl + row * ALA + lc) = *(const uint4*)(vl + gidx);
            }
        }
        __syncthreads();

        // ---- S = Q K^T : per warp 16 rows x 64 cols, 3-term ----
        float Sc[8][4];
#pragma unroll
        for (int j = 0; j < 8; j++)
#pragma unroll
            for (int e = 0; e < 4; e++) Sc[j][e] = 0.0f;

#pragma unroll
        for (int kk = 0; kk < 4; kk++) {
            uint32_t qh0, qh1, qh2, qh3, ql0, ql1, ql2, ql3;
            ldsm4(qh0, qh1, qh2, qh3, bQh + qoff + kk * 32);
            ldsm4(ql0, ql1, ql2, ql3, bQl + qoff + kk * 32);
#pragma unroll
            for (int ng = 0; ng < 4; ng++) {
                uint32_t kh0, kh1, kh2, kh3, kl0, kl1, kl2, kl3;
                uint32_t ka = koff + (uint32_t)(ng * 16 * ALA * 2 + kk * 32);
                ldsm4(kh0, kh1, kh2, kh3, bKh + ka);
                ldsm4(kl0, kl1, kl2, kl3, bKl + ka);
                mma16816(Sc[2 * ng],     qh0, qh1, qh2, qh3, kh0, kh1);
                mma16816(Sc[2 * ng],     qh0, qh1, qh2, qh3, kl0, kl1);
                mma16816(Sc[2 * ng],     ql0, ql1, ql2, ql3, kh0, kh1);
                mma16816(Sc[2 * ng + 1], qh0, qh1, qh2, qh3, kh2, kh3);
                mma16816(Sc[2 * ng + 1], qh0, qh1, qh2, qh3, kl2, kl3);
                mma16816(Sc[2 * ng + 1], ql0, ql1, ql2, ql3, kh2, kh3);
            }
        }

        // ---- causal mask on the two diagonal tiles ----
        if (kb >= (sb << 1)) {
            int row0 = s0 + 16 * w + g;
            int c00  = (kb << 6) + 2 * tq;
#pragma unroll
            for (int j = 0; j < 8; j++) {
                int c = c00 + 8 * j;
                if (c > row0)         Sc[j][0] = -1e30f;
                if (c + 1 > row0)     Sc[j][1] = -1e30f;
                if (c > row0 + 8)     Sc[j][2] = -1e30f;
                if (c + 1 > row0 + 8) Sc[j][3] = -1e30f;
            }
        }

        // ---- warp-local online softmax (rows g and g+8) ----
        {
            float mx0 = -1e30f, mx1 = -1e30f;
#pragma unroll
            for (int j = 0; j < 8; j++) {
                mx0 = fmaxf(mx0, fmaxf(Sc[j][0], Sc[j][1]));
                mx1 = fmaxf(mx1, fmaxf(Sc[j][2], Sc[j][3]));
            }
            mx0 = fmaxf(mx0, __shfl_xor_sync(0xffffffffu, mx0, 1));
            mx0 = fmaxf(mx0, __shfl_xor_sync(0xffffffffu, mx0, 2));
            mx1 = fmaxf(mx1, __shfl_xor_sync(0xffffffffu, mx1, 1));
            mx1 = fmaxf(mx1, __shfl_xor_sync(0xffffffffu, mx1, 2));
            float nm0 = fmaxf(rm0, mx0), nm1 = fmaxf(rm1, mx1);
            float a0 = __expf(rm0 - nm0), a1 = __expf(rm1 - nm1);
            float ps0 = 0.0f, ps1 = 0.0f;
#pragma unroll
            for (int j = 0; j < 8; j++) {
                float e0 = __expf(Sc[j][0] - nm0);
                float e1 = __expf(Sc[j][1] - nm0);
                float e2 = __expf(Sc[j][2] - nm1);
                float e3 = __expf(Sc[j][3] - nm1);
                Sc[j][0] = e0; Sc[j][1] = e1; Sc[j][2] = e2; Sc[j][3] = e3;
                ps0 += e0 + e1; ps1 += e2 + e3;
            }
            ps0 += __shfl_xor_sync(0xffffffffu, ps0, 1);
            ps0 += __shfl_xor_sync(0xffffffffu, ps0, 2);
            ps1 += __shfl_xor_sync(0xffffffffu, ps1, 1);
            ps1 += __shfl_xor_sync(0xffffffffu, ps1, 2);
            rl0 = rl0 * a0 + ps0; rl1 = rl1 * a1 + ps1;
            rm0 = nm0; rm1 = nm1;
#pragma unroll
            for (int j = 0; j < 8; j++) {
                accO[j][0] *= a0; accO[j][1] *= a0;
                accO[j][2] *= a1; accO[j][3] *= a1;
            }
        }

        // ---- O += P V : P stays in registers (C-layout == A-layout) ----
#pragma unroll
        for (int kk = 0; kk < 4; kk++) {
            // split P (fp32) -> bf16 hi/lo, pack into A-frags
            float p0 = Sc[2 * kk][0],     p1 = Sc[2 * kk][1];
            float p2 = Sc[2 * kk][2],     p3 = Sc[2 * kk][3];
            float p4 = Sc[2 * kk + 1][0], p5 = Sc[2 * kk + 1][1];
            float p6 = Sc[2 * kk + 1][2], p7 = Sc[2 * kk + 1][3];
            uint32_t ah0 = pk2(p0, p1), ah1 = pk2(p2, p3);
            uint32_t ah2 = pk2(p4, p5), ah3 = pk2(p6, p7);
            __nv_bfloat162 t0 = *(__nv_bfloat162*)&ah0;
            __nv_bfloat162 t1 = *(__nv_bfloat162*)&ah1;
            __nv_bfloat162 t2 = *(__nv_bfloat162*)&ah2;
            __nv_bfloat162 t3 = *(__nv_bfloat162*)&ah3;
            uint32_t al0 = pk2(p0 - __bfloat162float(t0.x), p1 - __bfloat162float(t0.y));
            uint32_t al1 = pk2(p2 - __bfloat162float(t1.x), p3 - __bfloat162float(t1.y));
            uint32_t al2 = pk2(p4 - __bfloat162float(t2.x), p5 - __bfloat162float(t2.y));
            uint32_t al3 = pk2(p6 - __bfloat162float(t3.x), p7 - __bfloat162float(t3.y));
#pragma unroll
            for (int ng = 0; ng < 4; ng++) {
                uint32_t vh0, vh1, vh2, vh3, vl0, vl1, vl2, vl3;
                uint32_t va = voff + (uint32_t)(kk * 16 * ALA * 2 + ng * 32);
                ldsm4t(vh0, vh1, vh2, vh3, bVh + va);
                ldsm4t(vl0, vl1, vl2, vl3, bVl + va);
                mma16816(accO[2 * ng],     ah0, ah1, ah2, ah3, vh0, vh1);
                mma16816(accO[2 * ng],     ah0, ah1, ah2, ah3, vl0, vl1);
                mma16816(accO[2 * ng],     al0, al1, al2, al3, vh0, vh1);
                mma16816(accO[2 * ng + 1], ah0, ah1, ah2, ah3, vh2, vh3);
                mma16816(accO[2 * ng + 1], ah0, ah1, ah2, ah3, vl2, vl3);
                mma16816(accO[2 * ng + 1], al0, al1, al2, al3, vh2, vh3);
            }
        }
    }

    // ---- epilogue: normalize, write fp16 O ----
    {
        float inv0 = 1.0f / rl0, inv1 = 1.0f / rl1;
        size_t base0 = qbase + (size_t)(16 * w + g) * EN + 2 * tq;
        size_t base1 = base0 + 8 * EN;
#pragma unroll
        for (int j = 0; j < 8; j++) {
            *(__half2*)(ofp + base0 + 8 * j) =
                __floats2half2_rn(accO[j][0] * inv0, accO[j][1] * inv0);
            *(__half2*)(ofp + base1 + 8 * j) =
                __floats2half2_rn(accO[j][2] * inv1, accO[j][3] * inv1);
        }
    }
}

// ---------------------------------------------------------------------------
// kernel_launch
// ---------------------------------------------------------------------------
extern "C" void kernel_launch(void* const* d_in, const int* in_sizes, int n_in,
                              void* d_out, int out_size)
{
    (void)in_sizes; (void)n_in; (void)out_size;

    const float* query = (const float*)d_in[0];
    const float* key   = (const float*)d_in[1];
    const float* value = (const float*)d_in[2];
    // d_in[3] = attn_mask (int32 tril) -- causal, handled analytically
    const float* Wq = (const float*)d_in[4];
    const float* bq = (const float*)d_in[5];
    const float* Wk = (const float*)d_in[6];
    const float* bk = (const float*)d_in[7];
    const float* Wv = (const float*)d_in[8];
    const float* bv = (const float*)d_in[9];
    const float* Wp = (const float*)d_in[10];
    const float* bp = (const float*)d_in[11];
    float* out = (float*)d_out;

    void* sp = nullptr;
    cudaGetSymbolAddress(&sp, g_scratch);
    float* base = (float*)sp;
    float* gQ = base;                 // fp32 proj outputs
    float* gK = base + 4ull * FM;
    float* gV = base + 8ull * FM;
    __nv_bfloat16* qh = (__nv_bfloat16*)(base + 12ull * FM);
    __nv_bfloat16* ql = (__nv_bfloat16*)(base + 14ull * FM);
    __nv_bfloat16* kh = (__nv_bfloat16*)(base + 16ull * FM);
    __nv_bfloat16* kl = (__nv_bfloat16*)(base + 18ull * FM);
    __nv_bfloat16* vh = (__nv_bfloat16*)(base + 20ull * FM);
    __nv_bfloat16* vl = (__nv_bfloat16*)(base + 22ull * FM);
    __half* qf  = (__half*)(base + 24ull * FM);
    __half* kf  = (__half*)(base + 26ull * FM);
    __half* vf  = (__half*)(base + 28ull * FM);
    __half* ofp = (__half*)(base + 30ull * FM);
    __half* wf  = (__half*)(base + 32ull * FM);
    __half* wqf = wf;
    __half* wkf = wf + 262144;
    __half* wvf = wf + 524288;
    __half* wpf = wf + 786432;

    cudaFuncSetAttribute(gemm_fp16_kernel,
                         cudaFuncAttributeMaxDynamicSharedMemorySize, GEMM16_SM);
    cudaFuncSetAttribute(attention_mma_kernel,
                         cudaFuncAttributeMaxDynamicSharedMemorySize, ATT_SM);

    const int NB = NSE / 4;
    const int WB = EN * EN / 4;

    // phase 0: convert inputs + weights to fp16
    cvt_fp16_kernel<<<NB / 256, 256>>>(query, qf, NB);
    cvt_fp16_kernel<<<NB / 256, 256>>>(key,   kf, NB);
    cvt_fp16_kernel<<<NB / 256, 256>>>(value, vf, NB);
    cvt_fp16_kernel<<<WB / 256, 256>>>(Wq, wqf, WB);
    cvt_fp16_kernel<<<WB / 256, 256>>>(Wk, wkf, WB);
    cvt_fp16_kernel<<<WB / 256, 256>>>(Wv, wvf, WB);
    cvt_fp16_kernel<<<WB / 256, 256>>>(Wp, wpf, WB);

    // phase 1: projections (Q pre-scaled by 1/sqrt(HD) = 0.125)
    dim3 gg(EN / 128, MTOT / 128);
    gemm_fp16_kernel<<<gg, 256, GEMM16_SM>>>(qf, wqf, bq, gQ, 0.125f);
    gemm_fp16_kernel<<<gg, 256, GEMM16_SM>>>(kf, wkf, bk, gK, 1.0f);
    gemm_fp16_kernel<<<gg, 256, GEMM16_SM>>>(vf, wvf, bv, gV, 1.0f);

    // phase 2: split projected Q/K/V to bf16 hi/lo
    split_kernel<<<NB / 256, 256>>>(gQ, qh, ql, NB);
    split_kernel<<<NB / 256, 256>>>(gK, kh, kl, NB);
    split_kernel<<<NB / 256, 256>>>(gV, vh, vl, NB);

    // phase 3: FA2-style mma flash attention -> fp16 O
    attention_mma_kernel<<<dim3(SEQ / 128, NBAT * NHEAD), 256, ATT_SM>>>(
        qh, ql, kh, kl, vh, vl, ofp);

    // phase 4: output projection (fp16 single-term)
    gemm_fp16_kernel<<<gg, 256, GEMM16_SM>>>(ofp, wpf, bp, out, 1.0f);
}

// round 15
// speedup vs baseline: 4.3684x; 1.3749x over previous
#include <cuda_runtime.h>
#include <cuda_bf16.h>
#include <cuda_fp16.h>
#include <mma.h>
#include <cstdint>

using namespace nvcuda;

// Problem constants
#define EN    512
#define SEQ   2048
#define NBAT  4
#define NHEAD 8
#define HDIM  64
#define MTOT  (NBAT * SEQ)          // 8192
#define NSE   (NBAT * SEQ * EN)     // 4,194,304 floats per buffer
#define FM    (1024 * 1024)

// 132 MB scratch
__device__ float g_scratch[33ull * FM];

// ---------------------------------------------------------------------------
// Convert fp32 -> fp16
// ---------------------------------------------------------------------------
__global__ void cvt_fp16_kernel(const float* __restrict__ x,
                                __half* __restrict__ y, int n4)
{
    int i = blockIdx.x * blockDim.x + threadIdx.x;
    if (i >= n4) return;
    float4 v = ((const float4*)x)[i];
    __half2* yp = (__half2*)y;
    yp[2 * i]     = __floats2half2_rn(v.x, v.y);
    yp[2 * i + 1] = __floats2half2_rn(v.z, v.w);
}

// ---------------------------------------------------------------------------
// fp16 single-term WMMA GEMM (verified R13/R14): C = (A W^T + bias) * scale
// ---------------------------------------------------------------------------
#define LDT 40
#define GEMM16_SM (2 * 128 * LDT * 2 + 16 * 128 * 4)   // 28672

__global__ __launch_bounds__(256)
void gemm_fp16_kernel(const __half* __restrict__ Af,
                      const __half* __restrict__ Wf,
                      const float* __restrict__ bias,
                      float* __restrict__ C, float scale)
{
    extern __shared__ char smraw[];
    __half* sA = (__half*)smraw;
    __half* sW = sA + 128 * LDT;
    float* sBias = (float*)(sW + 128 * LDT);

    const int t   = threadIdx.x;
    const int wid = t >> 5;
    const int n0  = blockIdx.x << 7;
    const int m0  = blockIdx.y << 7;
    const int wm  = wid >> 1;
    const int wn  = wid & 1;

    for (int i = t; i < 16 * 128; i += 256) sBias[i] = bias[n0 + (i & 127)];

    const int lr0 = t >> 2, lc = (t & 3) << 3;

    wmma::fragment<wmma::accumulator, 16, 16, 16, float> acc[2][4];
#pragma unroll
    for (int i = 0; i < 2; i++)
#pragma unroll
        for (int j = 0; j < 4; j++) wmma::fill_fragment(acc[i][j], 0.0f);

    uint4 pA[2], pW[2];
#pragma unroll
    for (int j = 0; j < 2; j++) {
        int row = lr0 + j * 64;
        pA[j] = *(const uint4*)(Af + (size_t)(m0 + row) * EN + lc);
        pW[j] = *(const uint4*)(Wf + (size_t)(n0 + row) * EN + lc);
    }

    for (int kt = 0; kt < EN; kt += 32) {
#pragma unroll
        for (int j = 0; j < 2; j++) {
            int row = lr0 + j * 64;
            *(uint4*)(sA + row * LDT + lc) = pA[j];
            *(uint4*)(sW + row * LDT + lc) = pW[j];
        }
        __syncthreads();

        if (kt + 32 < EN) {
#pragma unroll
            for (int j = 0; j < 2; j++) {
                int row = lr0 + j * 64;
                pA[j] = *(const uint4*)(Af + (size_t)(m0 + row) * EN + kt + 32 + lc);
                pW[j] = *(const uint4*)(Wf + (size_t)(n0 + row) * EN + kt + 32 + lc);
            }
        }

#pragma unroll
        for (int kk = 0; kk < 32; kk += 16) {
            wmma::fragment<wmma::matrix_a, 16, 16, 16, __half,
                           wmma::row_major> ah[2];
            wmma::fragment<wmma::matrix_b, 16, 16, 16, __half,
                           wmma::col_major> bh[4];
#pragma unroll
            for (int i = 0; i < 2; i++)
                wmma::load_matrix_sync(ah[i], sA + (wm * 32 + i * 16) * LDT + kk, LDT);
#pragma unroll
            for (int j = 0; j < 4; j++)
                wmma::load_matrix_sync(bh[j], sW + (wn * 64 + j * 16) * LDT + kk, LDT);
#pragma unroll
            for (int i = 0; i < 2; i++)
#pragma unroll
                for (int j = 0; j < 4; j++)
                    wmma::mma_sync(acc[i][j], ah[i], bh[j], acc[i][j]);
        }
        __syncthreads();
    }

    wmma::fragment<wmma::accumulator, 16, 16, 16, float> bf;
#pragma unroll
    for (int j = 0; j < 4; j++) {
        int c = wn * 64 + j * 16;
        wmma::load_matrix_sync(bf, sBias + c, 128, wmma::mem_row_major);
#pragma unroll
        for (int i = 0; i < 2; i++) {
            int r = wm * 32 + i * 16;
#pragma unroll
            for (int e = 0; e < bf.num_elements; e++)
                acc[i][j].x[e] = (acc[i][j].x[e] + bf.x[e]) * scale;
            wmma::store_matrix_sync(C + (size_t)(m0 + r) * EN + n0 + c,
                                    acc[i][j], EN, wmma::mem_row_major);
        }
    }
}

// ---------------------------------------------------------------------------
// FA2-style fp16 flash attention (raw mma.sync.m16n8k16.f32.f16.f16.f32).
// Br = 128, Bc = 64, 256 threads = 8 warps; warp w owns rows 16w..16w+15.
// QK^T: single-term fp16.  PV: P split to fp16 hi/lo (2-term), V fp16.
// K/V fills via cp.async, double-buffered (loads overlap previous compute).
// Smem: Q 128x64 + 2x(K,V 64x64) fp16 at stride 72 -> 54 KB, 2 CTAs/SM.
// ---------------------------------------------------------------------------
#define ALA 72
#define AQ_B (128 * ALA * 2)      // 18432
#define AK_B (64 * ALA * 2)       //  9216
#define ATT_SM (AQ_B + 4 * AK_B)  // 55296

__device__ __forceinline__ void ldsm4(uint32_t& r0, uint32_t& r1,
                                      uint32_t& r2, uint32_t& r3, uint32_t a)
{
    asm volatile("ldmatrix.sync.aligned.m8n8.x4.shared.b16 {%0,%1,%2,%3}, [%4];"
                 : "=r"(r0), "=r"(r1), "=r"(r2), "=r"(r3) : "r"(a) : "memory");
}
__device__ __forceinline__ void ldsm4t(uint32_t& r0, uint32_t& r1,
                                       uint32_t& r2, uint32_t& r3, uint32_t a)
{
    asm volatile("ldmatrix.sync.aligned.m8n8.x4.trans.shared.b16 {%0,%1,%2,%3}, [%4];"
                 : "=r"(r0), "=r"(r1), "=r"(r2), "=r"(r3) : "r"(a) : "memory");
}
__device__ __forceinline__ void mma16816h(float* c, uint32_t a0, uint32_t a1,
                                          uint32_t a2, uint32_t a3,
                                          uint32_t b0, uint32_t b1)
{
    asm volatile(
        "mma.sync.aligned.m16n8k16.row.col.f32.f16.f16.f32 "
        "{%0,%1,%2,%3}, {%4,%5,%6,%7}, {%8,%9}, {%0,%1,%2,%3};"
        : "+f"(c[0]), "+f"(c[1]), "+f"(c[2]), "+f"(c[3])
        : "r"(a0), "r"(a1), "r"(a2), "r"(a3), "r"(b0), "r"(b1));
}
__device__ __forceinline__ uint32_t pkh2(float x, float y)
{
    __half2 t = __floats2half2_rn(x, y);
    return *reinterpret_cast<uint32_t*>(&t);
}
__device__ __forceinline__ void cpa16(uint32_t dst, const void* src)
{
    asm volatile("cp.async.cg.shared.global [%0], [%1], 16;"
                 :: "r"(dst), "l"(src) : "memory");
}
#define CPA_COMMIT() asm volatile("cp.async.commit_group;" ::: "memory")
#define CPA_WAIT1()  asm volatile("cp.async.wait_group 1;" ::: "memory")

__global__ __launch_bounds__(256, 2)
void attention_fp16_kernel(const __half* __restrict__ qf,
                           const __half* __restrict__ kf,
                           const __half* __restrict__ vf,
                           __half* __restrict__ ofp)
{
    extern __shared__ char smraw[];
    __half* sQ = (__half*)smraw;                       // 128x64
    // K/V double buffers
    uint32_t sbase = (uint32_t)__cvta_generic_to_shared(smraw);
    const uint32_t bQ  = sbase;
    const uint32_t bK0 = sbase + AQ_B;
    const uint32_t bK1 = sbase + AQ_B + AK_B;
    const uint32_t bV0 = sbase + AQ_B + 2 * AK_B;
    const uint32_t bV1 = sbase + AQ_B + 3 * AK_B;

    const int t  = threadIdx.x;
    const int w  = t >> 5;
    const int l  = t & 31;
    const int g  = l >> 2;
    const int tq = l & 3;
    const int sb = (int)gridDim.x - 1 - (int)blockIdx.x;   // heavy-first
    const int s0 = sb << 7;
    const int nh = blockIdx.y;
    const int n  = nh >> 3, h = nh & 7;

    const size_t qbase = (size_t)(n * SEQ + s0) * EN + h * HDIM;
    const size_t kvb0  = (size_t)(n * SEQ) * EN + h * HDIM;

    // loader mapping: lrow 0..31, lc = 16B chunk (8 halfs)
    const int lrow = t >> 3, lc = (t & 7) << 3;

    // ---- load Q tile 128x64 fp16 (regular loads, once) ----
#pragma unroll
    for (int p = 0; p < 4; p++) {
        int row = lrow + p * 32;
        *(uint4*)(sQ + row * ALA + lc) =
            *(const uint4*)(qf + qbase + (size_t)row * EN + lc);
    }

    // ---- cp.async prologue: K/V tile 0 into buffer 0 ----
    {
        size_t kvb = kvb0;
#pragma unroll
        for (int p = 0; p < 2; p++) {
            int row = lrow + p * 32;
            uint32_t so = (uint32_t)((row * ALA + lc) * 2);
            cpa16(bK0 + so, kf + kvb + (size_t)row * EN + lc);
            cpa16(bV0 + so, vf + kvb + (size_t)row * EN + lc);
        }
    }
    CPA_COMMIT();

    // fragment addresses (byte offsets; fp16 = 2 bytes)
    const uint32_t qoff = (uint32_t)(((16 * w + (l & 15)) * ALA + ((l >> 4) << 3)) * 2);
    const uint32_t koff = (uint32_t)(((((l >> 4) << 3) + (l & 7)) * ALA
                                     + (((l >> 3) & 1) << 3)) * 2);
    const uint32_t voff = (uint32_t)((((((l >> 3) & 1) << 3) + (l & 7)) * ALA
                                     + ((l >> 4) << 3)) * 2);

    float accO[8][4];
#pragma unroll
    for (int j = 0; j < 8; j++)
#pragma unroll
        for (int e = 0; e < 4; e++) accO[j][e] = 0.0f;
    float rm0 = -1e30f, rm1 = -1e30f, rl0 = 0.0f, rl1 = 0.0f;

    const int kbmax = (sb << 1) + 2;
    for (int kb = 0; kb < kbmax; kb++) {
        const uint32_t bK = (kb & 1) ? bK1 : bK0;
        const uint32_t bV = (kb & 1) ? bV1 : bV0;

        // issue next tile's loads into the other buffer (overlaps compute wait)
        if (kb + 1 < kbmax) {
            const uint32_t nK = (kb & 1) ? bK0 : bK1;
            const uint32_t nV = (kb & 1) ? bV0 : bV1;
            size_t kvb = kvb0 + (size_t)((kb + 1) << 6) * EN;
#pragma unroll
            for (int p = 0; p < 2; p++) {
                int row = lrow + p * 32;
                uint32_t so = (uint32_t)((row * ALA + lc) * 2);
                cpa16(nK + so, kf + kvb + (size_t)row * EN + lc);
                cpa16(nV + so, vf + kvb + (size_t)row * EN + lc);
            }
        }
        CPA_COMMIT();
        CPA_WAIT1();          // tile kb complete (newest group still pending)
        __syncthreads();

        // ---- S = Q K^T : fp16 single-term ----
        float Sc[8][4];
#pragma unroll
        for (int j = 0; j < 8; j++)
#pragma unroll
            for (int e = 0; e < 4; e++) Sc[j][e] = 0.0f;

#pragma unroll
        for (int kk = 0; kk < 4; kk++) {
            uint32_t q0, q1, q2, q3;
            ldsm4(q0, q1, q2, q3, bQ + qoff + kk * 32);
#pragma unroll
            for (int ng = 0; ng < 4; ng++) {
                uint32_t k0, k1, k2, k3;
                ldsm4(k0, k1, k2, k3,
                      bK + koff + (uint32_t)(ng * 16 * ALA * 2 + kk * 32));
                mma16816h(Sc[2 * ng],     q0, q1, q2, q3, k0, k1);
                mma16816h(Sc[2 * ng + 1], q0, q1, q2, q3, k2, k3);
            }
        }

        // ---- causal mask on diagonal tiles ----
        if (kb >= (sb << 1)) {
            int row0 = s0 + 16 * w + g;
            int c00  = (kb << 6) + 2 * tq;
#pragma unroll
            for (int j = 0; j < 8; j++) {
                int c = c00 + 8 * j;
                if (c > row0)         Sc[j][0] = -1e30f;
                if (c + 1 > row0)     Sc[j][1] = -1e30f;
                if (c > row0 + 8)     Sc[j][2] = -1e30f;
                if (c + 1 > row0 + 8) Sc[j][3] = -1e30f;
            }
        }

        // ---- warp-local online softmax (rows g and g+8) ----
        {
            float mx0 = -1e30f, mx1 = -1e30f;
#pragma unroll
            for (int j = 0; j < 8; j++) {
                mx0 = fmaxf(mx0, fmaxf(Sc[j][0], Sc[j][1]));
                mx1 = fmaxf(mx1, fmaxf(Sc[j][2], Sc[j][3]));
            }
            mx0 = fmaxf(mx0, __shfl_xor_sync(0xffffffffu, mx0, 1));
            mx0 = fmaxf(mx0, __shfl_xor_sync(0xffffffffu, mx0, 2));
            mx1 = fmaxf(mx1, __shfl_xor_sync(0xffffffffu, mx1, 1));
            mx1 = fmaxf(mx1, __shfl_xor_sync(0xffffffffu, mx1, 2));
            float nm0 = fmaxf(rm0, mx0), nm1 = fmaxf(rm1, mx1);
            float a0 = __expf(rm0 - nm0), a1 = __expf(rm1 - nm1);
            float ps0 = 0.0f, ps1 = 0.0f;
#pragma unroll
            for (int j = 0; j < 8; j++) {
                float e0 = __expf(Sc[j][0] - nm0);
                float e1 = __expf(Sc[j][1] - nm0);
                float e2 = __expf(Sc[j][2] - nm1);
                float e3 = __expf(Sc[j][3] - nm1);
                Sc[j][0] = e0; Sc[j][1] = e1; Sc[j][2] = e2; Sc[j][3] = e3;
                ps0 += e0 + e1; ps1 += e2 + e3;
            }
            ps0 += __shfl_xor_sync(0xffffffffu, ps0, 1);
            ps0 += __shfl_xor_sync(0xffffffffu, ps0, 2);
            ps1 += __shfl_xor_sync(0xffffffffu, ps1, 1);
            ps1 += __shfl_xor_sync(0xffffffffu, ps1, 2);
            rl0 = rl0 * a0 + ps0; rl1 = rl1 * a1 + ps1;
            rm0 = nm0; rm1 = nm1;
#pragma unroll
            for (int j = 0; j < 8; j++) {
                accO[j][0] *= a0; accO[j][1] *= a0;
                accO[j][2] *= a1; accO[j][3] *= a1;
            }
        }

        // ---- O += P V : P in fp16 hi/lo (2-term), V fp16 ----
#pragma unroll
        for (int kk = 0; kk < 4; kk++) {
            float p0 = Sc[2 * kk][0],     p1 = Sc[2 * kk][1];
            float p2 = Sc[2 * kk][2],     p3 = Sc[2 * kk][3];
            float p4 = Sc[2 * kk + 1][0], p5 = Sc[2 * kk + 1][1];
            float p6 = Sc[2 * kk + 1][2], p7 = Sc[2 * kk + 1][3];
            uint32_t ph0 = pkh2(p0, p1), ph1 = pkh2(p2, p3);
            uint32_t ph2 = pkh2(p4, p5), ph3 = pkh2(p6, p7);
            __half2 h0 = *(__half2*)&ph0, h1 = *(__half2*)&ph1;
            __half2 h2 = *(__half2*)&ph2, h3 = *(__half2*)&ph3;
            uint32_t pl0 = pkh2(p0 - __low2float(h0), p1 - __high2float(h0));
            uint32_t pl1 = pkh2(p2 - __low2float(h1), p3 - __high2float(h1));
            uint32_t pl2 = pkh2(p4 - __low2float(h2), p5 - __high2float(h2));
            uint32_t pl3 = pkh2(p6 - __low2float(h3), p7 - __high2float(h3));
#pragma unroll
            for (int ng = 0; ng < 4; ng++) {
                uint32_t v0, v1, v2, v3;
                ldsm4t(v0, v1, v2, v3,
                       bV + voff + (uint32_t)(kk * 16 * ALA * 2 + ng * 32));
                mma16816h(accO[2 * ng],     ph0, ph1, ph2, ph3, v0, v1);
                mma16816h(accO[2 * ng],     pl0, pl1, pl2, pl3, v0, v1);
                mma16816h(accO[2 * ng + 1], ph0, ph1, ph2, ph3, v2, v3);
                mma16816h(accO[2 * ng + 1], pl0, pl1, pl2, pl3, v2, v3);
            }
        }
        __syncthreads();   // all warps done with this buffer before overwrite
    }

    // ---- epilogue: normalize, write fp16 O ----
    {
        float inv0 = 1.0f / rl0, inv1 = 1.0f / rl1;
        size_t base0 = qbase + (size_t)(16 * w + g) * EN + 2 * tq;
        size_t base1 = base0 + 8 * EN;
#pragma unroll
        for (int j = 0; j < 8; j++) {
            *(__half2*)(ofp + base0 + 8 * j) =
                __floats2half2_rn(accO[j][0] * inv0, accO[j][1] * inv0);
            *(__half2*)(ofp + base1 + 8 * j) =
                __floats2half2_rn(accO[j][2] * inv1, accO[j][3] * inv1);
        }
    }
}

// ---------------------------------------------------------------------------
// kernel_launch
// ---------------------------------------------------------------------------
extern "C" void kernel_launch(void* const* d_in, const int* in_sizes, int n_in,
                              void* d_out, int out_size)
{
    (void)in_sizes; (void)n_in; (void)out_size;

    const float* query = (const float*)d_in[0];
    const float* key   = (const float*)d_in[1];
    const float* value = (const float*)d_in[2];
    // d_in[3] = attn_mask (int32 tril) -- causal, handled analytically
    const float* Wq = (const float*)d_in[4];
    const float* bq = (const float*)d_in[5];
    const float* Wk = (const float*)d_in[6];
    const float* bk = (const float*)d_in[7];
    const float* Wv = (const float*)d_in[8];
    const float* bv = (const float*)d_in[9];
    const float* Wp = (const float*)d_in[10];
    const float* bp = (const float*)d_in[11];
    float* out = (float*)d_out;

    void* sp = nullptr;
    cudaGetSymbolAddress(&sp, g_scratch);
    float* base = (float*)sp;
    float* gQ = base;                 // fp32 proj outputs
    float* gK = base + 4ull * FM;
    float* gV = base + 8ull * FM;
    __half* qa  = (__half*)(base + 12ull * FM);   // fp16 attention operands
    __half* ka  = (__half*)(base + 14ull * FM);
    __half* va  = (__half*)(base + 16ull * FM);
    __half* qf  = (__half*)(base + 24ull * FM);   // fp16 inputs
    __half* kf  = (__half*)(base + 26ull * FM);
    __half* vf  = (__half*)(base + 28ull * FM);
    __half* ofp = (__half*)(base + 30ull * FM);
    __half* wf  = (__half*)(base + 32ull * FM);
    __half* wqf = wf;
    __half* wkf = wf + 262144;
    __half* wvf = wf + 524288;
    __half* wpf = wf + 786432;

    cudaFuncSetAttribute(gemm_fp16_kernel,
                         cudaFuncAttributeMaxDynamicSharedMemorySize, GEMM16_SM);
    cudaFuncSetAttribute(attention_fp16_kernel,
                         cudaFuncAttributeMaxDynamicSharedMemorySize, ATT_SM);

    const int NB = NSE / 4;
    const int WB = EN * EN / 4;

    // phase 0: convert inputs + weights to fp16
    cvt_fp16_kernel<<<NB / 256, 256>>>(query, qf, NB);
    cvt_fp16_kernel<<<NB / 256, 256>>>(key,   kf, NB);
    cvt_fp16_kernel<<<NB / 256, 256>>>(value, vf, NB);
    cvt_fp16_kernel<<<WB / 256, 256>>>(Wq, wqf, WB);
    cvt_fp16_kernel<<<WB / 256, 256>>>(Wk, wkf, WB);
    cvt_fp16_kernel<<<WB / 256, 256>>>(Wv, wvf, WB);
    cvt_fp16_kernel<<<WB / 256, 256>>>(Wp, wpf, WB);

    // phase 1: projections (Q pre-scaled by 1/sqrt(HD) = 0.125)
    dim3 gg(EN / 128, MTOT / 128);
    gemm_fp16_kernel<<<gg, 256, GEMM16_SM>>>(qf, wqf, bq, gQ, 0.125f);
    gemm_fp16_kernel<<<gg, 256, GEMM16_SM>>>(kf, wkf, bk, gK, 1.0f);
    gemm_fp16_kernel<<<gg, 256, GEMM16_SM>>>(vf, wvf, bv, gV, 1.0f);

    // phase 2: convert projected Q/K/V to fp16
    cvt_fp16_kernel<<<NB / 256, 256>>>(gQ, qa, NB);
    cvt_fp16_kernel<<<NB / 256, 256>>>(gK, ka, NB);
    cvt_fp16_kernel<<<NB / 256, 256>>>(gV, va, NB);

    // phase 3: fp16 flash attention -> fp16 O
    attention_fp16_kernel<<<dim3(SEQ / 128, NBAT * NHEAD), 256, ATT_SM>>>(
        qa, ka, va, ofp);

    // phase 4: output projection
    gemm_fp16_kernel<<<gg, 256, GEMM16_SM>>>(ofp, wpf, bp, out, 1.0f);
}

// round 16
// speedup vs baseline: 4.7204x; 1.0806x over previous
#include <cuda_runtime.h>
#include <cuda_bf16.h>
#include <cuda_fp16.h>
#include <mma.h>
#include <cstdint>

using namespace nvcuda;

// Problem constants
#define EN    512
#define SEQ   2048
#define NBAT  4
#define NHEAD 8
#define HDIM  64
#define MTOT  (NBAT * SEQ)          // 8192
#define NSE   (NBAT * SEQ * EN)     // 4,194,304 floats per buffer
#define FM    (1024 * 1024)

// 132 MB scratch
__device__ float g_scratch[33ull * FM];

// ---------------------------------------------------------------------------
// Batched fp32 -> fp16 converts (one launch for 3 inputs, one for 4 weights)
// ---------------------------------------------------------------------------
__global__ void cvt3_kernel(const float* __restrict__ x0,
                            const float* __restrict__ x1,
                            const float* __restrict__ x2,
                            __half* __restrict__ y0,
                            __half* __restrict__ y1,
                            __half* __restrict__ y2, int n4)
{
    int i = blockIdx.x * blockDim.x + threadIdx.x;
    if (i >= n4) return;
    const float* x = (blockIdx.y == 0) ? x0 : (blockIdx.y == 1) ? x1 : x2;
    __half*      y = (blockIdx.y == 0) ? y0 : (blockIdx.y == 1) ? y1 : y2;
    float4 v = ((const float4*)x)[i];
    __half2* yp = (__half2*)y;
    yp[2 * i]     = __floats2half2_rn(v.x, v.y);
    yp[2 * i + 1] = __floats2half2_rn(v.z, v.w);
}

__global__ void cvt4_kernel(const float* __restrict__ x0,
                            const float* __restrict__ x1,
                            const float* __restrict__ x2,
                            const float* __restrict__ x3,
                            __half* __restrict__ y0,
                            __half* __restrict__ y1,
                            __half* __restrict__ y2,
                            __half* __restrict__ y3, int n4)
{
    int i = blockIdx.x * blockDim.x + threadIdx.x;
    if (i >= n4) return;
    const float* x = (blockIdx.y == 0) ? x0 : (blockIdx.y == 1) ? x1
                   : (blockIdx.y == 2) ? x2 : x3;
    __half*      y = (blockIdx.y == 0) ? y0 : (blockIdx.y == 1) ? y1
                   : (blockIdx.y == 2) ? y2 : y3;
    float4 v = ((const float4*)x)[i];
    __half2* yp = (__half2*)y;
    yp[2 * i]     = __floats2half2_rn(v.x, v.y);
    yp[2 * i + 1] = __floats2half2_rn(v.z, v.w);
}

// ---------------------------------------------------------------------------
// fp16 single-term WMMA GEMM (verified R13-R15 mainloop):
//   C = (A W^T + bias) * scale,  templated output (float direct store, or
//   __half via 1KB/warp smem staging -> packed half2 stores).
// CTA tile 128x128, BK=32, 8 warps, warp tile 32x64.
// ---------------------------------------------------------------------------
#define LDT 40
#define GEMM16_SM (2 * 128 * LDT * 2 + 16 * 128 * 4 + 8 * 256 * 4)   // 36864

template <typename OutT>
__global__ __launch_bounds__(256)
void gemm_fp16_t(const __half* __restrict__ Af,
                 const __half* __restrict__ Wf,
                 const float* __restrict__ bias,
                 OutT* __restrict__ C, float scale)
{
    extern __shared__ char smraw[];
    __half* sA = (__half*)smraw;
    __half* sW = sA + 128 * LDT;
    float* sBias = (float*)(sW + 128 * LDT);          // [16][128] replicated
    float* sScr  = sBias + 16 * 128;                  // 8 x 256 floats

    const int t   = threadIdx.x;
    const int wid = t >> 5;
    const int lan = t & 31;
    const int n0  = blockIdx.x << 7;
    const int m0  = blockIdx.y << 7;
    const int wm  = wid >> 1;
    const int wn  = wid & 1;

    for (int i = t; i < 16 * 128; i += 256) sBias[i] = bias[n0 + (i & 127)];

    const int lr0 = t >> 2, lc = (t & 3) << 3;

    wmma::fragment<wmma::accumulator, 16, 16, 16, float> acc[2][4];
#pragma unroll
    for (int i = 0; i < 2; i++)
#pragma unroll
        for (int j = 0; j < 4; j++) wmma::fill_fragment(acc[i][j], 0.0f);

    uint4 pA[2], pW[2];
#pragma unroll
    for (int j = 0; j < 2; j++) {
        int row = lr0 + j * 64;
        pA[j] = *(const uint4*)(Af + (size_t)(m0 + row) * EN + lc);
        pW[j] = *(const uint4*)(Wf + (size_t)(n0 + row) * EN + lc);
    }

    for (int kt = 0; kt < EN; kt += 32) {
#pragma unroll
        for (int j = 0; j < 2; j++) {
            int row = lr0 + j * 64;
            *(uint4*)(sA + row * LDT + lc) = pA[j];
            *(uint4*)(sW + row * LDT + lc) = pW[j];
        }
        __syncthreads();

        if (kt + 32 < EN) {
#pragma unroll
            for (int j = 0; j < 2; j++) {
                int row = lr0 + j * 64;
                pA[j] = *(const uint4*)(Af + (size_t)(m0 + row) * EN + kt + 32 + lc);
                pW[j] = *(const uint4*)(Wf + (size_t)(n0 + row) * EN + kt + 32 + lc);
            }
        }

#pragma unroll
        for (int kk = 0; kk < 32; kk += 16) {
            wmma::fragment<wmma::matrix_a, 16, 16, 16, __half,
                           wmma::row_major> ah[2];
            wmma::fragment<wmma::matrix_b, 16, 16, 16, __half,
                           wmma::col_major> bh[4];
#pragma unroll
            for (int i = 0; i < 2; i++)
                wmma::load_matrix_sync(ah[i], sA + (wm * 32 + i * 16) * LDT + kk, LDT);
#pragma unroll
            for (int j = 0; j < 4; j++)
                wmma::load_matrix_sync(bh[j], sW + (wn * 64 + j * 16) * LDT + kk, LDT);
#pragma unroll
            for (int i = 0; i < 2; i++)
#pragma unroll
                for (int j = 0; j < 4; j++)
                    wmma::mma_sync(acc[i][j], ah[i], bh[j], acc[i][j]);
        }
        __syncthreads();
    }

    // epilogue
    float* myscr = sScr + wid * 256;
    wmma::fragment<wmma::accumulator, 16, 16, 16, float> bf;
#pragma unroll
    for (int j = 0; j < 4; j++) {
        int c = wn * 64 + j * 16;
        wmma::load_matrix_sync(bf, sBias + c, 128, wmma::mem_row_major);
#pragma unroll
        for (int i = 0; i < 2; i++) {
            int r = wm * 32 + i * 16;
#pragma unroll
            for (int e = 0; e < bf.num_elements; e++)
                acc[i][j].x[e] = (acc[i][j].x[e] + bf.x[e]) * scale;
            if constexpr (__is_same(OutT, float)) {
                wmma::store_matrix_sync(C + (size_t)(m0 + r) * EN + n0 + c,
                                        acc[i][j], EN, wmma::mem_row_major);
            } else {
                // stage fp32 in per-warp smem, emit packed fp16
                wmma::store_matrix_sync(myscr, acc[i][j], 16,
                                        wmma::mem_row_major);
                __syncwarp();
                int rr = lan >> 1, cc = (lan & 1) << 3;
                const float* sp = myscr + rr * 16 + cc;
                __half2 h0 = __floats2half2_rn(sp[0], sp[1]);
                __half2 h1 = __floats2half2_rn(sp[2], sp[3]);
                __half2 h2 = __floats2half2_rn(sp[4], sp[5]);
                __half2 h3 = __floats2half2_rn(sp[6], sp[7]);
                uint4 pack = make_uint4(*(uint32_t*)&h0, *(uint32_t*)&h1,
                                        *(uint32_t*)&h2, *(uint32_t*)&h3);
                *(uint4*)(C + (size_t)(m0 + r + rr) * EN + n0 + c + cc) = pack;
                __syncwarp();
            }
        }
    }
}

// ---------------------------------------------------------------------------
// FA2-style fp16 flash attention (verified R15).
// Br = 128, Bc = 64, 256 threads = 8 warps; warp w owns rows 16w..16w+15.
// QK^T: single-term fp16.  PV: P split to fp16 hi/lo (2-term), V fp16.
// K/V fills via cp.async, double-buffered.  54 KB smem -> 2 CTAs/SM.
// ---------------------------------------------------------------------------
#define ALA 72
#define AQ_B (128 * ALA * 2)      // 18432
#define AK_B (64 * ALA * 2)       //  9216
#define ATT_SM (AQ_B + 4 * AK_B)  // 55296

__device__ __forceinline__ void ldsm4(uint32_t& r0, uint32_t& r1,
                                      uint32_t& r2, uint32_t& r3, uint32_t a)
{
    asm volatile("ldmatrix.sync.aligned.m8n8.x4.shared.b16 {%0,%1,%2,%3}, [%4];"
                 : "=r"(r0), "=r"(r1), "=r"(r2), "=r"(r3) : "r"(a) : "memory");
}
__device__ __forceinline__ void ldsm4t(uint32_t& r0, uint32_t& r1,
                                       uint32_t& r2, uint32_t& r3, uint32_t a)
{
    asm volatile("ldmatrix.sync.aligned.m8n8.x4.trans.shared.b16 {%0,%1,%2,%3}, [%4];"
                 : "=r"(r0), "=r"(r1), "=r"(r2), "=r"(r3) : "r"(a) : "memory");
}
__device__ __forceinline__ void mma16816h(float* c, uint32_t a0, uint32_t a1,
                                          uint32_t a2, uint32_t a3,
                                          uint32_t b0, uint32_t b1)
{
    asm volatile(
        "mma.sync.aligned.m16n8k16.row.col.f32.f16.f16.f32 "
        "{%0,%1,%2,%3}, {%4,%5,%6,%7}, {%8,%9}, {%0,%1,%2,%3};"
        : "+f"(c[0]), "+f"(c[1]), "+f"(c[2]), "+f"(c[3])
        : "r"(a0), "r"(a1), "r"(a2), "r"(a3), "r"(b0), "r"(b1));
}
__device__ __forceinline__ uint32_t pkh2(float x, float y)
{
    __half2 t = __floats2half2_rn(x, y);
    return *reinterpret_cast<uint32_t*>(&t);
}
__device__ __forceinline__ void cpa16(uint32_t dst, const void* src)
{
    asm volatile("cp.async.cg.shared.global [%0], [%1], 16;"
                 :: "r"(dst), "l"(src) : "memory");
}
#define CPA_COMMIT() asm volatile("cp.async.commit_group;" ::: "memory")
#define CPA_WAIT1()  asm volatile("cp.async.wait_group 1;" ::: "memory")

__global__ __launch_bounds__(256, 2)
void attention_fp16_kernel(const __half* __restrict__ qf,
                           const __half* __restrict__ kf,
                           const __half* __restrict__ vf,
                           __half* __restrict__ ofp)
{
    extern __shared__ char smraw[];
    __half* sQ = (__half*)smraw;
    uint32_t sbase = (uint32_t)__cvta_generic_to_shared(smraw);
    const uint32_t bQ  = sbase;
    const uint32_t bK0 = sbase + AQ_B;
    const uint32_t bK1 = sbase + AQ_B + AK_B;
    const uint32_t bV0 = sbase + AQ_B + 2 * AK_B;
    const uint32_t bV1 = sbase + AQ_B + 3 * AK_B;

    const int t  = threadIdx.x;
    const int w  = t >> 5;
    const int l  = t & 31;
    const int g  = l >> 2;
    const int tq = l & 3;
    const int sb = (int)gridDim.x - 1 - (int)blockIdx.x;   // heavy-first
    const int s0 = sb << 7;
    const int nh = blockIdx.y;
    const int n  = nh >> 3, h = nh & 7;

    const size_t qbase = (size_t)(n * SEQ + s0) * EN + h * HDIM;
    const size_t kvb0  = (size_t)(n * SEQ) * EN + h * HDIM;

    const int lrow = t >> 3, lc = (t & 7) << 3;

    // ---- load Q tile 128x64 fp16 ----
#pragma unroll
    for (int p = 0; p < 4; p++) {
        int row = lrow + p * 32;
        *(uint4*)(sQ + row * ALA + lc) =
            *(const uint4*)(qf + qbase + (size_t)row * EN + lc);
    }

    // ---- cp.async prologue: K/V tile 0 ----
    {
#pragma unroll
        for (int p = 0; p < 2; p++) {
            int row = lrow + p * 32;
            uint32_t so = (uint32_t)((row * ALA + lc) * 2);
            cpa16(bK0 + so, kf + kvb0 + (size_t)row * EN + lc);
            cpa16(bV0 + so, vf + kvb0 + (size_t)row * EN + lc);
        }
    }
    CPA_COMMIT();

    const uint32_t qoff = (uint32_t)(((16 * w + (l & 15)) * ALA + ((l >> 4) << 3)) * 2);
    const uint32_t koff = (uint32_t)(((((l >> 4) << 3) + (l & 7)) * ALA
                                     + (((l >> 3) & 1) << 3)) * 2);
    const uint32_t voff = (uint32_t)((((((l >> 3) & 1) << 3) + (l & 7)) * ALA
                                     + ((l >> 4) << 3)) * 2);

    float accO[8][4];
#pragma unroll
    for (int j = 0; j < 8; j++)
#pragma unroll
        for (int e = 0; e < 4; e++) accO[j][e] = 0.0f;
    float rm0 = -1e30f, rm1 = -1e30f, rl0 = 0.0f, rl1 = 0.0f;

    const int kbmax = (sb << 1) + 2;
    for (int kb = 0; kb < kbmax; kb++) {
        const uint32_t bK = (kb & 1) ? bK1 : bK0;
        const uint32_t bV = (kb & 1) ? bV1 : bV0;

        if (kb + 1 < kbmax) {
            const uint32_t nK = (kb & 1) ? bK0 : bK1;
            const uint32_t nV = (kb & 1) ? bV0 : bV1;
            size_t kvb = kvb0 + (size_t)((kb + 1) << 6) * EN;
#pragma unroll
            for (int p = 0; p < 2; p++) {
                int row = lrow + p * 32;
                uint32_t so = (uint32_t)((row * ALA + lc) * 2);
                cpa16(nK + so, kf + kvb + (size_t)row * EN + lc);
                cpa16(nV + so, vf + kvb + (size_t)row * EN + lc);
            }
        }
        CPA_COMMIT();
        CPA_WAIT1();
        __syncthreads();

        // ---- S = Q K^T : fp16 single-term ----
        float Sc[8][4];
#pragma unroll
        for (int j = 0; j < 8; j++)
#pragma unroll
            for (int e = 0; e < 4; e++) Sc[j][e] = 0.0f;

#pragma unroll
        for (int kk = 0; kk < 4; kk++) {
            uint32_t q0, q1, q2, q3;
            ldsm4(q0, q1, q2, q3, bQ + qoff + kk * 32);
#pragma unroll
            for (int ng = 0; ng < 4; ng++) {
                uint32_t k0, k1, k2, k3;
                ldsm4(k0, k1, k2, k3,
                      bK + koff + (uint32_t)(ng * 16 * ALA * 2 + kk * 32));
                mma16816h(Sc[2 * ng],     q0, q1, q2, q3, k0, k1);
                mma16816h(Sc[2 * ng + 1], q0, q1, q2, q3, k2, k3);
            }
        }

        // ---- causal mask on diagonal tiles ----
        if (kb >= (sb << 1)) {
            int row0 = s0 + 16 * w + g;
            int c00  = (kb << 6) + 2 * tq;
#pragma unroll
            for (int j = 0; j < 8; j++) {
                int c = c00 + 8 * j;
                if (c > row0)         Sc[j][0] = -1e30f;
                if (c + 1 > row0)     Sc[j][1] = -1e30f;
                if (c > row0 + 8)     Sc[j][2] = -1e30f;
                if (c + 1 > row0 + 8) Sc[j][3] = -1e30f;
            }
        }

        // ---- warp-local online softmax ----
        {
            float mx0 = -1e30f, mx1 = -1e30f;
#pragma unroll
            for (int j = 0; j < 8; j++) {
                mx0 = fmaxf(mx0, fmaxf(Sc[j][0], Sc[j][1]));
                mx1 = fmaxf(mx1, fmaxf(Sc[j][2], Sc[j][3]));
            }
            mx0 = fmaxf(mx0, __shfl_xor_sync(0xffffffffu, mx0, 1));
            mx0 = fmaxf(mx0, __shfl_xor_sync(0xffffffffu, mx0, 2));
            mx1 = fmaxf(mx1, __shfl_xor_sync(0xffffffffu, mx1, 1));
            mx1 = fmaxf(mx1, __shfl_xor_sync(0xffffffffu, mx1, 2));
            float nm0 = fmaxf(rm0, mx0), nm1 = fmaxf(rm1, mx1);
            float a0 = __expf(rm0 - nm0), a1 = __expf(rm1 - nm1);
            float ps0 = 0.0f, ps1 = 0.0f;
#pragma unroll
            for (int j = 0; j < 8; j++) {
                float e0 = __expf(Sc[j][0] - nm0);
                float e1 = __expf(Sc[j][1] - nm0);
                float e2 = __expf(Sc[j][2] - nm1);
                float e3 = __expf(Sc[j][3] - nm1);
                Sc[j][0] = e0; Sc[j][1] = e1; Sc[j][2] = e2; Sc[j][3] = e3;
                ps0 += e0 + e1; ps1 += e2 + e3;
            }
            ps0 += __shfl_xor_sync(0xffffffffu, ps0, 1);
            ps0 += __shfl_xor_sync(0xffffffffu, ps0, 2);
            ps1 += __shfl_xor_sync(0xffffffffu, ps1, 1);
            ps1 += __shfl_xor_sync(0xffffffffu, ps1, 2);
            rl0 = rl0 * a0 + ps0; rl1 = rl1 * a1 + ps1;
            rm0 = nm0; rm1 = nm1;
#pragma unroll
            for (int j = 0; j < 8; j++) {
                accO[j][0] *= a0; accO[j][1] *= a0;
                accO[j][2] *= a1; accO[j][3] *= a1;
            }
        }

        // ---- O += P V : P fp16 hi/lo (2-term), V fp16 ----
#pragma unroll
        for (int kk = 0; kk < 4; kk++) {
            float p0 = Sc[2 * kk][0],     p1 = Sc[2 * kk][1];
            float p2 = Sc[2 * kk][2],     p3 = Sc[2 * kk][3];
            float p4 = Sc[2 * kk + 1][0], p5 = Sc[2 * kk + 1][1];
            float p6 = Sc[2 * kk + 1][2], p7 = Sc[2 * kk + 1][3];
            uint32_t ph0 = pkh2(p0, p1), ph1 = pkh2(p2, p3);
            uint32_t ph2 = pkh2(p4, p5), ph3 = pkh2(p6, p7);
            __half2 h0 = *(__half2*)&ph0, h1 = *(__half2*)&ph1;
            __half2 h2 = *(__half2*)&ph2, h3 = *(__half2*)&ph3;
            uint32_t pl0 = pkh2(p0 - __low2float(h0), p1 - __high2float(h0));
            uint32_t pl1 = pkh2(p2 - __low2float(h1), p3 - __high2float(h1));
            uint32_t pl2 = pkh2(p4 - __low2float(h2), p5 - __high2float(h2));
            uint32_t pl3 = pkh2(p6 - __low2float(h3), p7 - __high2float(h3));
#pragma unroll
            for (int ng = 0; ng < 4; ng++) {
                uint32_t v0, v1, v2, v3;
                ldsm4t(v0, v1, v2, v3,
                       bV + voff + (uint32_t)(kk * 16 * ALA * 2 + ng * 32));
                mma16816h(accO[2 * ng],     ph0, ph1, ph2, ph3, v0, v1);
                mma16816h(accO[2 * ng],     pl0, pl1, pl2, pl3, v0, v1);
                mma16816h(accO[2 * ng + 1], ph0, ph1, ph2, ph3, v2, v3);
                mma16816h(accO[2 * ng + 1], pl0, pl1, pl2, pl3, v2, v3);
            }
        }
        __syncthreads();
    }

    // ---- epilogue: normalize, write fp16 O ----
    {
        float inv0 = 1.0f / rl0, inv1 = 1.0f / rl1;
        size_t base0 = qbase + (size_t)(16 * w + g) * EN + 2 * tq;
        size_t base1 = base0 + 8 * EN;
#pragma unroll
        for (int j = 0; j < 8; j++) {
            *(__half2*)(ofp + base0 + 8 * j) =
                __floats2half2_rn(accO[j][0] * inv0, accO[j][1] * inv0);
            *(__half2*)(ofp + base1 + 8 * j) =
                __floats2half2_rn(accO[j][2] * inv1, accO[j][3] * inv1);
        }
    }
}

// ---------------------------------------------------------------------------
// kernel_launch
// ---------------------------------------------------------------------------
extern "C" void kernel_launch(void* const* d_in, const int* in_sizes, int n_in,
                              void* d_out, int out_size)
{
    (void)in_sizes; (void)n_in; (void)out_size;

    const float* query = (const float*)d_in[0];
    const float* key   = (const float*)d_in[1];
    const float* value = (const float*)d_in[2];
    // d_in[3] = attn_mask (int32 tril) -- causal, handled analytically
    const float* Wq = (const float*)d_in[4];
    const float* bq = (const float*)d_in[5];
    const float* Wk = (const float*)d_in[6];
    const float* bk = (const float*)d_in[7];
    const float* Wv = (const float*)d_in[8];
    const float* bv = (const float*)d_in[9];
    const float* Wp = (const float*)d_in[10];
    const float* bp = (const float*)d_in[11];
    float* out = (float*)d_out;

    void* sp = nullptr;
    cudaGetSymbolAddress(&sp, g_scratch);
    float* base = (float*)sp;
    __half* qa  = (__half*)(base + 12ull * FM);   // fp16 attention operands
    __half* ka  = (__half*)(base + 14ull * FM);
    __half* va  = (__half*)(base + 16ull * FM);
    __half* qf  = (__half*)(base + 24ull * FM);   // fp16 inputs
    __half* kf  = (__half*)(base + 26ull * FM);
    __half* vf  = (__half*)(base + 28ull * FM);
    __half* ofp = (__half*)(base + 30ull * FM);
    __half* wf  = (__half*)(base + 32ull * FM);
    __half* wqf = wf;
    __half* wkf = wf + 262144;
    __half* wvf = wf + 524288;
    __half* wpf = wf + 786432;

    cudaFuncSetAttribute(gemm_fp16_t<float>,
                         cudaFuncAttributeMaxDynamicSharedMemorySize, GEMM16_SM);
    cudaFuncSetAttribute(gemm_fp16_t<__half>,
                         cudaFuncAttributeMaxDynamicSharedMemorySize, GEMM16_SM);
    cudaFuncSetAttribute(attention_fp16_kernel,
                         cudaFuncAttributeMaxDynamicSharedMemorySize, ATT_SM);

    const int NB = NSE / 4;
    const int WB = EN * EN / 4;

    // phase 0: batched converts (2 launches)
    cvt3_kernel<<<dim3(NB / 256, 3), 256>>>(query, key, value, qf, kf, vf, NB);
    cvt4_kernel<<<dim3(WB / 256, 4), 256>>>(Wq, Wk, Wv, Wp,
                                            wqf, wkf, wvf, wpf, WB);

    // phase 1: projections, fp16 output direct (Q pre-scaled by 0.125)
    dim3 gg(EN / 128, MTOT / 128);
    gemm_fp16_t<__half><<<gg, 256, GEMM16_SM>>>(qf, wqf, bq, qa, 0.125f);
    gemm_fp16_t<__half><<<gg, 256, GEMM16_SM>>>(kf, wkf, bk, ka, 1.0f);
    gemm_fp16_t<__half><<<gg, 256, GEMM16_SM>>>(vf, wvf, bv, va, 1.0f);

    // phase 2: fp16 flash attention -> fp16 O
    attention_fp16_kernel<<<dim3(SEQ / 128, NBAT * NHEAD), 256, ATT_SM>>>(
        qa, ka, va, ofp);

    // phase 3: output projection (fp32 store)
    gemm_fp16_t<float><<<gg, 256, GEMM16_SM>>>(ofp, wpf, bp, out, 1.0f);
}

// round 17
// speedup vs baseline: 5.1388x; 1.0886x over previous
#include <cuda_runtime.h>
#include <cuda_bf16.h>
#include <cuda_fp16.h>
#include <mma.h>
#include <cstdint>

using namespace nvcuda;

// Problem constants
#define EN    512
#define SEQ   2048
#define NBAT  4
#define NHEAD 8
#define HDIM  64
#define MTOT  (NBAT * SEQ)          // 8192
#define NSE   (NBAT * SEQ * EN)     // 4,194,304 floats per buffer
#define FM    (1024 * 1024)

// scale folded into Q projection: (1/sqrt(64)) * log2(e)
#define QSCALE 0.18033688011116028f

// 132 MB scratch
__device__ float g_scratch[33ull * FM];

// ---------------------------------------------------------------------------
// Batched fp32 -> fp16 converts
// ---------------------------------------------------------------------------
__global__ void cvt3_kernel(const float* __restrict__ x0,
                            const float* __restrict__ x1,
                            const float* __restrict__ x2,
                            __half* __restrict__ y0,
                            __half* __restrict__ y1,
                            __half* __restrict__ y2, int n4)
{
    int i = blockIdx.x * blockDim.x + threadIdx.x;
    if (i >= n4) return;
    const float* x = (blockIdx.y == 0) ? x0 : (blockIdx.y == 1) ? x1 : x2;
    __half*      y = (blockIdx.y == 0) ? y0 : (blockIdx.y == 1) ? y1 : y2;
    float4 v = ((const float4*)x)[i];
    __half2* yp = (__half2*)y;
    yp[2 * i]     = __floats2half2_rn(v.x, v.y);
    yp[2 * i + 1] = __floats2half2_rn(v.z, v.w);
}

__global__ void cvt4_kernel(const float* __restrict__ x0,
                            const float* __restrict__ x1,
                            const float* __restrict__ x2,
                            const float* __restrict__ x3,
                            __half* __restrict__ y0,
                            __half* __restrict__ y1,
                            __half* __restrict__ y2,
                            __half* __restrict__ y3, int n4)
{
    int i = blockIdx.x * blockDim.x + threadIdx.x;
    if (i >= n4) return;
    const float* x = (blockIdx.y == 0) ? x0 : (blockIdx.y == 1) ? x1
                   : (blockIdx.y == 2) ? x2 : x3;
    __half*      y = (blockIdx.y == 0) ? y0 : (blockIdx.y == 1) ? y1
                   : (blockIdx.y == 2) ? y2 : y3;
    float4 v = ((const float4*)x)[i];
    __half2* yp = (__half2*)y;
    yp[2 * i]     = __floats2half2_rn(v.x, v.y);
    yp[2 * i + 1] = __floats2half2_rn(v.z, v.w);
}

// ---------------------------------------------------------------------------
// fp16 single-term WMMA GEMM mainloop (verified R13-R16).
// GEMM_BODY computes C = (A W^T + bias) * scale for a 128x128 CTA tile.
// ---------------------------------------------------------------------------
#define LDT 40
#define GEMM16_SM (2 * 128 * LDT * 2 + 16 * 128 * 4 + 8 * 256 * 4)   // 36864

template <typename OutT>
__device__ __forceinline__ void gemm_body(const __half* __restrict__ Af,
                                          const __half* __restrict__ Wf,
                                          const float* __restrict__ bias,
                                          OutT* __restrict__ C, float scale,
                                          char* smraw)
{
    __half* sA = (__half*)smraw;
    __half* sW = sA + 128 * LDT;
    float* sBias = (float*)(sW + 128 * LDT);          // [16][128] replicated
    float* sScr  = sBias + 16 * 128;                  // 8 x 256 floats

    const int t   = threadIdx.x;
    const int wid = t >> 5;
    const int lan = t & 31;
    const int n0  = blockIdx.x << 7;
    const int m0  = blockIdx.y << 7;
    const int wm  = wid >> 1;
    const int wn  = wid & 1;

    for (int i = t; i < 16 * 128; i += 256) sBias[i] = bias[n0 + (i & 127)];

    const int lr0 = t >> 2, lc = (t & 3) << 3;

    wmma::fragment<wmma::accumulator, 16, 16, 16, float> acc[2][4];
#pragma unroll
    for (int i = 0; i < 2; i++)
#pragma unroll
        for (int j = 0; j < 4; j++) wmma::fill_fragment(acc[i][j], 0.0f);

    uint4 pA[2], pW[2];
#pragma unroll
    for (int j = 0; j < 2; j++) {
        int row = lr0 + j * 64;
        pA[j] = *(const uint4*)(Af + (size_t)(m0 + row) * EN + lc);
        pW[j] = *(const uint4*)(Wf + (size_t)(n0 + row) * EN + lc);
    }

    for (int kt = 0; kt < EN; kt += 32) {
#pragma unroll
        for (int j = 0; j < 2; j++) {
            int row = lr0 + j * 64;
            *(uint4*)(sA + row * LDT + lc) = pA[j];
            *(uint4*)(sW + row * LDT + lc) = pW[j];
        }
        __syncthreads();

        if (kt + 32 < EN) {
#pragma unroll
            for (int j = 0; j < 2; j++) {
                int row = lr0 + j * 64;
                pA[j] = *(const uint4*)(Af + (size_t)(m0 + row) * EN + kt + 32 + lc);
                pW[j] = *(const uint4*)(Wf + (size_t)(n0 + row) * EN + kt + 32 + lc);
            }
        }

#pragma unroll
        for (int kk = 0; kk < 32; kk += 16) {
            wmma::fragment<wmma::matrix_a, 16, 16, 16, __half,
                           wmma::row_major> ah[2];
            wmma::fragment<wmma::matrix_b, 16, 16, 16, __half,
                           wmma::col_major> bh[4];
#pragma unroll
            for (int i = 0; i < 2; i++)
                wmma::load_matrix_sync(ah[i], sA + (wm * 32 + i * 16) * LDT + kk, LDT);
#pragma unroll
            for (int j = 0; j < 4; j++)
                wmma::load_matrix_sync(bh[j], sW + (wn * 64 + j * 16) * LDT + kk, LDT);
#pragma unroll
            for (int i = 0; i < 2; i++)
#pragma unroll
                for (int j = 0; j < 4; j++)
                    wmma::mma_sync(acc[i][j], ah[i], bh[j], acc[i][j]);
        }
        __syncthreads();
    }

    float* myscr = sScr + wid * 256;
    wmma::fragment<wmma::accumulator, 16, 16, 16, float> bf;
#pragma unroll
    for (int j = 0; j < 4; j++) {
        int c = wn * 64 + j * 16;
        wmma::load_matrix_sync(bf, sBias + c, 128, wmma::mem_row_major);
#pragma unroll
        for (int i = 0; i < 2; i++) {
            int r = wm * 32 + i * 16;
#pragma unroll
            for (int e = 0; e < bf.num_elements; e++)
                acc[i][j].x[e] = (acc[i][j].x[e] + bf.x[e]) * scale;
            if constexpr (__is_same(OutT, float)) {
                wmma::store_matrix_sync(C + (size_t)(m0 + r) * EN + n0 + c,
                                        acc[i][j], EN, wmma::mem_row_major);
            } else {
                wmma::store_matrix_sync(myscr, acc[i][j], 16,
                                        wmma::mem_row_major);
                __syncwarp();
                int rr = lan >> 1, cc = (lan & 1) << 3;
                const float* sp = myscr + rr * 16 + cc;
                __half2 h0 = __floats2half2_rn(sp[0], sp[1]);
                __half2 h1 = __floats2half2_rn(sp[2], sp[3]);
                __half2 h2 = __floats2half2_rn(sp[4], sp[5]);
                __half2 h3 = __floats2half2_rn(sp[6], sp[7]);
                uint4 pack = make_uint4(*(uint32_t*)&h0, *(uint32_t*)&h1,
                                        *(uint32_t*)&h2, *(uint32_t*)&h3);
                *(uint4*)(C + (size_t)(m0 + r + rr) * EN + n0 + c + cc) = pack;
                __syncwarp();
            }
        }
    }
}

// Fused QKV projection: blockIdx.z selects (A, W, bias, C, scale).
__global__ __launch_bounds__(256)
void gemm_qkv_kernel(const __half* __restrict__ qf, const __half* __restrict__ kf,
                     const __half* __restrict__ vf,
                     const __half* __restrict__ wq, const __half* __restrict__ wk,
                     const __half* __restrict__ wv,
                     const float* __restrict__ bq, const float* __restrict__ bk,
                     const float* __restrict__ bv,
                     __half* __restrict__ qa, __half* __restrict__ ka,
                     __half* __restrict__ va)
{
    extern __shared__ char smraw[];
    int z = blockIdx.z;
    const __half* A = (z == 0) ? qf : (z == 1) ? kf : vf;
    const __half* W = (z == 0) ? wq : (z == 1) ? wk : wv;
    const float*  b = (z == 0) ? bq : (z == 1) ? bk : bv;
    __half*       C = (z == 0) ? qa : (z == 1) ? ka : va;
    float     scale = (z == 0) ? QSCALE : 1.0f;
    gemm_body<__half>(A, W, b, C, scale, smraw);
}

// Output projection: fp32 store.
__global__ __launch_bounds__(256)
void gemm_out_kernel(const __half* __restrict__ Af, const __half* __restrict__ Wf,
                     const float* __restrict__ bias, float* __restrict__ C)
{
    extern __shared__ char smraw[];
    gemm_body<float>(Af, Wf, bias, C, 1.0f, smraw);
}

// ---------------------------------------------------------------------------
// FA2-style fp16 flash attention (verified R15/R16 numerics; exp2 domain).
// Br = 64, Bc = 64, 128 threads = 4 warps; warp w owns rows 16w..16w+15.
// 46 KB smem + <=128 regs -> 4 CTAs/SM = 4 independent dependency streams
// (the latency-hiding that 2 CTAs couldn't provide).
// QK^T: single-term fp16 (Q pre-scaled by 0.125*log2e; softmax uses exp2f).
// PV: P split to fp16 hi/lo (2-term), V fp16.  cp.async double-buffered K/V.
// ---------------------------------------------------------------------------
#define ALA 72
#define AQ_B (64 * ALA * 2)       // 9216
#define AK_B (64 * ALA * 2)       // 9216
#define ATT_SM (AQ_B + 4 * AK_B)  // 46080

__device__ __forceinline__ void ldsm4(uint32_t& r0, uint32_t& r1,
                                      uint32_t& r2, uint32_t& r3, uint32_t a)
{
    asm volatile("ldmatrix.sync.aligned.m8n8.x4.shared.b16 {%0,%1,%2,%3}, [%4];"
                 : "=r"(r0), "=r"(r1), "=r"(r2), "=r"(r3) : "r"(a) : "memory");
}
__device__ __forceinline__ void ldsm4t(uint32_t& r0, uint32_t& r1,
                                       uint32_t& r2, uint32_t& r3, uint32_t a)
{
    asm volatile("ldmatrix.sync.aligned.m8n8.x4.trans.shared.b16 {%0,%1,%2,%3}, [%4];"
                 : "=r"(r0), "=r"(r1), "=r"(r2), "=r"(r3) : "r"(a) : "memory");
}
__device__ __forceinline__ void mma16816h(float* c, uint32_t a0, uint32_t a1,
                                          uint32_t a2, uint32_t a3,
                                          uint32_t b0, uint32_t b1)
{
    asm volatile(
        "mma.sync.aligned.m16n8k16.row.col.f32.f16.f16.f32 "
        "{%0,%1,%2,%3}, {%4,%5,%6,%7}, {%8,%9}, {%0,%1,%2,%3};"
        : "+f"(c[0]), "+f"(c[1]), "+f"(c[2]), "+f"(c[3])
        : "r"(a0), "r"(a1), "r"(a2), "r"(a3), "r"(b0), "r"(b1));
}
__device__ __forceinline__ uint32_t pkh2(float x, float y)
{
    __half2 t = __floats2half2_rn(x, y);
    return *reinterpret_cast<uint32_t*>(&t);
}
__device__ __forceinline__ void cpa16(uint32_t dst, const void* src)
{
    asm volatile("cp.async.cg.shared.global [%0], [%1], 16;"
                 :: "r"(dst), "l"(src) : "memory");
}
#define CPA_COMMIT() asm volatile("cp.async.commit_group;" ::: "memory")
#define CPA_WAIT1()  asm volatile("cp.async.wait_group 1;" ::: "memory")

__global__ __launch_bounds__(128, 4)
void attention_fp16_kernel(const __half* __restrict__ qf,
                           const __half* __restrict__ kf,
                           const __half* __restrict__ vf,
                           __half* __restrict__ ofp)
{
    extern __shared__ char smraw[];
    __half* sQ = (__half*)smraw;
    uint32_t sbase = (uint32_t)__cvta_generic_to_shared(smraw);
    const uint32_t bQ  = sbase;
    const uint32_t bK0 = sbase + AQ_B;
    const uint32_t bK1 = sbase + AQ_B + AK_B;
    const uint32_t bV0 = sbase + AQ_B + 2 * AK_B;
    const uint32_t bV1 = sbase + AQ_B + 3 * AK_B;

    const int t  = threadIdx.x;
    const int w  = t >> 5;           // 0..3 -> rows 16w..16w+15
    const int l  = t & 31;
    const int g  = l >> 2;
    const int tq = l & 3;
    const int sb = (int)gridDim.x - 1 - (int)blockIdx.x;   // heavy-first
    const int s0 = sb << 6;
    const int nh = blockIdx.y;
    const int n  = nh >> 3, h = nh & 7;

    const size_t qbase = (size_t)(n * SEQ + s0) * EN + h * HDIM;
    const size_t kvb0  = (size_t)(n * SEQ) * EN + h * HDIM;

    const int lrow = t >> 3, lc = (t & 7) << 3;   // 16 rows x 8 chunks

    // ---- load Q tile 64x64 fp16 ----
#pragma unroll
    for (int p = 0; p < 4; p++) {
        int row = lrow + p * 16;
        *(uint4*)(sQ + row * ALA + lc) =
            *(const uint4*)(qf + qbase + (size_t)row * EN + lc);
    }

    // ---- cp.async prologue: K/V tile 0 ----
#pragma unroll
    for (int p = 0; p < 4; p++) {
        int row = lrow + p * 16;
        uint32_t so = (uint32_t)((row * ALA + lc) * 2);
        cpa16(bK0 + so, kf + kvb0 + (size_t)row * EN + lc);
        cpa16(bV0 + so, vf + kvb0 + (size_t)row * EN + lc);
    }
    CPA_COMMIT();

    const uint32_t qoff = (uint32_t)(((16 * w + (l & 15)) * ALA + ((l >> 4) << 3)) * 2);
    const uint32_t koff = (uint32_t)(((((l >> 4) << 3) + (l & 7)) * ALA
                                     + (((l >> 3) & 1) << 3)) * 2);
    const uint32_t voff = (uint32_t)((((((l >> 3) & 1) << 3) + (l & 7)) * ALA
                                     + ((l >> 4) << 3)) * 2);

    float accO[8][4];
#pragma unroll
    for (int j = 0; j < 8; j++)
#pragma unroll
        for (int e = 0; e < 4; e++) accO[j][e] = 0.0f;
    float rm0 = -1e30f, rm1 = -1e30f, rl0 = 0.0f, rl1 = 0.0f;

    const int kbmax = sb + 1;
    for (int kb = 0; kb < kbmax; kb++) {
        const uint32_t bK = (kb & 1) ? bK1 : bK0;
        const uint32_t bV = (kb & 1) ? bV1 : bV0;

        if (kb + 1 < kbmax) {
            const uint32_t nK = (kb & 1) ? bK0 : bK1;
            const uint32_t nV = (kb & 1) ? bV0 : bV1;
            size_t kvb = kvb0 + (size_t)((kb + 1) << 6) * EN;
#pragma unroll
            for (int p = 0; p < 4; p++) {
                int row = lrow + p * 16;
                uint32_t so = (uint32_t)((row * ALA + lc) * 2);
                cpa16(nK + so, kf + kvb + (size_t)row * EN + lc);
                cpa16(nV + so, vf + kvb + (size_t)row * EN + lc);
            }
        }
        CPA_COMMIT();
        CPA_WAIT1();
        __syncthreads();

        // ---- S = Q K^T : fp16 single-term (log2 domain) ----
        float Sc[8][4];
#pragma unroll
        for (int j = 0; j < 8; j++)
#pragma unroll
            for (int e = 0; e < 4; e++) Sc[j][e] = 0.0f;

#pragma unroll
        for (int kk = 0; kk < 4; kk++) {
            uint32_t q0, q1, q2, q3;
            ldsm4(q0, q1, q2, q3, bQ + qoff + kk * 32);
#pragma unroll
            for (int ng = 0; ng < 4; ng++) {
                uint32_t k0, k1, k2, k3;
                ldsm4(k0, k1, k2, k3,
                      bK + koff + (uint32_t)(ng * 16 * ALA * 2 + kk * 32));
                mma16816h(Sc[2 * ng],     q0, q1, q2, q3, k0, k1);
                mma16816h(Sc[2 * ng + 1], q0, q1, q2, q3, k2, k3);
            }
        }

        // ---- causal mask on diagonal tile ----
        if (kb == sb) {
            int row0 = s0 + 16 * w + g;
            int c00  = (kb << 6) + 2 * tq;
#pragma unroll
            for (int j = 0; j < 8; j++) {
                int c = c00 + 8 * j;
                if (c > row0)         Sc[j][0] = -1e30f;
                if (c + 1 > row0)     Sc[j][1] = -1e30f;
                if (c > row0 + 8)     Sc[j][2] = -1e30f;
                if (c + 1 > row0 + 8) Sc[j][3] = -1e30f;
            }
        }

        // ---- warp-local online softmax (exp2 domain) ----
        {
            float mx0 = -1e30f, mx1 = -1e30f;
#pragma unroll
            for (int j = 0; j < 8; j++) {
                mx0 = fmaxf(mx0, fmaxf(Sc[j][0], Sc[j][1]));
                mx1 = fmaxf(mx1, fmaxf(Sc[j][2], Sc[j][3]));
            }
            mx0 = fmaxf(mx0, __shfl_xor_sync(0xffffffffu, mx0, 1));
            mx0 = fmaxf(mx0, __shfl_xor_sync(0xffffffffu, mx0, 2));
            mx1 = fmaxf(mx1, __shfl_xor_sync(0xffffffffu, mx1, 1));
            mx1 = fmaxf(mx1, __shfl_xor_sync(0xffffffffu, mx1, 2));
            float nm0 = fmaxf(rm0, mx0), nm1 = fmaxf(rm1, mx1);
            float a0 = exp2f(rm0 - nm0), a1 = exp2f(rm1 - nm1);
            float ps0 = 0.0f, ps1 = 0.0f;
#pragma unroll
            for (int j = 0; j < 8; j++) {
                float e0 = exp2f(Sc[j][0] - nm0);
                float e1 = exp2f(Sc[j][1] - nm0);
                float e2 = exp2f(Sc[j][2] - nm1);
                float e3 = exp2f(Sc[j][3] - nm1);
                Sc[j][0] = e0; Sc[j][1] = e1; Sc[j][2] = e2; Sc[j][3] = e3;
                ps0 += e0 + e1; ps1 += e2 + e3;
            }
            ps0 += __shfl_xor_sync(0xffffffffu, ps0, 1);
            ps0 += __shfl_xor_sync(0xffffffffu, ps0, 2);
            ps1 += __shfl_xor_sync(0xffffffffu, ps1, 1);
            ps1 += __shfl_xor_sync(0xffffffffu, ps1, 2);
            rl0 = rl0 * a0 + ps0; rl1 = rl1 * a1 + ps1;
            rm0 = nm0; rm1 = nm1;
#pragma unroll
            for (int j = 0; j < 8; j++) {
                accO[j][0] *= a0; accO[j][1] *= a0;
                accO[j][2] *= a1; accO[j][3] *= a1;
            }
        }

        // ---- O += P V : P fp16 hi/lo (2-term), V fp16 ----
#pragma unroll
        for (int kk = 0; kk < 4; kk++) {
            float p0 = Sc[2 * kk][0],     p1 = Sc[2 * kk][1];
            float p2 = Sc[2 * kk][2],     p3 = Sc[2 * kk][3];
            float p4 = Sc[2 * kk + 1][0], p5 = Sc[2 * kk + 1][1];
            float p6 = Sc[2 * kk + 1][2], p7 = Sc[2 * kk + 1][3];
            uint32_t ph0 = pkh2(p0, p1), ph1 = pkh2(p2, p3);
            uint32_t ph2 = pkh2(p4, p5), ph3 = pkh2(p6, p7);
            __half2 h0 = *(__half2*)&ph0, h1 = *(__half2*)&ph1;
            __half2 h2 = *(__half2*)&ph2, h3 = *(__half2*)&ph3;
            uint32_t pl0 = pkh2(p0 - __low2float(h0), p1 - __high2float(h0));
            uint32_t pl1 = pkh2(p2 - __low2float(h1), p3 - __high2float(h1));
            uint32_t pl2 = pkh2(p4 - __low2float(h2), p5 - __high2float(h2));
            uint32_t pl3 = pkh2(p6 - __low2float(h3), p7 - __high2float(h3));
#pragma unroll
            for (int ng = 0; ng < 4; ng++) {
                uint32_t v0, v1, v2, v3;
                ldsm4t(v0, v1, v2, v3,
                       bV + voff + (uint32_t)(kk * 16 * ALA * 2 + ng * 32));
                mma16816h(accO[2 * ng],     ph0, ph1, ph2, ph3, v0, v1);
                mma16816h(accO[2 * ng],     pl0, pl1, pl2, pl3, v0, v1);
                mma16816h(accO[2 * ng + 1], ph0, ph1, ph2, ph3, v2, v3);
                mma16816h(accO[2 * ng + 1], pl0, pl1, pl2, pl3, v2, v3);
            }
        }
        __syncthreads();
    }

    // ---- epilogue: normalize, write fp16 O ----
    {
        float inv0 = 1.0f / rl0, inv1 = 1.0f / rl1;
        size_t base0 = qbase + (size_t)(16 * w + g) * EN + 2 * tq;
        size_t base1 = base0 + 8 * EN;
#pragma unroll
        for (int j = 0; j < 8; j++) {
            *(__half2*)(ofp + base0 + 8 * j) =
                __floats2half2_rn(accO[j][0] * inv0, accO[j][1] * inv0);
            *(__half2*)(ofp + base1 + 8 * j) =
                __floats2half2_rn(accO[j][2] * inv1, accO[j][3] * inv1);
        }
    }
}

// ---------------------------------------------------------------------------
// kernel_launch
// ---------------------------------------------------------------------------
extern "C" void kernel_launch(void* const* d_in, const int* in_sizes, int n_in,
                              void* d_out, int out_size)
{
    (void)in_sizes; (void)n_in; (void)out_size;

    const float* query = (const float*)d_in[0];
    const float* key   = (const float*)d_in[1];
    const float* value = (const float*)d_in[2];
    // d_in[3] = attn_mask (int32 tril) -- causal, handled analytically
    const float* Wq = (const float*)d_in[4];
    const float* bq = (const float*)d_in[5];
    const float* Wk = (const float*)d_in[6];
    const float* bk = (const float*)d_in[7];
    const float* Wv = (const float*)d_in[8];
    const float* bv = (const float*)d_in[9];
    const float* Wp = (const float*)d_in[10];
    const float* bp = (const float*)d_in[11];
    float* out = (float*)d_out;

    void* sp = nullptr;
    cudaGetSymbolAddress(&sp, g_scratch);
    float* base = (float*)sp;
    __half* qa  = (__half*)(base + 12ull * FM);   // fp16 attention operands
    __half* ka  = (__half*)(base + 14ull * FM);
    __half* va  = (__half*)(base + 16ull * FM);
    __half* qf  = (__half*)(base + 24ull * FM);   // fp16 inputs
    __half* kf  = (__half*)(base + 26ull * FM);
    __half* vf  = (__half*)(base + 28ull * FM);
    __half* ofp = (__half*)(base + 30ull * FM);
    __half* wf  = (__half*)(base + 32ull * FM);
    __half* wqf = wf;
    __half* wkf = wf + 262144;
    __half* wvf = wf + 524288;
    __half* wpf = wf + 786432;

    cudaFuncSetAttribute(gemm_qkv_kernel,
                         cudaFuncAttributeMaxDynamicSharedMemorySize, GEMM16_SM);
    cudaFuncSetAttribute(gemm_out_kernel,
                         cudaFuncAttributeMaxDynamicSharedMemorySize, GEMM16_SM);
    cudaFuncSetAttribute(attention_fp16_kernel,
                         cudaFuncAttributeMaxDynamicSharedMemorySize, ATT_SM);

    const int NB = NSE / 4;
    const int WB = EN * EN / 4;

    // phase 0: batched converts (2 launches)
    cvt3_kernel<<<dim3(NB / 256, 3), 256>>>(query, key, value, qf, kf, vf, NB);
    cvt4_kernel<<<dim3(WB / 256, 4), 256>>>(Wq, Wk, Wv, Wp,
                                            wqf, wkf, wvf, wpf, WB);

    // phase 1: fused QKV projections, fp16 out (Q scaled by 0.125*log2e)
    gemm_qkv_kernel<<<dim3(EN / 128, MTOT / 128, 3), 256, GEMM16_SM>>>(
        qf, kf, vf, wqf, wkf, wvf, bq, bk, bv, qa, ka, va);

    // phase 2: fp16 flash attention (Br=64, 4 CTAs/SM) -> fp16 O
    attention_fp16_kernel<<<dim3(SEQ / 64, NBAT * NHEAD), 128, ATT_SM>>>(
        qa, ka, va, ofp);

    // phase 3: output projection (fp32 store)
    gemm_out_kernel<<<dim3(EN / 128, MTOT / 128), 256, GEMM16_SM>>>(
        ofp, wpf, bp, out);
}